// round 11
// baseline (speedup 1.0000x reference)
#include <cuda_runtime.h>
#include <cuda_bf16.h>
#include <stdint.h>
#include <math.h>

#define BSZ   8
#define N0    4096
#define NMSG  4
#define NTOT  4100
#define CDIM  128
#define DH    32
#define ATT_SCALE 0.17677669529663687f  // 1/sqrt(32)

#define L1   256
#define LT1  260
#define HR1  16
#define WR1  16
#define L2   1024
#define LT2  1028
#define HR2  32
#define WR2  32

#define M_Q   (BSZ * NTOT)   // 32800
#define M_P1  (BSZ * L1)     // 2048
#define M_P2  (BSZ * L2)     // 8192
#define M_KV1 (BSZ * LT1)    // 2080
#define M_KV2 (BSZ * LT2)    // 8224

// stage1 grid layout
#define NQ_TILES  ((M_Q + 63) / 64)            // 513
#define P1_TILES  (M_P1 / 64)                  // 32
#define KSPLIT1   4
#define P1_BLKS   (P1_TILES * KSPLIT1)         // 128
#define P2_TILES  (M_P2 / 64)                  // 128
#define STAGE1_GRID (NQ_TILES + P1_BLKS + P2_TILES)

// kv grid
#define KV1_TILES ((M_KV1 + 63) / 64)          // 33
#define KV2_TILES ((M_KV2 + 63) / 64)          // 129

// ---------------- scratch (static device globals; no allocs) ----------------
__device__ float g_p1[KSPLIT1 * M_P1 * CDIM];  // PATCH1 K-split partials (no bias)
__device__ float g_p2[M_P2 * CDIM];            // PATCH2 output (no bias)
__device__ float g_v1f[M_KV1 * 64];            // V fp32 (pre-dwconv)
__device__ float g_v2f[M_KV2 * 64];
__device__ float g_ws1[CDIM * CDIM];           // transposed summed SR weights [c][o]
__device__ float g_ws2[CDIM * CDIM];

__device__ __nv_bfloat16 g_xb[BSZ * N0 * CDIM];
__device__ __nv_bfloat16 g_msgb[BSZ * NMSG * CDIM];
__device__ __nv_bfloat16 g_qb[M_Q * CDIM];     // Q (pre-scaled)
__device__ __nv_bfloat16 g_xk1b[M_KV1 * CDIM]; // post LN+GELU
__device__ __nv_bfloat16 g_xk2b[M_KV2 * CDIM];
__device__ __nv_bfloat16 g_k1b[M_KV1 * 64];    // K bf16
__device__ __nv_bfloat16 g_k2b[M_KV2 * 64];
__device__ __nv_bfloat16 g_v1mb[M_KV1 * 64];   // V + dwconv, bf16
__device__ __nv_bfloat16 g_v2mb[M_KV2 * 64];

__device__ __nv_bfloat16 g_wqb[CDIM * CDIM];
__device__ __nv_bfloat16 g_sr1wb[CDIM * CDIM * 16]; // [o][pos*128+c]
__device__ __nv_bfloat16 g_sr2wb[CDIM * CDIM * 4];
__device__ __nv_bfloat16 g_kv1wb[CDIM * CDIM];
__device__ __nv_bfloat16 g_kv2wb[CDIM * CDIM];
__device__ __nv_bfloat16 g_projwb[CDIM * CDIM];

// ---------------------------------------------------------------------------
__device__ __forceinline__ void mma_bf16(float c[4],
                                         uint32_t a0, uint32_t a1, uint32_t a2, uint32_t a3,
                                         uint32_t b0, uint32_t b1) {
    asm volatile(
        "mma.sync.aligned.m16n8k16.row.col.f32.bf16.bf16.f32 "
        "{%0,%1,%2,%3}, {%4,%5,%6,%7}, {%8,%9}, {%0,%1,%2,%3};"
        : "+f"(c[0]), "+f"(c[1]), "+f"(c[2]), "+f"(c[3])
        : "r"(a0), "r"(a1), "r"(a2), "r"(a3), "r"(b0), "r"(b1));
}

__device__ __forceinline__ uint32_t pack_bf16x2(float lo, float hi) {
    __nv_bfloat162 h = __floats2bfloat162_rn(lo, hi);
    return *reinterpret_cast<uint32_t*>(&h);
}

// ---------------------------------------------------------------------------
// prep: all fp32->bf16 conversions, SR weight reorder, summed-SR weights.
// ---------------------------------------------------------------------------
#define PS0 4096                  // xb (float4 per thread)
#define PS1 (PS0 + 16)            // msgb
#define PS2 (PS1 + 64)            // wqb
#define PS3 (PS2 + 64)            // kv1wb
#define PS4 (PS3 + 64)            // kv2wb
#define PS5 (PS4 + 64)            // projwb
#define PS6 (PS5 + 1024)          // wreorder sr1
#define PS7 (PS6 + 256)           // wreorder sr2
#define PS8 (PS7 + 64)            // wsum1
#define PS9 (PS8 + 64)            // wsum2   -> grid = PS9

__global__ void prep_kernel(const float* __restrict__ x,   const float* __restrict__ msg,
                            const float* __restrict__ Wq,  const float* __restrict__ kv1w,
                            const float* __restrict__ kv2w, const float* __restrict__ projw,
                            const float* __restrict__ sr1w, const float* __restrict__ sr2w) {
    int bid = blockIdx.x, t = threadIdx.x;
    if (bid < PS0) {
        int i = (bid * 256 + t) * 4;
        float4 v = *(const float4*)(x + i);
        __nv_bfloat16* o = g_xb + i;
        o[0] = __float2bfloat16(v.x); o[1] = __float2bfloat16(v.y);
        o[2] = __float2bfloat16(v.z); o[3] = __float2bfloat16(v.w);
    } else if (bid < PS1) {
        int i = (bid - PS0) * 256 + t;
        g_msgb[i] = __float2bfloat16(msg[i]);
    } else if (bid < PS2) {
        int i = (bid - PS1) * 256 + t;  g_wqb[i]   = __float2bfloat16(Wq[i]);
    } else if (bid < PS3) {
        int i = (bid - PS2) * 256 + t;  g_kv1wb[i] = __float2bfloat16(kv1w[i]);
    } else if (bid < PS4) {
        int i = (bid - PS3) * 256 + t;  g_kv2wb[i] = __float2bfloat16(kv2w[i]);
    } else if (bid < PS5) {
        int i = (bid - PS4) * 256 + t;  g_projwb[i] = __float2bfloat16(projw[i]);
    } else if (bid < PS6) {
        int idx = (bid - PS5) * 256 + t;          // [o][c][pos] src
        int o = idx >> 11;                         // / (128*16)
        int rem = idx & 2047;
        int cch = rem >> 4, pos = rem & 15;
        g_sr1wb[(size_t)o * 2048 + pos * CDIM + cch] = __float2bfloat16(sr1w[idx]);
    } else if (bid < PS7) {
        int idx = (bid - PS6) * 256 + t;
        int o = idx >> 9;                          // / (128*4)
        int rem = idx & 511;
        int cch = rem >> 2, pos = rem & 3;
        g_sr2wb[(size_t)o * 512 + pos * CDIM + cch] = __float2bfloat16(sr2w[idx]);
    } else if (bid < PS8) {
        int idx = (bid - PS7) * 256 + t;
        int c = idx >> 7, o = idx & 127;
        const float* p = sr1w + (o * CDIM + c) * 16;
        float s = 0.f;
#pragma unroll
        for (int i = 0; i < 16; i++) s += p[i];
        g_ws1[c * CDIM + o] = s;
    } else {
        int idx = (bid - PS8) * 256 + t;
        int c = idx >> 7, o = idx & 127;
        const float* p = sr2w + (o * CDIM + c) * 4;
        float s = 0.f;
#pragma unroll
        for (int i = 0; i < 4; i++) s += p[i];
        g_ws2[c * CDIM + o] = s;
    }
}

// ---------------------------------------------------------------------------
// stage1: Q projection + both SR patch-embed GEMMs in ONE launch.
// ---------------------------------------------------------------------------
__global__ void stage1_kernel(const float* __restrict__ bq) {
    __shared__ __nv_bfloat16 Xs[64][40];
    __shared__ __nv_bfloat16 Wsm[128][40];

    const int tid  = threadIdx.x;
    const int warp = tid >> 5;
    const int lane = tid & 31;
    const int mrow = (warp & 3) * 16;
    const int colBase = (warp >> 2) * 64;
    const int bid = blockIdx.x;

    int mode, S = 4, rowBase, K, kbase = 0, KTOT, M, Lloc = L1;
    const __nv_bfloat16* Wb;
    float* outP = nullptr;
    if (bid < NQ_TILES) {
        mode = 0; rowBase = bid * 64; K = 128; KTOT = 128; M = M_Q; Wb = g_wqb;
    } else if (bid < NQ_TILES + P1_BLKS) {
        int q = bid - NQ_TILES;
        mode = 1; S = 4; Lloc = L1;
        rowBase = (q >> 2) * 64;
        int kseg = q & 3;
        K = 512; kbase = kseg * 512; KTOT = 2048; M = M_P1;
        Wb = g_sr1wb; outP = g_p1 + (size_t)kseg * M_P1 * CDIM;
    } else {
        int q = bid - NQ_TILES - P1_BLKS;
        mode = 1; S = 2; Lloc = L2;
        rowBase = q * 64;
        K = 512; kbase = 0; KTOT = 512; M = M_P2;
        Wb = g_sr2wb; outP = g_p2;
    }

    const int lrow = tid >> 2;
    const int koff = (tid & 3) * 8;
    const int gr = rowBase + lrow;
    const bool valid = gr < M;

    const __nv_bfloat16* srcRow = nullptr;
    int pb = 0, phr = 0, pwr = 0;
    if (mode == 0) {
        if (valid) {
            int b = gr / NTOT, n = gr - b * NTOT;
            srcRow = (n < N0) ? g_xb + ((size_t)b * N0 + n) * CDIM
                              : g_msgb + ((size_t)b * NMSG + (n - N0)) * CDIM;
        }
    } else {
        if (valid) {
            pb = gr / Lloc; int l = gr - pb * Lloc;
            int Wr = (S == 4) ? WR1 : WR2;
            phr = l / Wr; pwr = l - phr * Wr;
        }
    }

    const int fr = lane >> 2;
    const int m2 = (lane & 3) * 2;

    float c[8][4];
#pragma unroll
    for (int nt = 0; nt < 8; nt++) { c[nt][0] = c[nt][1] = c[nt][2] = c[nt][3] = 0.f; }

    for (int k0 = 0; k0 < K; k0 += 32) {
        uint4 xv = make_uint4(0u, 0u, 0u, 0u);
        if (valid) {
            if (mode == 1) {
                int gk = kbase + k0;
                int pos = gk >> 7;
                int ky = (S == 4) ? (pos >> 2) : (pos >> 1);
                int kx = (S == 4) ? (pos & 3)  : (pos & 1);
                int p = (phr * S + ky) * 64 + pwr * S + kx;
                xv = *(const uint4*)(g_xb + ((size_t)pb * N0 + p) * CDIM + (gk & 127) + koff);
            } else {
                xv = *(const uint4*)(srcRow + k0 + koff);
            }
        }
        *(uint4*)&Xs[lrow][koff] = xv;
        {
            const __nv_bfloat16* wp = Wb + (size_t)(tid >> 1) * KTOT + kbase + k0 + (tid & 1) * 16;
            *(uint4*)&Wsm[tid >> 1][(tid & 1) * 16]     = *(const uint4*)wp;
            *(uint4*)&Wsm[tid >> 1][(tid & 1) * 16 + 8] = *(const uint4*)(wp + 8);
        }
        __syncthreads();

#pragma unroll
        for (int kt = 0; kt < 2; kt++) {
            uint32_t a0 = *(const uint32_t*)&Xs[mrow + fr][kt * 16 + m2];
            uint32_t a1 = *(const uint32_t*)&Xs[mrow + fr + 8][kt * 16 + m2];
            uint32_t a2 = *(const uint32_t*)&Xs[mrow + fr][kt * 16 + m2 + 8];
            uint32_t a3 = *(const uint32_t*)&Xs[mrow + fr + 8][kt * 16 + m2 + 8];
#pragma unroll
            for (int nt = 0; nt < 8; nt++) {
                uint32_t b0 = *(const uint32_t*)&Wsm[colBase + nt * 8 + fr][kt * 16 + m2];
                uint32_t b1 = *(const uint32_t*)&Wsm[colBase + nt * 8 + fr][kt * 16 + m2 + 8];
                mma_bf16(c[nt], a0, a1, a2, a3, b0, b1);
            }
        }
        __syncthreads();
    }

    const int r0 = rowBase + mrow + fr;
    const int r1 = r0 + 8;
#pragma unroll
    for (int nt = 0; nt < 8; nt++) {
        int col = colBase + nt * 8 + m2;
        if (mode == 0) {
            float bb0 = bq[col], bb1 = bq[col + 1];
            if (r0 < M) *(uint32_t*)&g_qb[(size_t)r0 * CDIM + col] =
                pack_bf16x2((c[nt][0] + bb0) * ATT_SCALE, (c[nt][1] + bb1) * ATT_SCALE);
            if (r1 < M) *(uint32_t*)&g_qb[(size_t)r1 * CDIM + col] =
                pack_bf16x2((c[nt][2] + bb0) * ATT_SCALE, (c[nt][3] + bb1) * ATT_SCALE);
        } else {
            if (r0 < M) *(float2*)&outP[(size_t)r0 * CDIM + col] = make_float2(c[nt][0], c[nt][1]);
            if (r1 < M) *(float2*)&outP[(size_t)r1 * CDIM + col] = make_float2(c[nt][2], c[nt][3]);
        }
    }
}

// ---------------------------------------------------------------------------
// LN+GELU fused: sums PATCH partials (+SR bias), msg-token SR matvec, LN+GELU.
// ---------------------------------------------------------------------------
__global__ void lnfuse_kernel(const float* __restrict__ msg,
                              const float* __restrict__ sr1b, const float* __restrict__ sr2b,
                              const float* __restrict__ ln1g, const float* __restrict__ ln1b,
                              const float* __restrict__ ln2g, const float* __restrict__ ln2b) {
    __shared__ float sm1[4], sm2[4];
    __shared__ float mrow[CDIM];
    int bid = blockIdx.x;
    int t = threadIdx.x, w = t >> 5, lane = t & 31;

    int br, b, l;
    if (bid < M_KV1) { br = 0; b = bid / LT1; l = bid - b * LT1; }
    else { int r2 = bid - M_KV1; br = 1; b = r2 / LT2; l = r2 - b * LT2; }

    const int Lloc = br ? L2 : L1;
    float v;
    if (l < Lloc) {
        if (br == 0) {
            size_t o = ((size_t)b * L1 + l) * CDIM + t;
            v = g_p1[o] + g_p1[(size_t)M_P1 * CDIM + o] + g_p1[(size_t)2 * M_P1 * CDIM + o]
              + g_p1[(size_t)3 * M_P1 * CDIM + o] + sr1b[t];
        } else {
            v = g_p2[((size_t)b * L2 + l) * CDIM + t] + sr2b[t];
        }
    } else {
        int n = l - Lloc;
        mrow[t] = msg[((size_t)b * NMSG + n) * CDIM + t];
        __syncthreads();
        const float* wsT = br ? g_ws2 : g_ws1;
        float a0 = 0.f, a1 = 0.f, a2 = 0.f, a3 = 0.f;
#pragma unroll 8
        for (int cc = 0; cc < CDIM; cc += 4) {
            a0 += mrow[cc + 0] * wsT[(cc + 0) * CDIM + t];
            a1 += mrow[cc + 1] * wsT[(cc + 1) * CDIM + t];
            a2 += mrow[cc + 2] * wsT[(cc + 2) * CDIM + t];
            a3 += mrow[cc + 3] * wsT[(cc + 3) * CDIM + t];
        }
        v = (a0 + a1) + (a2 + a3) + (br ? sr2b[t] : sr1b[t]);
    }
    __syncthreads();

    float s1 = v, s2 = v * v;
#pragma unroll
    for (int off = 16; off > 0; off >>= 1) {
        s1 += __shfl_xor_sync(0xffffffffu, s1, off);
        s2 += __shfl_xor_sync(0xffffffffu, s2, off);
    }
    if (lane == 0) { sm1[w] = s1; sm2[w] = s2; }
    __syncthreads();
    s1 = (sm1[0] + sm1[1]) + (sm1[2] + sm1[3]);
    s2 = (sm2[0] + sm2[1]) + (sm2[2] + sm2[3]);
    float mu  = s1 * (1.f / 128.f);
    float var = fmaxf(s2 * (1.f / 128.f) - mu * mu, 0.f);
    const float* g  = br ? ln2g : ln1g;
    const float* be = br ? ln2b : ln1b;
    float y = (v - mu) * rsqrtf(var + 1e-5f) * g[t] + be[t];
    float gel = 0.5f * y * (1.f + erff(y * 0.70710678118654752f));
    __nv_bfloat16* ob = br ? g_xk2b : g_xk1b;
    size_t row = br ? ((size_t)b * LT2 + l) : ((size_t)b * LT1 + l);
    ob[row * CDIM + t] = __float2bfloat16(gel);
}

// ---------------------------------------------------------------------------
// KV projections, both branches. K half -> bf16, V half -> fp32.
// ---------------------------------------------------------------------------
__global__ void kv_kernel(const float* __restrict__ kv1b_, const float* __restrict__ kv2b_) {
    __shared__ __nv_bfloat16 Xs[64][40];
    __shared__ __nv_bfloat16 Wsm[128][40];

    const int tid  = threadIdx.x;
    const int warp = tid >> 5;
    const int lane = tid & 31;
    const int mrow = (warp & 3) * 16;
    const int colBase = (warp >> 2) * 64;
    const int bid = blockIdx.x;

    int rowBase, M;
    const __nv_bfloat16 *Ab, *Wb;
    const float* bias;
    __nv_bfloat16* kb;
    float* vf;
    if (bid < KV1_TILES) {
        rowBase = bid * 64; M = M_KV1;
        Ab = g_xk1b; Wb = g_kv1wb; bias = kv1b_; kb = g_k1b; vf = g_v1f;
    } else {
        rowBase = (bid - KV1_TILES) * 64; M = M_KV2;
        Ab = g_xk2b; Wb = g_kv2wb; bias = kv2b_; kb = g_k2b; vf = g_v2f;
    }

    const int lrow = tid >> 2;
    const int koff = (tid & 3) * 8;
    const int gr = rowBase + lrow;
    const bool valid = gr < M;
    const int fr = lane >> 2;
    const int m2 = (lane & 3) * 2;

    float c[8][4];
#pragma unroll
    for (int nt = 0; nt < 8; nt++) { c[nt][0] = c[nt][1] = c[nt][2] = c[nt][3] = 0.f; }

    for (int k0 = 0; k0 < CDIM; k0 += 32) {
        uint4 xv = make_uint4(0u, 0u, 0u, 0u);
        if (valid) xv = *(const uint4*)(Ab + (size_t)gr * CDIM + k0 + koff);
        *(uint4*)&Xs[lrow][koff] = xv;
        {
            const __nv_bfloat16* wp = Wb + (size_t)(tid >> 1) * CDIM + k0 + (tid & 1) * 16;
            *(uint4*)&Wsm[tid >> 1][(tid & 1) * 16]     = *(const uint4*)wp;
            *(uint4*)&Wsm[tid >> 1][(tid & 1) * 16 + 8] = *(const uint4*)(wp + 8);
        }
        __syncthreads();
#pragma unroll
        for (int kt = 0; kt < 2; kt++) {
            uint32_t a0 = *(const uint32_t*)&Xs[mrow + fr][kt * 16 + m2];
            uint32_t a1 = *(const uint32_t*)&Xs[mrow + fr + 8][kt * 16 + m2];
            uint32_t a2 = *(const uint32_t*)&Xs[mrow + fr][kt * 16 + m2 + 8];
            uint32_t a3 = *(const uint32_t*)&Xs[mrow + fr + 8][kt * 16 + m2 + 8];
#pragma unroll
            for (int nt = 0; nt < 8; nt++) {
                uint32_t b0 = *(const uint32_t*)&Wsm[colBase + nt * 8 + fr][kt * 16 + m2];
                uint32_t b1 = *(const uint32_t*)&Wsm[colBase + nt * 8 + fr][kt * 16 + m2 + 8];
                mma_bf16(c[nt], a0, a1, a2, a3, b0, b1);
            }
        }
        __syncthreads();
    }

    const int r0 = rowBase + mrow + fr;
    const int r1 = r0 + 8;
#pragma unroll
    for (int nt = 0; nt < 8; nt++) {
        int col = colBase + nt * 8 + m2;
        float bb0 = bias[col], bb1 = bias[col + 1];
        float v00 = c[nt][0] + bb0, v01 = c[nt][1] + bb1;
        float v10 = c[nt][2] + bb0, v11 = c[nt][3] + bb1;
        if (col < 64) {  // K -> bf16
            if (r0 < M) *(uint32_t*)&kb[(size_t)r0 * 64 + col] = pack_bf16x2(v00, v01);
            if (r1 < M) *(uint32_t*)&kb[(size_t)r1 * 64 + col] = pack_bf16x2(v10, v11);
        } else {         // V -> fp32
            int vc = col - 64;
            if (r0 < M) *(float2*)&vf[(size_t)r0 * 64 + vc] = make_float2(v00, v01);
            if (r1 < M) *(float2*)&vf[(size_t)r1 * 64 + vc] = make_float2(v10, v11);
        }
    }
}

// ---------------------------------------------------------------------------
// v_mod both branches. bf16 out.
// ---------------------------------------------------------------------------
__global__ void vmod_kernel(const float* __restrict__ lw1, const float* __restrict__ lb1,
                            const float* __restrict__ lw2, const float* __restrict__ lb2) {
    int tid = threadIdx.x;
    int ch = tid & 63;
    int row = blockIdx.x * 4 + (tid >> 6);
    if (row >= M_KV1 + M_KV2) return;

    int b, l, Hr, Wr, Lloc, Lt;
    const float *vf, *lw, *lb;
    __nv_bfloat16* vm;
    if (row < M_KV1) {
        b = row / LT1; l = row - b * LT1;
        Hr = HR1; Wr = WR1; Lloc = L1; Lt = LT1;
        vf = g_v1f; lw = lw1; lb = lb1; vm = g_v1mb;
    } else {
        int r2 = row - M_KV1;
        b = r2 / LT2; l = r2 - b * LT2;
        Hr = HR2; Wr = WR2; Lloc = L2; Lt = LT2;
        vf = g_v2f; lw = lw2; lb = lb2; vm = g_v2mb;
    }
    float self = vf[((size_t)b * Lt + l) * 64 + ch];
    float o;
    if (l < Lloc) {
        int hr = l / Wr, wr = l - hr * Wr;
        float acc = lb[ch];
#pragma unroll
        for (int dy = 0; dy < 3; dy++) {
#pragma unroll
            for (int dx = 0; dx < 3; dx++) {
                int yy = hr + dy - 1, xx = wr + dx - 1;
                if (yy >= 0 && yy < Hr && xx >= 0 && xx < Wr)
                    acc += lw[ch * 9 + dy * 3 + dx] *
                           vf[((size_t)b * Lt + yy * Wr + xx) * 64 + ch];
            }
        }
        o = self + acc;
    } else {
        o = 2.f * self;
    }
    vm[((size_t)b * Lt + l) * 64 + ch] = __float2bfloat16(o);
}

// ---------------------------------------------------------------------------
// FUSED attention (all 4 heads) + output projection + residual.
// Block = 128 threads (4 warps), 64 query rows of batch b.
// Per head: flash loop (double-buffered K/V), normalized output kept in
// registers as mma C-fragments. Since proj K=128 = 4 heads x 32, each head's
// C-frags repack directly into proj A-frags (FA2 trick) -> proj GEMM in-reg.
// Eliminates g_x12b round trip and the separate proj kernel.
// ---------------------------------------------------------------------------
#define QT 64
__global__ void __launch_bounds__(128)
attnproj_kernel(const float* __restrict__ projb,
                const float* __restrict__ resx, const float* __restrict__ resmsg,
                float* __restrict__ out_img, float* __restrict__ out_msg) {
    __shared__ __nv_bfloat16 Qs[QT][40];
    __shared__ __nv_bfloat16 Ks[2][64][40];
    __shared__ __nv_bfloat16 Vt[2][32][66];
    __shared__ __nv_bfloat16 Wsm[128][40];

    const int tid  = threadIdx.x;
    const int warp = tid >> 5;
    const int lane = tid & 31;
    const int qt = blockIdx.x, b = blockIdx.y;
    const int n0 = qt * QT;

    const int lr = tid >> 1;           // 0..63 (load row / W col)
    const int lh = (tid & 1) * 16;     // 0 / 16 (load d-offset)
    const int fr = lane >> 2;
    const int m2 = (lane & 3) * 2;
    const int r0 = warp * 16 + fr;

    float oall[4][4][4];   // [head][ntile][frag] — attention outputs, reg-resident

#pragma unroll
    for (int hg = 0; hg < 4; hg++) {
        const int hbr = hg >> 1, hh = hg & 1;
        const __nv_bfloat16* kb = hbr ? g_k2b : g_k1b;
        const __nv_bfloat16* vm = hbr ? g_v2mb : g_v1mb;
        const int Lt = hbr ? LT2 : LT1;

        __syncthreads();   // previous head's smem readers done
        // Q tile: 64 rows x 32 d (2 uint4 per thread)
        {
            int n = n0 + lr;
            uint4 v0 = make_uint4(0u,0u,0u,0u), v1 = make_uint4(0u,0u,0u,0u);
            if (n < NTOT) {
                const __nv_bfloat16* qp = g_qb + ((size_t)b * NTOT + n) * CDIM + hg * DH + lh;
                v0 = *(const uint4*)qp;
                v1 = *(const uint4*)(qp + 8);
            }
            *(uint4*)&Qs[lr][lh]     = v0;
            *(uint4*)&Qs[lr][lh + 8] = v1;
        }
        // preload chunk 0 into buffer 0
        {
            uint4 k0v = make_uint4(0u,0u,0u,0u), k1v = make_uint4(0u,0u,0u,0u);
            uint4 v0v = make_uint4(0u,0u,0u,0u), v1v = make_uint4(0u,0u,0u,0u);
            if (lr < Lt) {
                size_t base = ((size_t)b * Lt + lr) * 64 + hh * DH + lh;
                k0v = *(const uint4*)(kb + base);
                k1v = *(const uint4*)(kb + base + 8);
                v0v = *(const uint4*)(vm + base);
                v1v = *(const uint4*)(vm + base + 8);
            }
            *(uint4*)&Ks[0][lr][lh]     = k0v;
            *(uint4*)&Ks[0][lr][lh + 8] = k1v;
            const __nv_bfloat16* va = (const __nv_bfloat16*)&v0v;
            const __nv_bfloat16* vb2 = (const __nv_bfloat16*)&v1v;
#pragma unroll
            for (int j = 0; j < 8; j++) Vt[0][lh + j][lr]     = va[j];
#pragma unroll
            for (int j = 0; j < 8; j++) Vt[0][lh + 8 + j][lr] = vb2[j];
        }
        __syncthreads();

        uint32_t qa[2][4];
#pragma unroll
        for (int kt = 0; kt < 2; kt++) {
            qa[kt][0] = *(const uint32_t*)&Qs[r0][kt * 16 + m2];
            qa[kt][1] = *(const uint32_t*)&Qs[r0 + 8][kt * 16 + m2];
            qa[kt][2] = *(const uint32_t*)&Qs[r0][kt * 16 + m2 + 8];
            qa[kt][3] = *(const uint32_t*)&Qs[r0 + 8][kt * 16 + m2 + 8];
        }

#pragma unroll
        for (int nt = 0; nt < 4; nt++) {
            oall[hg][nt][0] = 0.f; oall[hg][nt][1] = 0.f;
            oall[hg][nt][2] = 0.f; oall[hg][nt][3] = 0.f;
        }
        float m0 = -1e30f, m1 = -1e30f, l0 = 0.f, l1 = 0.f;

        const int nc = (Lt + 63) >> 6;
        for (int ci = 0; ci < nc; ci++) {
            const int c0 = ci << 6;
            const int buf = ci & 1;
            const bool pf = (ci + 1) < nc;

            uint4 kn0 = make_uint4(0u,0u,0u,0u), kn1 = make_uint4(0u,0u,0u,0u);
            uint4 vn0 = make_uint4(0u,0u,0u,0u), vn1 = make_uint4(0u,0u,0u,0u);
            if (pf) {
                int gl = c0 + 64 + lr;
                if (gl < Lt) {
                    size_t base = ((size_t)b * Lt + gl) * 64 + hh * DH + lh;
                    kn0 = *(const uint4*)(kb + base);
                    kn1 = *(const uint4*)(kb + base + 8);
                    vn0 = *(const uint4*)(vm + base);
                    vn1 = *(const uint4*)(vm + base + 8);
                }
            }

            float s[8][4];
#pragma unroll
            for (int nt = 0; nt < 8; nt++) { s[nt][0] = s[nt][1] = s[nt][2] = s[nt][3] = 0.f; }
#pragma unroll
            for (int nt = 0; nt < 8; nt++) {
#pragma unroll
                for (int kt = 0; kt < 2; kt++) {
                    uint32_t b0 = *(const uint32_t*)&Ks[buf][nt * 8 + fr][kt * 16 + m2];
                    uint32_t b1 = *(const uint32_t*)&Ks[buf][nt * 8 + fr][kt * 16 + m2 + 8];
                    mma_bf16(s[nt], qa[kt][0], qa[kt][1], qa[kt][2], qa[kt][3], b0, b1);
                }
            }

            float mx0 = m0, mx1 = m1;
#pragma unroll
            for (int nt = 0; nt < 8; nt++) {
                int gc = c0 + nt * 8 + m2;
                if (gc >= Lt)     { s[nt][0] = -1e30f; s[nt][2] = -1e30f; }
                if (gc + 1 >= Lt) { s[nt][1] = -1e30f; s[nt][3] = -1e30f; }
                mx0 = fmaxf(mx0, fmaxf(s[nt][0], s[nt][1]));
                mx1 = fmaxf(mx1, fmaxf(s[nt][2], s[nt][3]));
            }
            mx0 = fmaxf(mx0, __shfl_xor_sync(0xffffffffu, mx0, 1));
            mx0 = fmaxf(mx0, __shfl_xor_sync(0xffffffffu, mx0, 2));
            mx1 = fmaxf(mx1, __shfl_xor_sync(0xffffffffu, mx1, 1));
            mx1 = fmaxf(mx1, __shfl_xor_sync(0xffffffffu, mx1, 2));
            float corr0 = __expf(m0 - mx0), corr1 = __expf(m1 - mx1);
            m0 = mx0; m1 = mx1;

            float ls0 = 0.f, ls1 = 0.f;
#pragma unroll
            for (int nt = 0; nt < 8; nt++) {
                s[nt][0] = __expf(s[nt][0] - m0);
                s[nt][1] = __expf(s[nt][1] - m0);
                s[nt][2] = __expf(s[nt][2] - m1);
                s[nt][3] = __expf(s[nt][3] - m1);
                ls0 += s[nt][0] + s[nt][1];
                ls1 += s[nt][2] + s[nt][3];
            }
            ls0 += __shfl_xor_sync(0xffffffffu, ls0, 1);
            ls0 += __shfl_xor_sync(0xffffffffu, ls0, 2);
            ls1 += __shfl_xor_sync(0xffffffffu, ls1, 1);
            ls1 += __shfl_xor_sync(0xffffffffu, ls1, 2);
            l0 = l0 * corr0 + ls0;
            l1 = l1 * corr1 + ls1;
#pragma unroll
            for (int nt = 0; nt < 4; nt++) {
                oall[hg][nt][0] *= corr0; oall[hg][nt][1] *= corr0;
                oall[hg][nt][2] *= corr1; oall[hg][nt][3] *= corr1;
            }

#pragma unroll
            for (int kt = 0; kt < 4; kt++) {
                uint32_t a0 = pack_bf16x2(s[2 * kt][0],     s[2 * kt][1]);
                uint32_t a1 = pack_bf16x2(s[2 * kt][2],     s[2 * kt][3]);
                uint32_t a2 = pack_bf16x2(s[2 * kt + 1][0], s[2 * kt + 1][1]);
                uint32_t a3 = pack_bf16x2(s[2 * kt + 1][2], s[2 * kt + 1][3]);
#pragma unroll
                for (int nt = 0; nt < 4; nt++) {
                    uint32_t b0 = *(const uint32_t*)&Vt[buf][nt * 8 + fr][kt * 16 + m2];
                    uint32_t b1 = *(const uint32_t*)&Vt[buf][nt * 8 + fr][kt * 16 + m2 + 8];
                    mma_bf16(oall[hg][nt], a0, a1, a2, a3, b0, b1);
                }
            }

            if (pf) {
                *(uint4*)&Ks[buf ^ 1][lr][lh]     = kn0;
                *(uint4*)&Ks[buf ^ 1][lr][lh + 8] = kn1;
                const __nv_bfloat16* va = (const __nv_bfloat16*)&vn0;
                const __nv_bfloat16* vb2 = (const __nv_bfloat16*)&vn1;
#pragma unroll
                for (int j = 0; j < 8; j++) Vt[buf ^ 1][lh + j][lr]     = va[j];
#pragma unroll
                for (int j = 0; j < 8; j++) Vt[buf ^ 1][lh + 8 + j][lr] = vb2[j];
            }
            __syncthreads();
        }

        // normalize (register-only)
        float inv0 = 1.f / l0, inv1 = 1.f / l1;
#pragma unroll
        for (int nt = 0; nt < 4; nt++) {
            oall[hg][nt][0] *= inv0; oall[hg][nt][1] *= inv0;
            oall[hg][nt][2] *= inv1; oall[hg][nt][3] *= inv1;
        }
    }

    // ---- proj GEMM: out[64,128] = x12[64,128] @ projw^T; A from oall regs ----
    float c[16][4];
#pragma unroll
    for (int nt = 0; nt < 16; nt++) { c[nt][0] = c[nt][1] = c[nt][2] = c[nt][3] = 0.f; }

#pragma unroll
    for (int hg = 0; hg < 4; hg++) {     // k-chunk of 32 == head hg
        __syncthreads();                 // Wsm reuse guard
#pragma unroll
        for (int p = 0; p < 2; p++) {
            int row = lr + p * 64;
            const __nv_bfloat16* wp = g_projwb + (size_t)row * CDIM + hg * 32 + lh;
            *(uint4*)&Wsm[row][lh]     = *(const uint4*)wp;
            *(uint4*)&Wsm[row][lh + 8] = *(const uint4*)(wp + 8);
        }
        __syncthreads();
#pragma unroll
        for (int kt = 0; kt < 2; kt++) {
            uint32_t a0 = pack_bf16x2(oall[hg][2 * kt][0],     oall[hg][2 * kt][1]);
            uint32_t a1 = pack_bf16x2(oall[hg][2 * kt][2],     oall[hg][2 * kt][3]);
            uint32_t a2 = pack_bf16x2(oall[hg][2 * kt + 1][0], oall[hg][2 * kt + 1][1]);
            uint32_t a3 = pack_bf16x2(oall[hg][2 * kt + 1][2], oall[hg][2 * kt + 1][3]);
#pragma unroll
            for (int nt = 0; nt < 16; nt++) {
                uint32_t b0 = *(const uint32_t*)&Wsm[nt * 8 + fr][kt * 16 + m2];
                uint32_t b1 = *(const uint32_t*)&Wsm[nt * 8 + fr][kt * 16 + m2 + 8];
                mma_bf16(c[nt], a0, a1, a2, a3, b0, b1);
            }
        }
    }

    // epilogue: bias + residual, split write
    const int nr0 = n0 + r0, nr1 = nr0 + 8;
#pragma unroll
    for (int nt = 0; nt < 16; nt++) {
        int col = nt * 8 + m2;
        float bb0 = projb[col], bb1 = projb[col + 1];
        if (nr0 < NTOT) {
            if (nr0 < N0) {
                size_t oo = ((size_t)b * N0 + nr0) * CDIM + col;
                *(float2*)&out_img[oo] = make_float2(c[nt][0] + bb0 + resx[oo],
                                                     c[nt][1] + bb1 + resx[oo + 1]);
            } else {
                size_t oo = ((size_t)b * NMSG + (nr0 - N0)) * CDIM + col;
                *(float2*)&out_msg[oo] = make_float2(c[nt][0] + bb0 + resmsg[oo],
                                                     c[nt][1] + bb1 + resmsg[oo + 1]);
            }
        }
        if (nr1 < NTOT) {
            if (nr1 < N0) {
                size_t oo = ((size_t)b * N0 + nr1) * CDIM + col;
                *(float2*)&out_img[oo] = make_float2(c[nt][2] + bb0 + resx[oo],
                                                     c[nt][3] + bb1 + resx[oo + 1]);
            } else {
                size_t oo = ((size_t)b * NMSG + (nr1 - N0)) * CDIM + col;
                *(float2*)&out_msg[oo] = make_float2(c[nt][2] + bb0 + resmsg[oo],
                                                     c[nt][3] + bb1 + resmsg[oo + 1]);
            }
        }
    }
}

// ---------------------------------------------------------------------------
extern "C" void kernel_launch(void* const* d_in, const int* in_sizes, int n_in,
                              void* d_out, int out_size) {
    const float* x     = (const float*)d_in[0];
    const float* msg   = (const float*)d_in[1];
    const float* Wq    = (const float*)d_in[2];
    const float* bq    = (const float*)d_in[3];
    const float* sr1w  = (const float*)d_in[4];
    const float* sr1b  = (const float*)d_in[5];
    const float* ln1g  = (const float*)d_in[6];
    const float* ln1b  = (const float*)d_in[7];
    const float* sr2w  = (const float*)d_in[8];
    const float* sr2b  = (const float*)d_in[9];
    const float* ln2g  = (const float*)d_in[10];
    const float* ln2b  = (const float*)d_in[11];
    const float* kv1w  = (const float*)d_in[12];
    const float* kv1b  = (const float*)d_in[13];
    const float* kv2w  = (const float*)d_in[14];
    const float* kv2b  = (const float*)d_in[15];
    const float* lc1w  = (const float*)d_in[16];
    const float* lc1b  = (const float*)d_in[17];
    const float* lc2w  = (const float*)d_in[18];
    const float* lc2b  = (const float*)d_in[19];
    const float* projw = (const float*)d_in[20];
    const float* projb = (const float*)d_in[21];
    (void)in_sizes; (void)n_in; (void)out_size;

    float* out_img = (float*)d_out;
    float* out_msg = out_img + (size_t)BSZ * N0 * CDIM;

    // 1. all conversions / weight prep in one launch
    prep_kernel<<<PS9, 256>>>(x, msg, Wq, kv1w, kv2w, projw, sr1w, sr2w);

    // 2. Q + PATCH1(K-split x4) + PATCH2 GEMMs in one launch
    stage1_kernel<<<STAGE1_GRID, 256>>>(bq);

    // 3. partial-sum + SR bias + msg matvec + LN + GELU -> bf16
    lnfuse_kernel<<<M_KV1 + M_KV2, 128>>>(msg, sr1b, sr2b, ln1g, ln1b, ln2g, ln2b);

    // 4. KV projections (both branches); K->bf16, V->fp32
    kv_kernel<<<KV1_TILES + KV2_TILES, 256>>>(kv1b, kv2b);

    // 5. V augmentation -> bf16
    vmod_kernel<<<(M_KV1 + M_KV2 + 3) / 4, 256>>>(lc1w, lc1b, lc2w, lc2b);

    // 6. fused attention (4 heads) + proj + residual, split write
    {
        dim3 grid((NTOT + QT - 1) / QT, BSZ);
        attnproj_kernel<<<grid, 128>>>(projb, x, msg, out_img, out_msg);
    }
}

// round 12
// speedup vs baseline: 1.1500x; 1.1500x over previous
#include <cuda_runtime.h>
#include <cuda_bf16.h>
#include <stdint.h>
#include <math.h>

#define BSZ   8
#define N0    4096
#define NMSG  4
#define NTOT  4100
#define CDIM  128
#define DH    32
#define ATT_SCALE 0.17677669529663687f  // 1/sqrt(32)

#define L1   256
#define LT1  260
#define HR1  16
#define WR1  16
#define L2   1024
#define LT2  1028
#define HR2  32
#define WR2  32

#define M_Q   (BSZ * NTOT)   // 32800
#define M_P1  (BSZ * L1)     // 2048
#define M_P2  (BSZ * L2)     // 8192
#define M_KV1 (BSZ * LT1)    // 2080
#define M_KV2 (BSZ * LT2)    // 8224

// stage1 grid layout
#define NQ_TILES  ((M_Q + 63) / 64)            // 513
#define P1_TILES  (M_P1 / 64)                  // 32
#define KSPLIT1   4
#define P1_BLKS   (P1_TILES * KSPLIT1)         // 128
#define P2_TILES  (M_P2 / 64)                  // 128
#define STAGE1_GRID (NQ_TILES + P1_BLKS + P2_TILES)

// kv grid
#define KV1_TILES ((M_KV1 + 63) / 64)          // 33
#define KV2_TILES ((M_KV2 + 63) / 64)          // 129

// ---------------- scratch (static device globals; no allocs) ----------------
__device__ float g_p1[KSPLIT1 * M_P1 * CDIM];  // PATCH1 K-split partials (no bias)
__device__ float g_p2[M_P2 * CDIM];            // PATCH2 output (no bias)
__device__ float g_v1f[M_KV1 * 64];            // V fp32 (pre-dwconv)
__device__ float g_v2f[M_KV2 * 64];
__device__ float g_ws1[CDIM * CDIM];           // transposed summed SR weights [c][o]
__device__ float g_ws2[CDIM * CDIM];

__device__ __nv_bfloat16 g_xb[BSZ * N0 * CDIM];
__device__ __nv_bfloat16 g_msgb[BSZ * NMSG * CDIM];
__device__ __nv_bfloat16 g_qb[M_Q * CDIM];     // Q (pre-scaled)
__device__ __nv_bfloat16 g_xk1b[M_KV1 * CDIM]; // post LN+GELU
__device__ __nv_bfloat16 g_xk2b[M_KV2 * CDIM];
__device__ __nv_bfloat16 g_k1b[M_KV1 * 64];    // K bf16
__device__ __nv_bfloat16 g_k2b[M_KV2 * 64];
__device__ __nv_bfloat16 g_v1mb[M_KV1 * 64];   // V + dwconv, bf16
__device__ __nv_bfloat16 g_v2mb[M_KV2 * 64];

__device__ __nv_bfloat16 g_wqb[CDIM * CDIM];
__device__ __nv_bfloat16 g_sr1wb[CDIM * CDIM * 16]; // [o][pos*128+c]
__device__ __nv_bfloat16 g_sr2wb[CDIM * CDIM * 4];
__device__ __nv_bfloat16 g_kv1wb[CDIM * CDIM];
__device__ __nv_bfloat16 g_kv2wb[CDIM * CDIM];
__device__ __nv_bfloat16 g_projwb[CDIM * CDIM];

// ---------------------------------------------------------------------------
__device__ __forceinline__ void mma_bf16(float c[4],
                                         uint32_t a0, uint32_t a1, uint32_t a2, uint32_t a3,
                                         uint32_t b0, uint32_t b1) {
    asm volatile(
        "mma.sync.aligned.m16n8k16.row.col.f32.bf16.bf16.f32 "
        "{%0,%1,%2,%3}, {%4,%5,%6,%7}, {%8,%9}, {%0,%1,%2,%3};"
        : "+f"(c[0]), "+f"(c[1]), "+f"(c[2]), "+f"(c[3])
        : "r"(a0), "r"(a1), "r"(a2), "r"(a3), "r"(b0), "r"(b1));
}

__device__ __forceinline__ uint32_t pack_bf16x2(float lo, float hi) {
    __nv_bfloat162 h = __floats2bfloat162_rn(lo, hi);
    return *reinterpret_cast<uint32_t*>(&h);
}

// ---------------------------------------------------------------------------
// prep: all fp32->bf16 conversions, SR weight reorder, summed-SR weights.
// ---------------------------------------------------------------------------
#define PS0 4096                  // xb (float4 per thread)
#define PS1 (PS0 + 16)            // msgb
#define PS2 (PS1 + 64)            // wqb
#define PS3 (PS2 + 64)            // kv1wb
#define PS4 (PS3 + 64)            // kv2wb
#define PS5 (PS4 + 64)            // projwb
#define PS6 (PS5 + 1024)          // wreorder sr1
#define PS7 (PS6 + 256)           // wreorder sr2
#define PS8 (PS7 + 64)            // wsum1
#define PS9 (PS8 + 64)            // wsum2   -> grid = PS9

__global__ void prep_kernel(const float* __restrict__ x,   const float* __restrict__ msg,
                            const float* __restrict__ Wq,  const float* __restrict__ kv1w,
                            const float* __restrict__ kv2w, const float* __restrict__ projw,
                            const float* __restrict__ sr1w, const float* __restrict__ sr2w) {
    int bid = blockIdx.x, t = threadIdx.x;
    if (bid < PS0) {
        int i = (bid * 256 + t) * 4;
        float4 v = *(const float4*)(x + i);
        __nv_bfloat16* o = g_xb + i;
        o[0] = __float2bfloat16(v.x); o[1] = __float2bfloat16(v.y);
        o[2] = __float2bfloat16(v.z); o[3] = __float2bfloat16(v.w);
    } else if (bid < PS1) {
        int i = (bid - PS0) * 256 + t;
        g_msgb[i] = __float2bfloat16(msg[i]);
    } else if (bid < PS2) {
        int i = (bid - PS1) * 256 + t;  g_wqb[i]   = __float2bfloat16(Wq[i]);
    } else if (bid < PS3) {
        int i = (bid - PS2) * 256 + t;  g_kv1wb[i] = __float2bfloat16(kv1w[i]);
    } else if (bid < PS4) {
        int i = (bid - PS3) * 256 + t;  g_kv2wb[i] = __float2bfloat16(kv2w[i]);
    } else if (bid < PS5) {
        int i = (bid - PS4) * 256 + t;  g_projwb[i] = __float2bfloat16(projw[i]);
    } else if (bid < PS6) {
        int idx = (bid - PS5) * 256 + t;          // [o][c][pos] src
        int o = idx >> 11;                         // / (128*16)
        int rem = idx & 2047;
        int cch = rem >> 4, pos = rem & 15;
        g_sr1wb[(size_t)o * 2048 + pos * CDIM + cch] = __float2bfloat16(sr1w[idx]);
    } else if (bid < PS7) {
        int idx = (bid - PS6) * 256 + t;
        int o = idx >> 9;                          // / (128*4)
        int rem = idx & 511;
        int cch = rem >> 2, pos = rem & 3;
        g_sr2wb[(size_t)o * 512 + pos * CDIM + cch] = __float2bfloat16(sr2w[idx]);
    } else if (bid < PS8) {
        int idx = (bid - PS7) * 256 + t;
        int c = idx >> 7, o = idx & 127;
        const float* p = sr1w + (o * CDIM + c) * 16;
        float s = 0.f;
#pragma unroll
        for (int i = 0; i < 16; i++) s += p[i];
        g_ws1[c * CDIM + o] = s;
    } else {
        int idx = (bid - PS8) * 256 + t;
        int c = idx >> 7, o = idx & 127;
        const float* p = sr2w + (o * CDIM + c) * 4;
        float s = 0.f;
#pragma unroll
        for (int i = 0; i < 4; i++) s += p[i];
        g_ws2[c * CDIM + o] = s;
    }
}

// ---------------------------------------------------------------------------
// stage1: Q projection + both SR patch-embed GEMMs in ONE launch.
// ---------------------------------------------------------------------------
__global__ void stage1_kernel(const float* __restrict__ bq) {
    __shared__ __nv_bfloat16 Xs[64][40];
    __shared__ __nv_bfloat16 Wsm[128][40];

    const int tid  = threadIdx.x;
    const int warp = tid >> 5;
    const int lane = tid & 31;
    const int mrow = (warp & 3) * 16;
    const int colBase = (warp >> 2) * 64;
    const int bid = blockIdx.x;

    int mode, S = 4, rowBase, K, kbase = 0, KTOT, M, Lloc = L1;
    const __nv_bfloat16* Wb;
    float* outP = nullptr;
    if (bid < NQ_TILES) {
        mode = 0; rowBase = bid * 64; K = 128; KTOT = 128; M = M_Q; Wb = g_wqb;
    } else if (bid < NQ_TILES + P1_BLKS) {
        int q = bid - NQ_TILES;
        mode = 1; S = 4; Lloc = L1;
        rowBase = (q >> 2) * 64;
        int kseg = q & 3;
        K = 512; kbase = kseg * 512; KTOT = 2048; M = M_P1;
        Wb = g_sr1wb; outP = g_p1 + (size_t)kseg * M_P1 * CDIM;
    } else {
        int q = bid - NQ_TILES - P1_BLKS;
        mode = 1; S = 2; Lloc = L2;
        rowBase = q * 64;
        K = 512; kbase = 0; KTOT = 512; M = M_P2;
        Wb = g_sr2wb; outP = g_p2;
    }

    const int lrow = tid >> 2;
    const int koff = (tid & 3) * 8;
    const int gr = rowBase + lrow;
    const bool valid = gr < M;

    const __nv_bfloat16* srcRow = nullptr;
    int pb = 0, phr = 0, pwr = 0;
    if (mode == 0) {
        if (valid) {
            int b = gr / NTOT, n = gr - b * NTOT;
            srcRow = (n < N0) ? g_xb + ((size_t)b * N0 + n) * CDIM
                              : g_msgb + ((size_t)b * NMSG + (n - N0)) * CDIM;
        }
    } else {
        if (valid) {
            pb = gr / Lloc; int l = gr - pb * Lloc;
            int Wr = (S == 4) ? WR1 : WR2;
            phr = l / Wr; pwr = l - phr * Wr;
        }
    }

    const int fr = lane >> 2;
    const int m2 = (lane & 3) * 2;

    float c[8][4];
#pragma unroll
    for (int nt = 0; nt < 8; nt++) { c[nt][0] = c[nt][1] = c[nt][2] = c[nt][3] = 0.f; }

    for (int k0 = 0; k0 < K; k0 += 32) {
        uint4 xv = make_uint4(0u, 0u, 0u, 0u);
        if (valid) {
            if (mode == 1) {
                int gk = kbase + k0;
                int pos = gk >> 7;
                int ky = (S == 4) ? (pos >> 2) : (pos >> 1);
                int kx = (S == 4) ? (pos & 3)  : (pos & 1);
                int p = (phr * S + ky) * 64 + pwr * S + kx;
                xv = *(const uint4*)(g_xb + ((size_t)pb * N0 + p) * CDIM + (gk & 127) + koff);
            } else {
                xv = *(const uint4*)(srcRow + k0 + koff);
            }
        }
        *(uint4*)&Xs[lrow][koff] = xv;
        {
            const __nv_bfloat16* wp = Wb + (size_t)(tid >> 1) * KTOT + kbase + k0 + (tid & 1) * 16;
            *(uint4*)&Wsm[tid >> 1][(tid & 1) * 16]     = *(const uint4*)wp;
            *(uint4*)&Wsm[tid >> 1][(tid & 1) * 16 + 8] = *(const uint4*)(wp + 8);
        }
        __syncthreads();

#pragma unroll
        for (int kt = 0; kt < 2; kt++) {
            uint32_t a0 = *(const uint32_t*)&Xs[mrow + fr][kt * 16 + m2];
            uint32_t a1 = *(const uint32_t*)&Xs[mrow + fr + 8][kt * 16 + m2];
            uint32_t a2 = *(const uint32_t*)&Xs[mrow + fr][kt * 16 + m2 + 8];
            uint32_t a3 = *(const uint32_t*)&Xs[mrow + fr + 8][kt * 16 + m2 + 8];
#pragma unroll
            for (int nt = 0; nt < 8; nt++) {
                uint32_t b0 = *(const uint32_t*)&Wsm[colBase + nt * 8 + fr][kt * 16 + m2];
                uint32_t b1 = *(const uint32_t*)&Wsm[colBase + nt * 8 + fr][kt * 16 + m2 + 8];
                mma_bf16(c[nt], a0, a1, a2, a3, b0, b1);
            }
        }
        __syncthreads();
    }

    const int r0 = rowBase + mrow + fr;
    const int r1 = r0 + 8;
#pragma unroll
    for (int nt = 0; nt < 8; nt++) {
        int col = colBase + nt * 8 + m2;
        if (mode == 0) {
            float bb0 = bq[col], bb1 = bq[col + 1];
            if (r0 < M) *(uint32_t*)&g_qb[(size_t)r0 * CDIM + col] =
                pack_bf16x2((c[nt][0] + bb0) * ATT_SCALE, (c[nt][1] + bb1) * ATT_SCALE);
            if (r1 < M) *(uint32_t*)&g_qb[(size_t)r1 * CDIM + col] =
                pack_bf16x2((c[nt][2] + bb0) * ATT_SCALE, (c[nt][3] + bb1) * ATT_SCALE);
        } else {
            if (r0 < M) *(float2*)&outP[(size_t)r0 * CDIM + col] = make_float2(c[nt][0], c[nt][1]);
            if (r1 < M) *(float2*)&outP[(size_t)r1 * CDIM + col] = make_float2(c[nt][2], c[nt][3]);
        }
    }
}

// ---------------------------------------------------------------------------
// LN+GELU fused: sums PATCH partials (+SR bias), msg-token SR matvec, LN+GELU.
// ---------------------------------------------------------------------------
__global__ void lnfuse_kernel(const float* __restrict__ msg,
                              const float* __restrict__ sr1b, const float* __restrict__ sr2b,
                              const float* __restrict__ ln1g, const float* __restrict__ ln1b,
                              const float* __restrict__ ln2g, const float* __restrict__ ln2b) {
    __shared__ float sm1[4], sm2[4];
    __shared__ float mrow[CDIM];
    int bid = blockIdx.x;
    int t = threadIdx.x, w = t >> 5, lane = t & 31;

    int br, b, l;
    if (bid < M_KV1) { br = 0; b = bid / LT1; l = bid - b * LT1; }
    else { int r2 = bid - M_KV1; br = 1; b = r2 / LT2; l = r2 - b * LT2; }

    const int Lloc = br ? L2 : L1;
    float v;
    if (l < Lloc) {
        if (br == 0) {
            size_t o = ((size_t)b * L1 + l) * CDIM + t;
            v = g_p1[o] + g_p1[(size_t)M_P1 * CDIM + o] + g_p1[(size_t)2 * M_P1 * CDIM + o]
              + g_p1[(size_t)3 * M_P1 * CDIM + o] + sr1b[t];
        } else {
            v = g_p2[((size_t)b * L2 + l) * CDIM + t] + sr2b[t];
        }
    } else {
        int n = l - Lloc;
        mrow[t] = msg[((size_t)b * NMSG + n) * CDIM + t];
        __syncthreads();
        const float* wsT = br ? g_ws2 : g_ws1;
        float a0 = 0.f, a1 = 0.f, a2 = 0.f, a3 = 0.f;
#pragma unroll 8
        for (int cc = 0; cc < CDIM; cc += 4) {
            a0 += mrow[cc + 0] * wsT[(cc + 0) * CDIM + t];
            a1 += mrow[cc + 1] * wsT[(cc + 1) * CDIM + t];
            a2 += mrow[cc + 2] * wsT[(cc + 2) * CDIM + t];
            a3 += mrow[cc + 3] * wsT[(cc + 3) * CDIM + t];
        }
        v = (a0 + a1) + (a2 + a3) + (br ? sr2b[t] : sr1b[t]);
    }
    __syncthreads();

    float s1 = v, s2 = v * v;
#pragma unroll
    for (int off = 16; off > 0; off >>= 1) {
        s1 += __shfl_xor_sync(0xffffffffu, s1, off);
        s2 += __shfl_xor_sync(0xffffffffu, s2, off);
    }
    if (lane == 0) { sm1[w] = s1; sm2[w] = s2; }
    __syncthreads();
    s1 = (sm1[0] + sm1[1]) + (sm1[2] + sm1[3]);
    s2 = (sm2[0] + sm2[1]) + (sm2[2] + sm2[3]);
    float mu  = s1 * (1.f / 128.f);
    float var = fmaxf(s2 * (1.f / 128.f) - mu * mu, 0.f);
    const float* g  = br ? ln2g : ln1g;
    const float* be = br ? ln2b : ln1b;
    float y = (v - mu) * rsqrtf(var + 1e-5f) * g[t] + be[t];
    float gel = 0.5f * y * (1.f + erff(y * 0.70710678118654752f));
    __nv_bfloat16* ob = br ? g_xk2b : g_xk1b;
    size_t row = br ? ((size_t)b * LT2 + l) : ((size_t)b * LT1 + l);
    ob[row * CDIM + t] = __float2bfloat16(gel);
}

// ---------------------------------------------------------------------------
// KV projections, both branches. K half -> bf16, V half -> fp32.
// ---------------------------------------------------------------------------
__global__ void kv_kernel(const float* __restrict__ kv1b_, const float* __restrict__ kv2b_) {
    __shared__ __nv_bfloat16 Xs[64][40];
    __shared__ __nv_bfloat16 Wsm[128][40];

    const int tid  = threadIdx.x;
    const int warp = tid >> 5;
    const int lane = tid & 31;
    const int mrow = (warp & 3) * 16;
    const int colBase = (warp >> 2) * 64;
    const int bid = blockIdx.x;

    int rowBase, M;
    const __nv_bfloat16 *Ab, *Wb;
    const float* bias;
    __nv_bfloat16* kb;
    float* vf;
    if (bid < KV1_TILES) {
        rowBase = bid * 64; M = M_KV1;
        Ab = g_xk1b; Wb = g_kv1wb; bias = kv1b_; kb = g_k1b; vf = g_v1f;
    } else {
        rowBase = (bid - KV1_TILES) * 64; M = M_KV2;
        Ab = g_xk2b; Wb = g_kv2wb; bias = kv2b_; kb = g_k2b; vf = g_v2f;
    }

    const int lrow = tid >> 2;
    const int koff = (tid & 3) * 8;
    const int gr = rowBase + lrow;
    const bool valid = gr < M;
    const int fr = lane >> 2;
    const int m2 = (lane & 3) * 2;

    float c[8][4];
#pragma unroll
    for (int nt = 0; nt < 8; nt++) { c[nt][0] = c[nt][1] = c[nt][2] = c[nt][3] = 0.f; }

    for (int k0 = 0; k0 < CDIM; k0 += 32) {
        uint4 xv = make_uint4(0u, 0u, 0u, 0u);
        if (valid) xv = *(const uint4*)(Ab + (size_t)gr * CDIM + k0 + koff);
        *(uint4*)&Xs[lrow][koff] = xv;
        {
            const __nv_bfloat16* wp = Wb + (size_t)(tid >> 1) * CDIM + k0 + (tid & 1) * 16;
            *(uint4*)&Wsm[tid >> 1][(tid & 1) * 16]     = *(const uint4*)wp;
            *(uint4*)&Wsm[tid >> 1][(tid & 1) * 16 + 8] = *(const uint4*)(wp + 8);
        }
        __syncthreads();
#pragma unroll
        for (int kt = 0; kt < 2; kt++) {
            uint32_t a0 = *(const uint32_t*)&Xs[mrow + fr][kt * 16 + m2];
            uint32_t a1 = *(const uint32_t*)&Xs[mrow + fr + 8][kt * 16 + m2];
            uint32_t a2 = *(const uint32_t*)&Xs[mrow + fr][kt * 16 + m2 + 8];
            uint32_t a3 = *(const uint32_t*)&Xs[mrow + fr + 8][kt * 16 + m2 + 8];
#pragma unroll
            for (int nt = 0; nt < 8; nt++) {
                uint32_t b0 = *(const uint32_t*)&Wsm[colBase + nt * 8 + fr][kt * 16 + m2];
                uint32_t b1 = *(const uint32_t*)&Wsm[colBase + nt * 8 + fr][kt * 16 + m2 + 8];
                mma_bf16(c[nt], a0, a1, a2, a3, b0, b1);
            }
        }
        __syncthreads();
    }

    const int r0 = rowBase + mrow + fr;
    const int r1 = r0 + 8;
#pragma unroll
    for (int nt = 0; nt < 8; nt++) {
        int col = colBase + nt * 8 + m2;
        float bb0 = bias[col], bb1 = bias[col + 1];
        float v00 = c[nt][0] + bb0, v01 = c[nt][1] + bb1;
        float v10 = c[nt][2] + bb0, v11 = c[nt][3] + bb1;
        if (col < 64) {  // K -> bf16
            if (r0 < M) *(uint32_t*)&kb[(size_t)r0 * 64 + col] = pack_bf16x2(v00, v01);
            if (r1 < M) *(uint32_t*)&kb[(size_t)r1 * 64 + col] = pack_bf16x2(v10, v11);
        } else {         // V -> fp32
            int vc = col - 64;
            if (r0 < M) *(float2*)&vf[(size_t)r0 * 64 + vc] = make_float2(v00, v01);
            if (r1 < M) *(float2*)&vf[(size_t)r1 * 64 + vc] = make_float2(v10, v11);
        }
    }
}

// ---------------------------------------------------------------------------
// v_mod both branches. bf16 out.
// ---------------------------------------------------------------------------
__global__ void vmod_kernel(const float* __restrict__ lw1, const float* __restrict__ lb1,
                            const float* __restrict__ lw2, const float* __restrict__ lb2) {
    int tid = threadIdx.x;
    int ch = tid & 63;
    int row = blockIdx.x * 4 + (tid >> 6);
    if (row >= M_KV1 + M_KV2) return;

    int b, l, Hr, Wr, Lloc, Lt;
    const float *vf, *lw, *lb;
    __nv_bfloat16* vm;
    if (row < M_KV1) {
        b = row / LT1; l = row - b * LT1;
        Hr = HR1; Wr = WR1; Lloc = L1; Lt = LT1;
        vf = g_v1f; lw = lw1; lb = lb1; vm = g_v1mb;
    } else {
        int r2 = row - M_KV1;
        b = r2 / LT2; l = r2 - b * LT2;
        Hr = HR2; Wr = WR2; Lloc = L2; Lt = LT2;
        vf = g_v2f; lw = lw2; lb = lb2; vm = g_v2mb;
    }
    float self = vf[((size_t)b * Lt + l) * 64 + ch];
    float o;
    if (l < Lloc) {
        int hr = l / Wr, wr = l - hr * Wr;
        float acc = lb[ch];
#pragma unroll
        for (int dy = 0; dy < 3; dy++) {
#pragma unroll
            for (int dx = 0; dx < 3; dx++) {
                int yy = hr + dy - 1, xx = wr + dx - 1;
                if (yy >= 0 && yy < Hr && xx >= 0 && xx < Wr)
                    acc += lw[ch * 9 + dy * 3 + dx] *
                           vf[((size_t)b * Lt + yy * Wr + xx) * 64 + ch];
            }
        }
        o = self + acc;
    } else {
        o = 2.f * self;
    }
    vm[((size_t)b * Lt + l) * 64 + ch] = __float2bfloat16(o);
}

// ---------------------------------------------------------------------------
// FUSED attention + proj, Round-10 attention geometry restored:
// QT=128 query rows, 256 threads (8 warps, 16 rows/warp), double-buffered K/V.
// 4 heads sequential per CTA; per-head normalized output stays in registers
// as C-frags; proj (K=128 = 4 heads x 32) consumes them via C->A repack.
// ---------------------------------------------------------------------------
#define QT 128
__global__ void __launch_bounds__(256)
attnproj_kernel(const float* __restrict__ projb,
                const float* __restrict__ resx, const float* __restrict__ resmsg,
                float* __restrict__ out_img, float* __restrict__ out_msg) {
    __shared__ __nv_bfloat16 Qs[QT][40];
    __shared__ __nv_bfloat16 Ks[2][64][40];
    __shared__ __nv_bfloat16 Vt[2][32][66];
    __shared__ __nv_bfloat16 Wsm[128][40];

    const int tid  = threadIdx.x;
    const int warp = tid >> 5;
    const int lane = tid & 31;
    const int qt = blockIdx.x, b = blockIdx.y;
    const int n0 = qt * QT;

    const int lr   = tid >> 2;         // 0..63 (K/V load row)
    const int lkof = (tid & 3) * 8;    // 0/8/16/24
    const int fr = lane >> 2;
    const int m2 = (lane & 3) * 2;
    const int r0 = warp * 16 + fr;

    float oall[4][4][4];   // [head][ntile][frag]

#pragma unroll
    for (int hg = 0; hg < 4; hg++) {
        const int hbr = hg >> 1, hh = hg & 1;
        const __nv_bfloat16* kb = hbr ? g_k2b : g_k1b;
        const __nv_bfloat16* vm = hbr ? g_v2mb : g_v1mb;
        const int Lt = hbr ? LT2 : LT1;

        // Q tile: 128 rows x 32 d (previous head's readers done at loop-end sync)
#pragma unroll
        for (int pass = 0; pass < 2; pass++) {
            int r = lr + pass * 64;
            int n = n0 + r;
            uint4 v = make_uint4(0u, 0u, 0u, 0u);
            if (n < NTOT)
                v = *(const uint4*)(g_qb + ((size_t)b * NTOT + n) * CDIM + hg * DH + lkof);
            *(uint4*)&Qs[r][lkof] = v;
        }
        // preload chunk 0 into buffer 0
        {
            uint4 kv4 = make_uint4(0u, 0u, 0u, 0u);
            uint4 vv4 = make_uint4(0u, 0u, 0u, 0u);
            if (lr < Lt) {
                size_t base = ((size_t)b * Lt + lr) * 64 + hh * DH + lkof;
                kv4 = *(const uint4*)(kb + base);
                vv4 = *(const uint4*)(vm + base);
            }
            *(uint4*)&Ks[0][lr][lkof] = kv4;
            const __nv_bfloat16* vb = (const __nv_bfloat16*)&kv4;
            (void)vb;
            const __nv_bfloat16* vv = (const __nv_bfloat16*)&vv4;
#pragma unroll
            for (int j = 0; j < 8; j++) Vt[0][lkof + j][lr] = vv[j];
        }
        __syncthreads();

        uint32_t qa[2][4];
#pragma unroll
        for (int kt = 0; kt < 2; kt++) {
            qa[kt][0] = *(const uint32_t*)&Qs[r0][kt * 16 + m2];
            qa[kt][1] = *(const uint32_t*)&Qs[r0 + 8][kt * 16 + m2];
            qa[kt][2] = *(const uint32_t*)&Qs[r0][kt * 16 + m2 + 8];
            qa[kt][3] = *(const uint32_t*)&Qs[r0 + 8][kt * 16 + m2 + 8];
        }

#pragma unroll
        for (int nt = 0; nt < 4; nt++) {
            oall[hg][nt][0] = 0.f; oall[hg][nt][1] = 0.f;
            oall[hg][nt][2] = 0.f; oall[hg][nt][3] = 0.f;
        }
        float m0 = -1e30f, m1 = -1e30f, l0 = 0.f, l1 = 0.f;

        const int nc = (Lt + 63) >> 6;
        for (int ci = 0; ci < nc; ci++) {
            const int c0 = ci << 6;
            const int buf = ci & 1;
            const bool pf = (ci + 1) < nc;

            uint4 kv4n = make_uint4(0u, 0u, 0u, 0u);
            uint4 vv4n = make_uint4(0u, 0u, 0u, 0u);
            if (pf) {
                int gl = c0 + 64 + lr;
                if (gl < Lt) {
                    size_t base = ((size_t)b * Lt + gl) * 64 + hh * DH + lkof;
                    kv4n = *(const uint4*)(kb + base);
                    vv4n = *(const uint4*)(vm + base);
                }
            }

            float s[8][4];
#pragma unroll
            for (int nt = 0; nt < 8; nt++) { s[nt][0] = s[nt][1] = s[nt][2] = s[nt][3] = 0.f; }
#pragma unroll
            for (int nt = 0; nt < 8; nt++) {
#pragma unroll
                for (int kt = 0; kt < 2; kt++) {
                    uint32_t b0 = *(const uint32_t*)&Ks[buf][nt * 8 + fr][kt * 16 + m2];
                    uint32_t b1 = *(const uint32_t*)&Ks[buf][nt * 8 + fr][kt * 16 + m2 + 8];
                    mma_bf16(s[nt], qa[kt][0], qa[kt][1], qa[kt][2], qa[kt][3], b0, b1);
                }
            }

            float mx0 = m0, mx1 = m1;
#pragma unroll
            for (int nt = 0; nt < 8; nt++) {
                int gc = c0 + nt * 8 + m2;
                if (gc >= Lt)     { s[nt][0] = -1e30f; s[nt][2] = -1e30f; }
                if (gc + 1 >= Lt) { s[nt][1] = -1e30f; s[nt][3] = -1e30f; }
                mx0 = fmaxf(mx0, fmaxf(s[nt][0], s[nt][1]));
                mx1 = fmaxf(mx1, fmaxf(s[nt][2], s[nt][3]));
            }
            mx0 = fmaxf(mx0, __shfl_xor_sync(0xffffffffu, mx0, 1));
            mx0 = fmaxf(mx0, __shfl_xor_sync(0xffffffffu, mx0, 2));
            mx1 = fmaxf(mx1, __shfl_xor_sync(0xffffffffu, mx1, 1));
            mx1 = fmaxf(mx1, __shfl_xor_sync(0xffffffffu, mx1, 2));
            float corr0 = __expf(m0 - mx0), corr1 = __expf(m1 - mx1);
            m0 = mx0; m1 = mx1;

            float ls0 = 0.f, ls1 = 0.f;
#pragma unroll
            for (int nt = 0; nt < 8; nt++) {
                s[nt][0] = __expf(s[nt][0] - m0);
                s[nt][1] = __expf(s[nt][1] - m0);
                s[nt][2] = __expf(s[nt][2] - m1);
                s[nt][3] = __expf(s[nt][3] - m1);
                ls0 += s[nt][0] + s[nt][1];
                ls1 += s[nt][2] + s[nt][3];
            }
            ls0 += __shfl_xor_sync(0xffffffffu, ls0, 1);
            ls0 += __shfl_xor_sync(0xffffffffu, ls0, 2);
            ls1 += __shfl_xor_sync(0xffffffffu, ls1, 1);
            ls1 += __shfl_xor_sync(0xffffffffu, ls1, 2);
            l0 = l0 * corr0 + ls0;
            l1 = l1 * corr1 + ls1;
#pragma unroll
            for (int nt = 0; nt < 4; nt++) {
                oall[hg][nt][0] *= corr0; oall[hg][nt][1] *= corr0;
                oall[hg][nt][2] *= corr1; oall[hg][nt][3] *= corr1;
            }

#pragma unroll
            for (int kt = 0; kt < 4; kt++) {
                uint32_t a0 = pack_bf16x2(s[2 * kt][0],     s[2 * kt][1]);
                uint32_t a1 = pack_bf16x2(s[2 * kt][2],     s[2 * kt][3]);
                uint32_t a2 = pack_bf16x2(s[2 * kt + 1][0], s[2 * kt + 1][1]);
                uint32_t a3 = pack_bf16x2(s[2 * kt + 1][2], s[2 * kt + 1][3]);
#pragma unroll
                for (int nt = 0; nt < 4; nt++) {
                    uint32_t b0 = *(const uint32_t*)&Vt[buf][nt * 8 + fr][kt * 16 + m2];
                    uint32_t b1 = *(const uint32_t*)&Vt[buf][nt * 8 + fr][kt * 16 + m2 + 8];
                    mma_bf16(oall[hg][nt], a0, a1, a2, a3, b0, b1);
                }
            }

            if (pf) {
                *(uint4*)&Ks[buf ^ 1][lr][lkof] = kv4n;
                const __nv_bfloat16* vv = (const __nv_bfloat16*)&vv4n;
#pragma unroll
                for (int j = 0; j < 8; j++) Vt[buf ^ 1][lkof + j][lr] = vv[j];
            }
            __syncthreads();
        }

        // normalize in registers
        float inv0 = 1.f / l0, inv1 = 1.f / l1;
#pragma unroll
        for (int nt = 0; nt < 4; nt++) {
            oall[hg][nt][0] *= inv0; oall[hg][nt][1] *= inv0;
            oall[hg][nt][2] *= inv1; oall[hg][nt][3] *= inv1;
        }
    }

    // ---- proj: out[128,128] = x12[128,128] @ projw^T; A from oall regs ----
    float c[16][4];
#pragma unroll
    for (int nt = 0; nt < 16; nt++) { c[nt][0] = c[nt][1] = c[nt][2] = c[nt][3] = 0.f; }

#pragma unroll
    for (int hg = 0; hg < 4; hg++) {     // k-chunk of 32 == head hg
        __syncthreads();                 // Wsm reuse guard
        {
            int row = tid >> 1;
            int lh = (tid & 1) * 16;
            const __nv_bfloat16* wp = g_projwb + (size_t)row * CDIM + hg * 32 + lh;
            *(uint4*)&Wsm[row][lh]     = *(const uint4*)wp;
            *(uint4*)&Wsm[row][lh + 8] = *(const uint4*)(wp + 8);
        }
        __syncthreads();
#pragma unroll
        for (int kt = 0; kt < 2; kt++) {
            uint32_t a0 = pack_bf16x2(oall[hg][2 * kt][0],     oall[hg][2 * kt][1]);
            uint32_t a1 = pack_bf16x2(oall[hg][2 * kt][2],     oall[hg][2 * kt][3]);
            uint32_t a2 = pack_bf16x2(oall[hg][2 * kt + 1][0], oall[hg][2 * kt + 1][1]);
            uint32_t a3 = pack_bf16x2(oall[hg][2 * kt + 1][2], oall[hg][2 * kt + 1][3]);
#pragma unroll
            for (int nt = 0; nt < 16; nt++) {
                uint32_t b0 = *(const uint32_t*)&Wsm[nt * 8 + fr][kt * 16 + m2];
                uint32_t b1 = *(const uint32_t*)&Wsm[nt * 8 + fr][kt * 16 + m2 + 8];
                mma_bf16(c[nt], a0, a1, a2, a3, b0, b1);
            }
        }
    }

    // epilogue: bias + residual, split write
    const int nr0 = n0 + r0, nr1 = nr0 + 8;
#pragma unroll
    for (int nt = 0; nt < 16; nt++) {
        int col = nt * 8 + m2;
        float bb0 = projb[col], bb1 = projb[col + 1];
        if (nr0 < NTOT) {
            if (nr0 < N0) {
                size_t oo = ((size_t)b * N0 + nr0) * CDIM + col;
                *(float2*)&out_img[oo] = make_float2(c[nt][0] + bb0 + resx[oo],
                                                     c[nt][1] + bb1 + resx[oo + 1]);
            } else {
                size_t oo = ((size_t)b * NMSG + (nr0 - N0)) * CDIM + col;
                *(float2*)&out_msg[oo] = make_float2(c[nt][0] + bb0 + resmsg[oo],
                                                     c[nt][1] + bb1 + resmsg[oo + 1]);
            }
        }
        if (nr1 < NTOT) {
            if (nr1 < N0) {
                size_t oo = ((size_t)b * N0 + nr1) * CDIM + col;
                *(float2*)&out_img[oo] = make_float2(c[nt][2] + bb0 + resx[oo],
                                                     c[nt][3] + bb1 + resx[oo + 1]);
            } else {
                size_t oo = ((size_t)b * NMSG + (nr1 - N0)) * CDIM + col;
                *(float2*)&out_msg[oo] = make_float2(c[nt][2] + bb0 + resmsg[oo],
                                                     c[nt][3] + bb1 + resmsg[oo + 1]);
            }
        }
    }
}

// ---------------------------------------------------------------------------
extern "C" void kernel_launch(void* const* d_in, const int* in_sizes, int n_in,
                              void* d_out, int out_size) {
    const float* x     = (const float*)d_in[0];
    const float* msg   = (const float*)d_in[1];
    const float* Wq    = (const float*)d_in[2];
    const float* bq    = (const float*)d_in[3];
    const float* sr1w  = (const float*)d_in[4];
    const float* sr1b  = (const float*)d_in[5];
    const float* ln1g  = (const float*)d_in[6];
    const float* ln1b  = (const float*)d_in[7];
    const float* sr2w  = (const float*)d_in[8];
    const float* sr2b  = (const float*)d_in[9];
    const float* ln2g  = (const float*)d_in[10];
    const float* ln2b  = (const float*)d_in[11];
    const float* kv1w  = (const float*)d_in[12];
    const float* kv1b  = (const float*)d_in[13];
    const float* kv2w  = (const float*)d_in[14];
    const float* kv2b  = (const float*)d_in[15];
    const float* lc1w  = (const float*)d_in[16];
    const float* lc1b  = (const float*)d_in[17];
    const float* lc2w  = (const float*)d_in[18];
    const float* lc2b  = (const float*)d_in[19];
    const float* projw = (const float*)d_in[20];
    const float* projb = (const float*)d_in[21];
    (void)in_sizes; (void)n_in; (void)out_size;

    float* out_img = (float*)d_out;
    float* out_msg = out_img + (size_t)BSZ * N0 * CDIM;

    // 1. all conversions / weight prep in one launch
    prep_kernel<<<PS9, 256>>>(x, msg, Wq, kv1w, kv2w, projw, sr1w, sr2w);

    // 2. Q + PATCH1(K-split x4) + PATCH2 GEMMs in one launch
    stage1_kernel<<<STAGE1_GRID, 256>>>(bq);

    // 3. partial-sum + SR bias + msg matvec + LN + GELU -> bf16
    lnfuse_kernel<<<M_KV1 + M_KV2, 128>>>(msg, sr1b, sr2b, ln1g, ln1b, ln2g, ln2b);

    // 4. KV projections (both branches); K->bf16, V->fp32
    kv_kernel<<<KV1_TILES + KV2_TILES, 256>>>(kv1b, kv2b);

    // 5. V augmentation -> bf16
    vmod_kernel<<<(M_KV1 + M_KV2 + 3) / 4, 256>>>(lc1w, lc1b, lc2w, lc2b);

    // 6. fused attention (4 heads, 128-q tiles, 256 thr) + proj + residual
    {
        dim3 grid((NTOT + QT - 1) / QT, BSZ);
        attnproj_kernel<<<grid, 256>>>(projb, x, msg, out_img, out_msg);
    }
}

// round 13
// speedup vs baseline: 1.3152x; 1.1436x over previous
#include <cuda_runtime.h>
#include <cuda_bf16.h>
#include <stdint.h>
#include <math.h>

#define BSZ   8
#define N0    4096
#define NMSG  4
#define NTOT  4100
#define CDIM  128
#define DH    32
#define ATT_SCALE 0.17677669529663687f  // 1/sqrt(32)

#define L1   256
#define LT1  260
#define HR1  16
#define WR1  16
#define L2   1024
#define LT2  1028
#define HR2  32
#define WR2  32

#define M_Q   (BSZ * NTOT)   // 32800
#define M_P1  (BSZ * L1)     // 2048
#define M_P2  (BSZ * L2)     // 8192
#define M_KV1 (BSZ * LT1)    // 2080
#define M_KV2 (BSZ * LT2)    // 8224

// stage1 grid layout
#define NQ_TILES  ((M_Q + 63) / 64)            // 513
#define P1_TILES  (M_P1 / 64)                  // 32
#define KSPLIT1   4
#define P1_BLKS   (P1_TILES * KSPLIT1)         // 128
#define P2_TILES  (M_P2 / 64)                  // 128
#define STAGE1_GRID (NQ_TILES + P1_BLKS + P2_TILES)

// kv grid (column-split x2 for occupancy)
#define KV1_TILES ((M_KV1 + 63) / 64)          // 33
#define KV2_TILES ((M_KV2 + 63) / 64)          // 129
#define KV_GRID   ((KV1_TILES + KV2_TILES) * 2)

// ---------------- scratch (static device globals; no allocs) ----------------
__device__ float g_p1[KSPLIT1 * M_P1 * CDIM];  // PATCH1 K-split partials (no bias)
__device__ float g_p2[M_P2 * CDIM];            // PATCH2 output (no bias)
__device__ float g_v1f[M_KV1 * 64];            // V fp32 (pre-dwconv)
__device__ float g_v2f[M_KV2 * 64];
__device__ float g_ws1[CDIM * CDIM];           // transposed summed SR weights [c][o]
__device__ float g_ws2[CDIM * CDIM];

__device__ __nv_bfloat16 g_xb[BSZ * N0 * CDIM];
__device__ __nv_bfloat16 g_msgb[BSZ * NMSG * CDIM];
__device__ __nv_bfloat16 g_qb[M_Q * CDIM];     // Q (pre-scaled)
__device__ __nv_bfloat16 g_xk1b[M_KV1 * CDIM]; // post LN+GELU
__device__ __nv_bfloat16 g_xk2b[M_KV2 * CDIM];
__device__ __nv_bfloat16 g_k1b[M_KV1 * 64];    // K bf16
__device__ __nv_bfloat16 g_k2b[M_KV2 * 64];
__device__ __nv_bfloat16 g_v1mb[M_KV1 * 64];   // V + dwconv, bf16
__device__ __nv_bfloat16 g_v2mb[M_KV2 * 64];
__device__ __nv_bfloat16 g_x12b[M_Q * CDIM];   // attention outputs

__device__ __nv_bfloat16 g_wqb[CDIM * CDIM];
__device__ __nv_bfloat16 g_sr1wb[CDIM * CDIM * 16]; // [o][pos*128+c]
__device__ __nv_bfloat16 g_sr2wb[CDIM * CDIM * 4];
__device__ __nv_bfloat16 g_kv1wb[CDIM * CDIM];
__device__ __nv_bfloat16 g_kv2wb[CDIM * CDIM];
__device__ __nv_bfloat16 g_projwb[CDIM * CDIM];

// ---------------------------------------------------------------------------
__device__ __forceinline__ void mma_bf16(float c[4],
                                         uint32_t a0, uint32_t a1, uint32_t a2, uint32_t a3,
                                         uint32_t b0, uint32_t b1) {
    asm volatile(
        "mma.sync.aligned.m16n8k16.row.col.f32.bf16.bf16.f32 "
        "{%0,%1,%2,%3}, {%4,%5,%6,%7}, {%8,%9}, {%0,%1,%2,%3};"
        : "+f"(c[0]), "+f"(c[1]), "+f"(c[2]), "+f"(c[3])
        : "r"(a0), "r"(a1), "r"(a2), "r"(a3), "r"(b0), "r"(b1));
}

__device__ __forceinline__ uint32_t pack_bf16x2(float lo, float hi) {
    __nv_bfloat162 h = __floats2bfloat162_rn(lo, hi);
    return *reinterpret_cast<uint32_t*>(&h);
}

// ---------------------------------------------------------------------------
// prep: all fp32->bf16 conversions, SR weight reorder, summed-SR weights.
// ---------------------------------------------------------------------------
#define PS0 4096                  // xb (float4 per thread)
#define PS1 (PS0 + 16)            // msgb
#define PS2 (PS1 + 64)            // wqb
#define PS3 (PS2 + 64)            // kv1wb
#define PS4 (PS3 + 64)            // kv2wb
#define PS5 (PS4 + 64)            // projwb
#define PS6 (PS5 + 1024)          // wreorder sr1
#define PS7 (PS6 + 256)           // wreorder sr2
#define PS8 (PS7 + 64)            // wsum1
#define PS9 (PS8 + 64)            // wsum2   -> grid = PS9

__global__ void prep_kernel(const float* __restrict__ x,   const float* __restrict__ msg,
                            const float* __restrict__ Wq,  const float* __restrict__ kv1w,
                            const float* __restrict__ kv2w, const float* __restrict__ projw,
                            const float* __restrict__ sr1w, const float* __restrict__ sr2w) {
    int bid = blockIdx.x, t = threadIdx.x;
    if (bid < PS0) {
        int i = (bid * 256 + t) * 4;
        float4 v = *(const float4*)(x + i);
        __nv_bfloat16* o = g_xb + i;
        o[0] = __float2bfloat16(v.x); o[1] = __float2bfloat16(v.y);
        o[2] = __float2bfloat16(v.z); o[3] = __float2bfloat16(v.w);
    } else if (bid < PS1) {
        int i = (bid - PS0) * 256 + t;
        g_msgb[i] = __float2bfloat16(msg[i]);
    } else if (bid < PS2) {
        int i = (bid - PS1) * 256 + t;  g_wqb[i]   = __float2bfloat16(Wq[i]);
    } else if (bid < PS3) {
        int i = (bid - PS2) * 256 + t;  g_kv1wb[i] = __float2bfloat16(kv1w[i]);
    } else if (bid < PS4) {
        int i = (bid - PS3) * 256 + t;  g_kv2wb[i] = __float2bfloat16(kv2w[i]);
    } else if (bid < PS5) {
        int i = (bid - PS4) * 256 + t;  g_projwb[i] = __float2bfloat16(projw[i]);
    } else if (bid < PS6) {
        int idx = (bid - PS5) * 256 + t;          // [o][c][pos] src
        int o = idx >> 11;                         // / (128*16)
        int rem = idx & 2047;
        int cch = rem >> 4, pos = rem & 15;
        g_sr1wb[(size_t)o * 2048 + pos * CDIM + cch] = __float2bfloat16(sr1w[idx]);
    } else if (bid < PS7) {
        int idx = (bid - PS6) * 256 + t;
        int o = idx >> 9;                          // / (128*4)
        int rem = idx & 511;
        int cch = rem >> 2, pos = rem & 3;
        g_sr2wb[(size_t)o * 512 + pos * CDIM + cch] = __float2bfloat16(sr2w[idx]);
    } else if (bid < PS8) {
        int idx = (bid - PS7) * 256 + t;
        int c = idx >> 7, o = idx & 127;
        const float* p = sr1w + (o * CDIM + c) * 16;
        float s = 0.f;
#pragma unroll
        for (int i = 0; i < 16; i++) s += p[i];
        g_ws1[c * CDIM + o] = s;
    } else {
        int idx = (bid - PS8) * 256 + t;
        int c = idx >> 7, o = idx & 127;
        const float* p = sr2w + (o * CDIM + c) * 4;
        float s = 0.f;
#pragma unroll
        for (int i = 0; i < 4; i++) s += p[i];
        g_ws2[c * CDIM + o] = s;
    }
}

// ---------------------------------------------------------------------------
// stage1: Q projection + both SR patch-embed GEMMs in ONE launch.
// ---------------------------------------------------------------------------
__global__ void stage1_kernel(const float* __restrict__ bq) {
    __shared__ __nv_bfloat16 Xs[64][40];
    __shared__ __nv_bfloat16 Wsm[128][40];

    const int tid  = threadIdx.x;
    const int warp = tid >> 5;
    const int lane = tid & 31;
    const int mrow = (warp & 3) * 16;
    const int colBase = (warp >> 2) * 64;
    const int bid = blockIdx.x;

    int mode, S = 4, rowBase, K, kbase = 0, KTOT, M, Lloc = L1;
    const __nv_bfloat16* Wb;
    float* outP = nullptr;
    if (bid < NQ_TILES) {
        mode = 0; rowBase = bid * 64; K = 128; KTOT = 128; M = M_Q; Wb = g_wqb;
    } else if (bid < NQ_TILES + P1_BLKS) {
        int q = bid - NQ_TILES;
        mode = 1; S = 4; Lloc = L1;
        rowBase = (q >> 2) * 64;
        int kseg = q & 3;
        K = 512; kbase = kseg * 512; KTOT = 2048; M = M_P1;
        Wb = g_sr1wb; outP = g_p1 + (size_t)kseg * M_P1 * CDIM;
    } else {
        int q = bid - NQ_TILES - P1_BLKS;
        mode = 1; S = 2; Lloc = L2;
        rowBase = q * 64;
        K = 512; kbase = 0; KTOT = 512; M = M_P2;
        Wb = g_sr2wb; outP = g_p2;
    }

    const int lrow = tid >> 2;
    const int koff = (tid & 3) * 8;
    const int gr = rowBase + lrow;
    const bool valid = gr < M;

    const __nv_bfloat16* srcRow = nullptr;
    int pb = 0, phr = 0, pwr = 0;
    if (mode == 0) {
        if (valid) {
            int b = gr / NTOT, n = gr - b * NTOT;
            srcRow = (n < N0) ? g_xb + ((size_t)b * N0 + n) * CDIM
                              : g_msgb + ((size_t)b * NMSG + (n - N0)) * CDIM;
        }
    } else {
        if (valid) {
            pb = gr / Lloc; int l = gr - pb * Lloc;
            int Wr = (S == 4) ? WR1 : WR2;
            phr = l / Wr; pwr = l - phr * Wr;
        }
    }

    const int fr = lane >> 2;
    const int m2 = (lane & 3) * 2;

    float c[8][4];
#pragma unroll
    for (int nt = 0; nt < 8; nt++) { c[nt][0] = c[nt][1] = c[nt][2] = c[nt][3] = 0.f; }

    for (int k0 = 0; k0 < K; k0 += 32) {
        uint4 xv = make_uint4(0u, 0u, 0u, 0u);
        if (valid) {
            if (mode == 1) {
                int gk = kbase + k0;
                int pos = gk >> 7;
                int ky = (S == 4) ? (pos >> 2) : (pos >> 1);
                int kx = (S == 4) ? (pos & 3)  : (pos & 1);
                int p = (phr * S + ky) * 64 + pwr * S + kx;
                xv = *(const uint4*)(g_xb + ((size_t)pb * N0 + p) * CDIM + (gk & 127) + koff);
            } else {
                xv = *(const uint4*)(srcRow + k0 + koff);
            }
        }
        *(uint4*)&Xs[lrow][koff] = xv;
        {
            const __nv_bfloat16* wp = Wb + (size_t)(tid >> 1) * KTOT + kbase + k0 + (tid & 1) * 16;
            *(uint4*)&Wsm[tid >> 1][(tid & 1) * 16]     = *(const uint4*)wp;
            *(uint4*)&Wsm[tid >> 1][(tid & 1) * 16 + 8] = *(const uint4*)(wp + 8);
        }
        __syncthreads();

#pragma unroll
        for (int kt = 0; kt < 2; kt++) {
            uint32_t a0 = *(const uint32_t*)&Xs[mrow + fr][kt * 16 + m2];
            uint32_t a1 = *(const uint32_t*)&Xs[mrow + fr + 8][kt * 16 + m2];
            uint32_t a2 = *(const uint32_t*)&Xs[mrow + fr][kt * 16 + m2 + 8];
            uint32_t a3 = *(const uint32_t*)&Xs[mrow + fr + 8][kt * 16 + m2 + 8];
#pragma unroll
            for (int nt = 0; nt < 8; nt++) {
                uint32_t b0 = *(const uint32_t*)&Wsm[colBase + nt * 8 + fr][kt * 16 + m2];
                uint32_t b1 = *(const uint32_t*)&Wsm[colBase + nt * 8 + fr][kt * 16 + m2 + 8];
                mma_bf16(c[nt], a0, a1, a2, a3, b0, b1);
            }
        }
        __syncthreads();
    }

    const int r0 = rowBase + mrow + fr;
    const int r1 = r0 + 8;
#pragma unroll
    for (int nt = 0; nt < 8; nt++) {
        int col = colBase + nt * 8 + m2;
        if (mode == 0) {
            float bb0 = bq[col], bb1 = bq[col + 1];
            if (r0 < M) *(uint32_t*)&g_qb[(size_t)r0 * CDIM + col] =
                pack_bf16x2((c[nt][0] + bb0) * ATT_SCALE, (c[nt][1] + bb1) * ATT_SCALE);
            if (r1 < M) *(uint32_t*)&g_qb[(size_t)r1 * CDIM + col] =
                pack_bf16x2((c[nt][2] + bb0) * ATT_SCALE, (c[nt][3] + bb1) * ATT_SCALE);
        } else {
            if (r0 < M) *(float2*)&outP[(size_t)r0 * CDIM + col] = make_float2(c[nt][0], c[nt][1]);
            if (r1 < M) *(float2*)&outP[(size_t)r1 * CDIM + col] = make_float2(c[nt][2], c[nt][3]);
        }
    }
}

// ---------------------------------------------------------------------------
// LN+GELU fused: sums PATCH partials (+SR bias), msg-token SR matvec, LN+GELU.
// ---------------------------------------------------------------------------
__global__ void lnfuse_kernel(const float* __restrict__ msg,
                              const float* __restrict__ sr1b, const float* __restrict__ sr2b,
                              const float* __restrict__ ln1g, const float* __restrict__ ln1b,
                              const float* __restrict__ ln2g, const float* __restrict__ ln2b) {
    __shared__ float sm1[4], sm2[4];
    __shared__ float mrow[CDIM];
    int bid = blockIdx.x;
    int t = threadIdx.x, w = t >> 5, lane = t & 31;

    int br, b, l;
    if (bid < M_KV1) { br = 0; b = bid / LT1; l = bid - b * LT1; }
    else { int r2 = bid - M_KV1; br = 1; b = r2 / LT2; l = r2 - b * LT2; }

    const int Lloc = br ? L2 : L1;
    float v;
    if (l < Lloc) {
        if (br == 0) {
            size_t o = ((size_t)b * L1 + l) * CDIM + t;
            v = g_p1[o] + g_p1[(size_t)M_P1 * CDIM + o] + g_p1[(size_t)2 * M_P1 * CDIM + o]
              + g_p1[(size_t)3 * M_P1 * CDIM + o] + sr1b[t];
        } else {
            v = g_p2[((size_t)b * L2 + l) * CDIM + t] + sr2b[t];
        }
    } else {
        int n = l - Lloc;
        mrow[t] = msg[((size_t)b * NMSG + n) * CDIM + t];
        __syncthreads();
        const float* wsT = br ? g_ws2 : g_ws1;
        float a0 = 0.f, a1 = 0.f, a2 = 0.f, a3 = 0.f;
#pragma unroll 8
        for (int cc = 0; cc < CDIM; cc += 4) {
            a0 += mrow[cc + 0] * wsT[(cc + 0) * CDIM + t];
            a1 += mrow[cc + 1] * wsT[(cc + 1) * CDIM + t];
            a2 += mrow[cc + 2] * wsT[(cc + 2) * CDIM + t];
            a3 += mrow[cc + 3] * wsT[(cc + 3) * CDIM + t];
        }
        v = (a0 + a1) + (a2 + a3) + (br ? sr2b[t] : sr1b[t]);
    }
    __syncthreads();

    float s1 = v, s2 = v * v;
#pragma unroll
    for (int off = 16; off > 0; off >>= 1) {
        s1 += __shfl_xor_sync(0xffffffffu, s1, off);
        s2 += __shfl_xor_sync(0xffffffffu, s2, off);
    }
    if (lane == 0) { sm1[w] = s1; sm2[w] = s2; }
    __syncthreads();
    s1 = (sm1[0] + sm1[1]) + (sm1[2] + sm1[3]);
    s2 = (sm2[0] + sm2[1]) + (sm2[2] + sm2[3]);
    float mu  = s1 * (1.f / 128.f);
    float var = fmaxf(s2 * (1.f / 128.f) - mu * mu, 0.f);
    const float* g  = br ? ln2g : ln1g;
    const float* be = br ? ln2b : ln1b;
    float y = (v - mu) * rsqrtf(var + 1e-5f) * g[t] + be[t];
    float gel = 0.5f * y * (1.f + erff(y * 0.70710678118654752f));
    __nv_bfloat16* ob = br ? g_xk2b : g_xk1b;
    size_t row = br ? ((size_t)b * LT2 + l) : ((size_t)b * LT1 + l);
    ob[row * CDIM + t] = __float2bfloat16(gel);
}

// ---------------------------------------------------------------------------
// KV projections, both branches, COLUMN-SPLIT x2 (64x64 tiles, grid=324).
// K half (cols<64) -> bf16, V half (cols>=64) -> fp32.
// ---------------------------------------------------------------------------
__global__ void kv_kernel(const float* __restrict__ kv1b_, const float* __restrict__ kv2b_) {
    __shared__ __nv_bfloat16 Xs[64][40];
    __shared__ __nv_bfloat16 Wsm[64][40];

    const int tid  = threadIdx.x;
    const int warp = tid >> 5;
    const int lane = tid & 31;
    const int mrow = (warp & 3) * 16;
    const int colBase = (warp >> 2) * 32;   // 0 or 32 within the half
    const int colHalf = (blockIdx.x & 1) * 64;
    const int bid = blockIdx.x >> 1;

    int rowBase, M;
    const __nv_bfloat16 *Ab, *Wb;
    const float* bias;
    __nv_bfloat16* kb;
    float* vf;
    if (bid < KV1_TILES) {
        rowBase = bid * 64; M = M_KV1;
        Ab = g_xk1b; Wb = g_kv1wb; bias = kv1b_; kb = g_k1b; vf = g_v1f;
    } else {
        rowBase = (bid - KV1_TILES) * 64; M = M_KV2;
        Ab = g_xk2b; Wb = g_kv2wb; bias = kv2b_; kb = g_k2b; vf = g_v2f;
    }

    const int lrow = tid >> 2;
    const int koff = (tid & 3) * 8;
    const int gr = rowBase + lrow;
    const bool valid = gr < M;
    const int fr = lane >> 2;
    const int m2 = (lane & 3) * 2;

    float c[4][4];
#pragma unroll
    for (int nt = 0; nt < 4; nt++) { c[nt][0] = c[nt][1] = c[nt][2] = c[nt][3] = 0.f; }

    for (int k0 = 0; k0 < CDIM; k0 += 32) {
        uint4 xv = make_uint4(0u, 0u, 0u, 0u);
        if (valid) xv = *(const uint4*)(Ab + (size_t)gr * CDIM + k0 + koff);
        *(uint4*)&Xs[lrow][koff] = xv;
        {
            // W: 64 cols (this half) x 32 k; one uint4 per thread
            const __nv_bfloat16* wp = Wb + (size_t)(colHalf + lrow) * CDIM + k0 + koff;
            *(uint4*)&Wsm[lrow][koff] = *(const uint4*)wp;
        }
        __syncthreads();
#pragma unroll
        for (int kt = 0; kt < 2; kt++) {
            uint32_t a0 = *(const uint32_t*)&Xs[mrow + fr][kt * 16 + m2];
            uint32_t a1 = *(const uint32_t*)&Xs[mrow + fr + 8][kt * 16 + m2];
            uint32_t a2 = *(const uint32_t*)&Xs[mrow + fr][kt * 16 + m2 + 8];
            uint32_t a3 = *(const uint32_t*)&Xs[mrow + fr + 8][kt * 16 + m2 + 8];
#pragma unroll
            for (int nt = 0; nt < 4; nt++) {
                uint32_t b0 = *(const uint32_t*)&Wsm[colBase + nt * 8 + fr][kt * 16 + m2];
                uint32_t b1 = *(const uint32_t*)&Wsm[colBase + nt * 8 + fr][kt * 16 + m2 + 8];
                mma_bf16(c[nt], a0, a1, a2, a3, b0, b1);
            }
        }
        __syncthreads();
    }

    const int r0 = rowBase + mrow + fr;
    const int r1 = r0 + 8;
#pragma unroll
    for (int nt = 0; nt < 4; nt++) {
        int col = colHalf + colBase + nt * 8 + m2;
        float bb0 = bias[col], bb1 = bias[col + 1];
        float v00 = c[nt][0] + bb0, v01 = c[nt][1] + bb1;
        float v10 = c[nt][2] + bb0, v11 = c[nt][3] + bb1;
        if (col < 64) {  // K -> bf16
            if (r0 < M) *(uint32_t*)&kb[(size_t)r0 * 64 + col] = pack_bf16x2(v00, v01);
            if (r1 < M) *(uint32_t*)&kb[(size_t)r1 * 64 + col] = pack_bf16x2(v10, v11);
        } else {         // V -> fp32
            int vc = col - 64;
            if (r0 < M) *(float2*)&vf[(size_t)r0 * 64 + vc] = make_float2(v00, v01);
            if (r1 < M) *(float2*)&vf[(size_t)r1 * 64 + vc] = make_float2(v10, v11);
        }
    }
}

// ---------------------------------------------------------------------------
// v_mod both branches. bf16 out.
// ---------------------------------------------------------------------------
__global__ void vmod_kernel(const float* __restrict__ lw1, const float* __restrict__ lb1,
                            const float* __restrict__ lw2, const float* __restrict__ lb2) {
    int tid = threadIdx.x;
    int ch = tid & 63;
    int row = blockIdx.x * 4 + (tid >> 6);
    if (row >= M_KV1 + M_KV2) return;

    int b, l, Hr, Wr, Lloc, Lt;
    const float *vf, *lw, *lb;
    __nv_bfloat16* vm;
    if (row < M_KV1) {
        b = row / LT1; l = row - b * LT1;
        Hr = HR1; Wr = WR1; Lloc = L1; Lt = LT1;
        vf = g_v1f; lw = lw1; lb = lb1; vm = g_v1mb;
    } else {
        int r2 = row - M_KV1;
        b = r2 / LT2; l = r2 - b * LT2;
        Hr = HR2; Wr = WR2; Lloc = L2; Lt = LT2;
        vf = g_v2f; lw = lw2; lb = lb2; vm = g_v2mb;
    }
    float self = vf[((size_t)b * Lt + l) * 64 + ch];
    float o;
    if (l < Lloc) {
        int hr = l / Wr, wr = l - hr * Wr;
        float acc = lb[ch];
#pragma unroll
        for (int dy = 0; dy < 3; dy++) {
#pragma unroll
            for (int dx = 0; dx < 3; dx++) {
                int yy = hr + dy - 1, xx = wr + dx - 1;
                if (yy >= 0 && yy < Hr && xx >= 0 && xx < Wr)
                    acc += lw[ch * 9 + dy * 3 + dx] *
                           vf[((size_t)b * Lt + yy * Wr + xx) * 64 + ch];
            }
        }
        o = self + acc;
    } else {
        o = 2.f * self;
    }
    vm[((size_t)b * Lt + l) * 64 + ch] = __float2bfloat16(o);
}

// ---------------------------------------------------------------------------
// bf16 flash attention: 128-query tiles, 8 warps, double-buffered K/V smem,
// Vt stride 66. Writes g_x12b directly. (Round-10 verified geometry.)
// ---------------------------------------------------------------------------
#define VTS 66
__global__ void attn_mma_kernel() {
    __shared__ __nv_bfloat16 Qs[128][40];
    __shared__ __nv_bfloat16 Ks[2][64][40];
    __shared__ __nv_bfloat16 Vt[2][32][VTS];   // V transposed [d][key]

    const int tid  = threadIdx.x;
    const int warp = tid >> 5;
    const int lane = tid & 31;
    const int qt = blockIdx.x, hg = blockIdx.y, b = blockIdx.z;
    const int br = hg >> 1, hh = hg & 1;
    const __nv_bfloat16* kb = br ? g_k2b : g_k1b;
    const __nv_bfloat16* vm = br ? g_v2mb : g_v1mb;
    const int Lt = br ? LT2 : LT1;
    const int n0 = qt * 128;

    const int lr   = tid >> 2;         // 0..63 (load row)
    const int lkof = (tid & 3) * 8;    // 0/8/16/24 (load d-offset)

    // Q tile: 128 rows x 32 d
#pragma unroll
    for (int pass = 0; pass < 2; pass++) {
        int r = lr + pass * 64;
        int n = n0 + r;
        uint4 v = make_uint4(0u, 0u, 0u, 0u);
        if (n < NTOT)
            v = *(const uint4*)(g_qb + ((size_t)b * NTOT + n) * CDIM + hg * DH + lkof);
        *(uint4*)&Qs[r][lkof] = v;
    }

    // preload chunk 0 into buffer 0
    {
        uint4 kv4 = make_uint4(0u, 0u, 0u, 0u);
        uint4 vv4 = make_uint4(0u, 0u, 0u, 0u);
        if (lr < Lt) {
            size_t base = ((size_t)b * Lt + lr) * 64 + hh * DH + lkof;
            kv4 = *(const uint4*)(kb + base);
            vv4 = *(const uint4*)(vm + base);
        }
        *(uint4*)&Ks[0][lr][lkof] = kv4;
        const __nv_bfloat16* vb = (const __nv_bfloat16*)&vv4;
#pragma unroll
        for (int j = 0; j < 8; j++) Vt[0][lkof + j][lr] = vb[j];
    }
    __syncthreads();

    const int fr = lane >> 2;
    const int m2 = (lane & 3) * 2;
    const int r0 = warp * 16 + fr;

    uint32_t qa[2][4];
#pragma unroll
    for (int kt = 0; kt < 2; kt++) {
        qa[kt][0] = *(const uint32_t*)&Qs[r0][kt * 16 + m2];
        qa[kt][1] = *(const uint32_t*)&Qs[r0 + 8][kt * 16 + m2];
        qa[kt][2] = *(const uint32_t*)&Qs[r0][kt * 16 + m2 + 8];
        qa[kt][3] = *(const uint32_t*)&Qs[r0 + 8][kt * 16 + m2 + 8];
    }

    float o[4][4];
#pragma unroll
    for (int i = 0; i < 4; i++)
#pragma unroll
        for (int j = 0; j < 4; j++) o[i][j] = 0.f;
    float m0 = -1e30f, m1 = -1e30f, l0 = 0.f, l1 = 0.f;

    const int nc = (Lt + 63) >> 6;
    for (int ci = 0; ci < nc; ci++) {
        const int c0 = ci << 6;
        const int buf = ci & 1;
        const bool pf = (ci + 1) < nc;

        // prefetch next chunk into registers (latency hidden behind MMAs)
        uint4 kv4n = make_uint4(0u, 0u, 0u, 0u);
        uint4 vv4n = make_uint4(0u, 0u, 0u, 0u);
        if (pf) {
            int gl = c0 + 64 + lr;
            if (gl < Lt) {
                size_t base = ((size_t)b * Lt + gl) * 64 + hh * DH + lkof;
                kv4n = *(const uint4*)(kb + base);
                vv4n = *(const uint4*)(vm + base);
            }
        }

        float s[8][4];
#pragma unroll
        for (int nt = 0; nt < 8; nt++) { s[nt][0] = s[nt][1] = s[nt][2] = s[nt][3] = 0.f; }
#pragma unroll
        for (int nt = 0; nt < 8; nt++) {
#pragma unroll
            for (int kt = 0; kt < 2; kt++) {
                uint32_t b0 = *(const uint32_t*)&Ks[buf][nt * 8 + fr][kt * 16 + m2];
                uint32_t b1 = *(const uint32_t*)&Ks[buf][nt * 8 + fr][kt * 16 + m2 + 8];
                mma_bf16(s[nt], qa[kt][0], qa[kt][1], qa[kt][2], qa[kt][3], b0, b1);
            }
        }

        float mx0 = m0, mx1 = m1;
#pragma unroll
        for (int nt = 0; nt < 8; nt++) {
            int gc = c0 + nt * 8 + m2;
            if (gc >= Lt)     { s[nt][0] = -1e30f; s[nt][2] = -1e30f; }
            if (gc + 1 >= Lt) { s[nt][1] = -1e30f; s[nt][3] = -1e30f; }
            mx0 = fmaxf(mx0, fmaxf(s[nt][0], s[nt][1]));
            mx1 = fmaxf(mx1, fmaxf(s[nt][2], s[nt][3]));
        }
        mx0 = fmaxf(mx0, __shfl_xor_sync(0xffffffffu, mx0, 1));
        mx0 = fmaxf(mx0, __shfl_xor_sync(0xffffffffu, mx0, 2));
        mx1 = fmaxf(mx1, __shfl_xor_sync(0xffffffffu, mx1, 1));
        mx1 = fmaxf(mx1, __shfl_xor_sync(0xffffffffu, mx1, 2));
        float corr0 = __expf(m0 - mx0), corr1 = __expf(m1 - mx1);
        m0 = mx0; m1 = mx1;

        float ls0 = 0.f, ls1 = 0.f;
#pragma unroll
        for (int nt = 0; nt < 8; nt++) {
            s[nt][0] = __expf(s[nt][0] - m0);
            s[nt][1] = __expf(s[nt][1] - m0);
            s[nt][2] = __expf(s[nt][2] - m1);
            s[nt][3] = __expf(s[nt][3] - m1);
            ls0 += s[nt][0] + s[nt][1];
            ls1 += s[nt][2] + s[nt][3];
        }
        ls0 += __shfl_xor_sync(0xffffffffu, ls0, 1);
        ls0 += __shfl_xor_sync(0xffffffffu, ls0, 2);
        ls1 += __shfl_xor_sync(0xffffffffu, ls1, 1);
        ls1 += __shfl_xor_sync(0xffffffffu, ls1, 2);
        l0 = l0 * corr0 + ls0;
        l1 = l1 * corr1 + ls1;
#pragma unroll
        for (int nt = 0; nt < 4; nt++) {
            o[nt][0] *= corr0; o[nt][1] *= corr0;
            o[nt][2] *= corr1; o[nt][3] *= corr1;
        }

#pragma unroll
        for (int kt = 0; kt < 4; kt++) {
            uint32_t a0 = pack_bf16x2(s[2 * kt][0],     s[2 * kt][1]);
            uint32_t a1 = pack_bf16x2(s[2 * kt][2],     s[2 * kt][3]);
            uint32_t a2 = pack_bf16x2(s[2 * kt + 1][0], s[2 * kt + 1][1]);
            uint32_t a3 = pack_bf16x2(s[2 * kt + 1][2], s[2 * kt + 1][3]);
#pragma unroll
            for (int nt = 0; nt < 4; nt++) {
                uint32_t b0 = *(const uint32_t*)&Vt[buf][nt * 8 + fr][kt * 16 + m2];
                uint32_t b1 = *(const uint32_t*)&Vt[buf][nt * 8 + fr][kt * 16 + m2 + 8];
                mma_bf16(o[nt], a0, a1, a2, a3, b0, b1);
            }
        }

        // store prefetched chunk into the other buffer
        if (pf) {
            *(uint4*)&Ks[buf ^ 1][lr][lkof] = kv4n;
            const __nv_bfloat16* vb = (const __nv_bfloat16*)&vv4n;
#pragma unroll
            for (int j = 0; j < 8; j++) Vt[buf ^ 1][lkof + j][lr] = vb[j];
        }
        __syncthreads();
    }

    float inv0 = 1.f / l0, inv1 = 1.f / l1;
    int nr0 = n0 + r0, nr1 = nr0 + 8;
#pragma unroll
    for (int nt = 0; nt < 4; nt++) {
        int col = hg * DH + nt * 8 + m2;
        if (nr0 < NTOT)
            *(uint32_t*)&g_x12b[((size_t)b * NTOT + nr0) * CDIM + col] =
                pack_bf16x2(o[nt][0] * inv0, o[nt][1] * inv0);
        if (nr1 < NTOT)
            *(uint32_t*)&g_x12b[((size_t)b * NTOT + nr1) * CDIM + col] =
                pack_bf16x2(o[nt][2] * inv1, o[nt][3] * inv1);
    }
}

// ---------------------------------------------------------------------------
// Final projection + residual, split write to harness output.
// ---------------------------------------------------------------------------
__global__ void proj_kernel(const float* __restrict__ projb,
                            const float* __restrict__ resx, const float* __restrict__ resmsg,
                            float* __restrict__ out_img, float* __restrict__ out_msg) {
    __shared__ __nv_bfloat16 Xs[64][40];
    __shared__ __nv_bfloat16 Wsm[128][40];

    const int tid  = threadIdx.x;
    const int warp = tid >> 5;
    const int lane = tid & 31;
    const int mrow = (warp & 3) * 16;
    const int colBase = (warp >> 2) * 64;
    const int rowBase = blockIdx.x * 64;

    const int lrow = tid >> 2;
    const int koff = (tid & 3) * 8;
    const int gr = rowBase + lrow;
    const bool valid = gr < M_Q;
    const int fr = lane >> 2;
    const int m2 = (lane & 3) * 2;

    float c[8][4];
#pragma unroll
    for (int nt = 0; nt < 8; nt++) { c[nt][0] = c[nt][1] = c[nt][2] = c[nt][3] = 0.f; }

    for (int k0 = 0; k0 < CDIM; k0 += 32) {
        uint4 xv = make_uint4(0u, 0u, 0u, 0u);
        if (valid) xv = *(const uint4*)(g_x12b + (size_t)gr * CDIM + k0 + koff);
        *(uint4*)&Xs[lrow][koff] = xv;
        {
            const __nv_bfloat16* wp = g_projwb + (size_t)(tid >> 1) * CDIM + k0 + (tid & 1) * 16;
            *(uint4*)&Wsm[tid >> 1][(tid & 1) * 16]     = *(const uint4*)wp;
            *(uint4*)&Wsm[tid >> 1][(tid & 1) * 16 + 8] = *(const uint4*)(wp + 8);
        }
        __syncthreads();
#pragma unroll
        for (int kt = 0; kt < 2; kt++) {
            uint32_t a0 = *(const uint32_t*)&Xs[mrow + fr][kt * 16 + m2];
            uint32_t a1 = *(const uint32_t*)&Xs[mrow + fr + 8][kt * 16 + m2];
            uint32_t a2 = *(const uint32_t*)&Xs[mrow + fr][kt * 16 + m2 + 8];
            uint32_t a3 = *(const uint32_t*)&Xs[mrow + fr + 8][kt * 16 + m2 + 8];
#pragma unroll
            for (int nt = 0; nt < 8; nt++) {
                uint32_t b0 = *(const uint32_t*)&Wsm[colBase + nt * 8 + fr][kt * 16 + m2];
                uint32_t b1 = *(const uint32_t*)&Wsm[colBase + nt * 8 + fr][kt * 16 + m2 + 8];
                mma_bf16(c[nt], a0, a1, a2, a3, b0, b1);
            }
        }
        __syncthreads();
    }

    const int r0 = rowBase + mrow + fr;
    const int r1 = r0 + 8;
#pragma unroll
    for (int nt = 0; nt < 8; nt++) {
        int col = colBase + nt * 8 + m2;
        float bb0 = projb[col], bb1 = projb[col + 1];
        if (r0 < M_Q) {
            int b = r0 / NTOT, n = r0 - b * NTOT;
            if (n < N0) {
                size_t oo = ((size_t)b * N0 + n) * CDIM + col;
                *(float2*)&out_img[oo] = make_float2(c[nt][0] + bb0 + resx[oo],
                                                     c[nt][1] + bb1 + resx[oo + 1]);
            } else {
                size_t oo = ((size_t)b * NMSG + (n - N0)) * CDIM + col;
                *(float2*)&out_msg[oo] = make_float2(c[nt][0] + bb0 + resmsg[oo],
                                                     c[nt][1] + bb1 + resmsg[oo + 1]);
            }
        }
        if (r1 < M_Q) {
            int b = r1 / NTOT, n = r1 - b * NTOT;
            if (n < N0) {
                size_t oo = ((size_t)b * N0 + n) * CDIM + col;
                *(float2*)&out_img[oo] = make_float2(c[nt][2] + bb0 + resx[oo],
                                                     c[nt][3] + bb1 + resx[oo + 1]);
            } else {
                size_t oo = ((size_t)b * NMSG + (n - N0)) * CDIM + col;
                *(float2*)&out_msg[oo] = make_float2(c[nt][2] + bb0 + resmsg[oo],
                                                     c[nt][3] + bb1 + resmsg[oo + 1]);
            }
        }
    }
}

// ---------------------------------------------------------------------------
extern "C" void kernel_launch(void* const* d_in, const int* in_sizes, int n_in,
                              void* d_out, int out_size) {
    const float* x     = (const float*)d_in[0];
    const float* msg   = (const float*)d_in[1];
    const float* Wq    = (const float*)d_in[2];
    const float* bq    = (const float*)d_in[3];
    const float* sr1w  = (const float*)d_in[4];
    const float* sr1b  = (const float*)d_in[5];
    const float* ln1g  = (const float*)d_in[6];
    const float* ln1b  = (const float*)d_in[7];
    const float* sr2w  = (const float*)d_in[8];
    const float* sr2b  = (const float*)d_in[9];
    const float* ln2g  = (const float*)d_in[10];
    const float* ln2b  = (const float*)d_in[11];
    const float* kv1w  = (const float*)d_in[12];
    const float* kv1b  = (const float*)d_in[13];
    const float* kv2w  = (const float*)d_in[14];
    const float* kv2b  = (const float*)d_in[15];
    const float* lc1w  = (const float*)d_in[16];
    const float* lc1b  = (const float*)d_in[17];
    const float* lc2w  = (const float*)d_in[18];
    const float* lc2b  = (const float*)d_in[19];
    const float* projw = (const float*)d_in[20];
    const float* projb = (const float*)d_in[21];
    (void)in_sizes; (void)n_in; (void)out_size;

    float* out_img = (float*)d_out;
    float* out_msg = out_img + (size_t)BSZ * N0 * CDIM;

    // 1. all conversions / weight prep in one launch
    prep_kernel<<<PS9, 256>>>(x, msg, Wq, kv1w, kv2w, projw, sr1w, sr2w);

    // 2. Q + PATCH1(K-split x4) + PATCH2 GEMMs in one launch
    stage1_kernel<<<STAGE1_GRID, 256>>>(bq);

    // 3. partial-sum + SR bias + msg matvec + LN + GELU -> bf16
    lnfuse_kernel<<<M_KV1 + M_KV2, 128>>>(msg, sr1b, sr2b, ln1g, ln1b, ln2g, ln2b);

    // 4. KV projections (both branches, column-split); K->bf16, V->fp32
    kv_kernel<<<KV_GRID, 256>>>(kv1b, kv2b);

    // 5. V augmentation -> bf16
    vmod_kernel<<<(M_KV1 + M_KV2 + 3) / 4, 256>>>(lc1w, lc1b, lc2w, lc2b);

    // 6. attention (both branches/heads), double-buffered, writes g_x12b
    {
        dim3 grid((NTOT + 127) / 128, 4, BSZ);
        attn_mma_kernel<<<grid, 256>>>();
    }

    // 7. output projection + residual, split write
    proj_kernel<<<NQ_TILES, 256>>>(projb, x, msg, out_img, out_msg);
}

// round 14
// speedup vs baseline: 1.3423x; 1.0206x over previous
#include <cuda_runtime.h>
#include <cuda_bf16.h>
#include <stdint.h>
#include <math.h>

#define BSZ   8
#define N0    4096
#define NMSG  4
#define NTOT  4100
#define CDIM  128
#define DH    32
#define ATT_SCALE 0.17677669529663687f  // 1/sqrt(32)

#define L1   256
#define LT1  260
#define HR1  16
#define WR1  16
#define L2   1024
#define LT2  1028
#define HR2  32
#define WR2  32

#define M_Q   (BSZ * NTOT)   // 32800
#define M_P1  (BSZ * L1)     // 2048
#define M_P2  (BSZ * L2)     // 8192
#define M_KV1 (BSZ * LT1)    // 2080
#define M_KV2 (BSZ * LT2)    // 8224

// stage1 grid layout: LONG jobs (PATCH, K=512) first, short Q tiles last.
#define NQ_TILES  ((M_Q + 63) / 64)            // 513
#define P1_TILES  (M_P1 / 64)                  // 32
#define KSPLIT1   4
#define P1_BLKS   (P1_TILES * KSPLIT1)         // 128
#define P2_TILES  (M_P2 / 64)                  // 128
#define STAGE1_GRID (NQ_TILES + P1_BLKS + P2_TILES)

// kv grid (column-split x2 for occupancy)
#define KV1_TILES ((M_KV1 + 63) / 64)          // 33
#define KV2_TILES ((M_KV2 + 63) / 64)          // 129
#define KV_GRID   ((KV1_TILES + KV2_TILES) * 2)

// ---------------- scratch (static device globals; no allocs) ----------------
__device__ float g_p1[KSPLIT1 * M_P1 * CDIM];  // PATCH1 K-split partials (no bias)
__device__ float g_p2[M_P2 * CDIM];            // PATCH2 output (no bias)
__device__ float g_v1f[M_KV1 * 64];            // V fp32 (pre-dwconv)
__device__ float g_v2f[M_KV2 * 64];
__device__ float g_ws1[CDIM * CDIM];           // transposed summed SR weights [c][o]
__device__ float g_ws2[CDIM * CDIM];

__device__ __nv_bfloat16 g_xb[BSZ * N0 * CDIM];
__device__ __nv_bfloat16 g_msgb[BSZ * NMSG * CDIM];
__device__ __nv_bfloat16 g_qb[M_Q * CDIM];     // Q (pre-scaled)
__device__ __nv_bfloat16 g_xk1b[M_KV1 * CDIM]; // post LN+GELU
__device__ __nv_bfloat16 g_xk2b[M_KV2 * CDIM];
__device__ __nv_bfloat16 g_k1b[M_KV1 * 64];    // K bf16
__device__ __nv_bfloat16 g_k2b[M_KV2 * 64];
__device__ __nv_bfloat16 g_v1mb[M_KV1 * 64];   // V + dwconv, bf16
__device__ __nv_bfloat16 g_v2mb[M_KV2 * 64];
__device__ __nv_bfloat16 g_x12b[M_Q * CDIM];   // attention outputs

__device__ __nv_bfloat16 g_wqb[CDIM * CDIM];
__device__ __nv_bfloat16 g_sr1wb[CDIM * CDIM * 16]; // [o][pos*128+c]
__device__ __nv_bfloat16 g_sr2wb[CDIM * CDIM * 4];
__device__ __nv_bfloat16 g_kv1wb[CDIM * CDIM];
__device__ __nv_bfloat16 g_kv2wb[CDIM * CDIM];
__device__ __nv_bfloat16 g_projwb[CDIM * CDIM];

// ---------------------------------------------------------------------------
__device__ __forceinline__ void mma_bf16(float c[4],
                                         uint32_t a0, uint32_t a1, uint32_t a2, uint32_t a3,
                                         uint32_t b0, uint32_t b1) {
    asm volatile(
        "mma.sync.aligned.m16n8k16.row.col.f32.bf16.bf16.f32 "
        "{%0,%1,%2,%3}, {%4,%5,%6,%7}, {%8,%9}, {%0,%1,%2,%3};"
        : "+f"(c[0]), "+f"(c[1]), "+f"(c[2]), "+f"(c[3])
        : "r"(a0), "r"(a1), "r"(a2), "r"(a3), "r"(b0), "r"(b1));
}

__device__ __forceinline__ uint32_t pack_bf16x2(float lo, float hi) {
    __nv_bfloat162 h = __floats2bfloat162_rn(lo, hi);
    return *reinterpret_cast<uint32_t*>(&h);
}

// ---------------------------------------------------------------------------
// prep: all fp32->bf16 conversions, SR weight reorder, summed-SR weights.
// ---------------------------------------------------------------------------
#define PS0 4096                  // xb (float4 per thread)
#define PS1 (PS0 + 16)            // msgb
#define PS2 (PS1 + 64)            // wqb
#define PS3 (PS2 + 64)            // kv1wb
#define PS4 (PS3 + 64)            // kv2wb
#define PS5 (PS4 + 64)            // projwb
#define PS6 (PS5 + 1024)          // wreorder sr1
#define PS7 (PS6 + 256)           // wreorder sr2
#define PS8 (PS7 + 64)            // wsum1
#define PS9 (PS8 + 64)            // wsum2   -> grid = PS9

__global__ void prep_kernel(const float* __restrict__ x,   const float* __restrict__ msg,
                            const float* __restrict__ Wq,  const float* __restrict__ kv1w,
                            const float* __restrict__ kv2w, const float* __restrict__ projw,
                            const float* __restrict__ sr1w, const float* __restrict__ sr2w) {
    int bid = blockIdx.x, t = threadIdx.x;
    if (bid < PS0) {
        int i = (bid * 256 + t) * 4;
        float4 v = *(const float4*)(x + i);
        __nv_bfloat16* o = g_xb + i;
        o[0] = __float2bfloat16(v.x); o[1] = __float2bfloat16(v.y);
        o[2] = __float2bfloat16(v.z); o[3] = __float2bfloat16(v.w);
    } else if (bid < PS1) {
        int i = (bid - PS0) * 256 + t;
        g_msgb[i] = __float2bfloat16(msg[i]);
    } else if (bid < PS2) {
        int i = (bid - PS1) * 256 + t;  g_wqb[i]   = __float2bfloat16(Wq[i]);
    } else if (bid < PS3) {
        int i = (bid - PS2) * 256 + t;  g_kv1wb[i] = __float2bfloat16(kv1w[i]);
    } else if (bid < PS4) {
        int i = (bid - PS3) * 256 + t;  g_kv2wb[i] = __float2bfloat16(kv2w[i]);
    } else if (bid < PS5) {
        int i = (bid - PS4) * 256 + t;  g_projwb[i] = __float2bfloat16(projw[i]);
    } else if (bid < PS6) {
        int idx = (bid - PS5) * 256 + t;          // [o][c][pos] src
        int o = idx >> 11;                         // / (128*16)
        int rem = idx & 2047;
        int cch = rem >> 4, pos = rem & 15;
        g_sr1wb[(size_t)o * 2048 + pos * CDIM + cch] = __float2bfloat16(sr1w[idx]);
    } else if (bid < PS7) {
        int idx = (bid - PS6) * 256 + t;
        int o = idx >> 9;                          // / (128*4)
        int rem = idx & 511;
        int cch = rem >> 2, pos = rem & 3;
        g_sr2wb[(size_t)o * 512 + pos * CDIM + cch] = __float2bfloat16(sr2w[idx]);
    } else if (bid < PS8) {
        int idx = (bid - PS7) * 256 + t;
        int c = idx >> 7, o = idx & 127;
        const float* p = sr1w + (o * CDIM + c) * 16;
        float s = 0.f;
#pragma unroll
        for (int i = 0; i < 16; i++) s += p[i];
        g_ws1[c * CDIM + o] = s;
    } else {
        int idx = (bid - PS8) * 256 + t;
        int c = idx >> 7, o = idx & 127;
        const float* p = sr2w + (o * CDIM + c) * 4;
        float s = 0.f;
#pragma unroll
        for (int i = 0; i < 4; i++) s += p[i];
        g_ws2[c * CDIM + o] = s;
    }
}

// ---------------------------------------------------------------------------
// stage1: Q projection + both SR patch-embed GEMMs in ONE launch.
// Schedule order: PATCH1 (long) first, then PATCH2, then Q (short) — so the
// tail waves are short CTAs, not K=512 ones.
// ---------------------------------------------------------------------------
__global__ void stage1_kernel(const float* __restrict__ bq) {
    __shared__ __nv_bfloat16 Xs[64][40];
    __shared__ __nv_bfloat16 Wsm[128][40];

    const int tid  = threadIdx.x;
    const int warp = tid >> 5;
    const int lane = tid & 31;
    const int mrow = (warp & 3) * 16;
    const int colBase = (warp >> 2) * 64;
    const int bid = blockIdx.x;

    int mode, S = 4, rowBase, K, kbase = 0, KTOT, M, Lloc = L1;
    const __nv_bfloat16* Wb;
    float* outP = nullptr;
    if (bid < P1_BLKS) {                       // PATCH1 first (longest)
        int q = bid;
        mode = 1; S = 4; Lloc = L1;
        rowBase = (q >> 2) * 64;
        int kseg = q & 3;
        K = 512; kbase = kseg * 512; KTOT = 2048; M = M_P1;
        Wb = g_sr1wb; outP = g_p1 + (size_t)kseg * M_P1 * CDIM;
    } else if (bid < P1_BLKS + P2_TILES) {     // PATCH2 next
        int q = bid - P1_BLKS;
        mode = 1; S = 2; Lloc = L2;
        rowBase = q * 64;
        K = 512; kbase = 0; KTOT = 512; M = M_P2;
        Wb = g_sr2wb; outP = g_p2;
    } else {                                   // Q tiles last (short, K=128)
        int q = bid - P1_BLKS - P2_TILES;
        mode = 0; rowBase = q * 64; K = 128; KTOT = 128; M = M_Q; Wb = g_wqb;
    }

    const int lrow = tid >> 2;
    const int koff = (tid & 3) * 8;
    const int gr = rowBase + lrow;
    const bool valid = gr < M;

    const __nv_bfloat16* srcRow = nullptr;
    int pb = 0, phr = 0, pwr = 0;
    if (mode == 0) {
        if (valid) {
            int b = gr / NTOT, n = gr - b * NTOT;
            srcRow = (n < N0) ? g_xb + ((size_t)b * N0 + n) * CDIM
                              : g_msgb + ((size_t)b * NMSG + (n - N0)) * CDIM;
        }
    } else {
        if (valid) {
            pb = gr / Lloc; int l = gr - pb * Lloc;
            int Wr = (S == 4) ? WR1 : WR2;
            phr = l / Wr; pwr = l - phr * Wr;
        }
    }

    const int fr = lane >> 2;
    const int m2 = (lane & 3) * 2;

    float c[8][4];
#pragma unroll
    for (int nt = 0; nt < 8; nt++) { c[nt][0] = c[nt][1] = c[nt][2] = c[nt][3] = 0.f; }

    for (int k0 = 0; k0 < K; k0 += 32) {
        uint4 xv = make_uint4(0u, 0u, 0u, 0u);
        if (valid) {
            if (mode == 1) {
                int gk = kbase + k0;
                int pos = gk >> 7;
                int ky = (S == 4) ? (pos >> 2) : (pos >> 1);
                int kx = (S == 4) ? (pos & 3)  : (pos & 1);
                int p = (phr * S + ky) * 64 + pwr * S + kx;
                xv = *(const uint4*)(g_xb + ((size_t)pb * N0 + p) * CDIM + (gk & 127) + koff);
            } else {
                xv = *(const uint4*)(srcRow + k0 + koff);
            }
        }
        *(uint4*)&Xs[lrow][koff] = xv;
        {
            const __nv_bfloat16* wp = Wb + (size_t)(tid >> 1) * KTOT + kbase + k0 + (tid & 1) * 16;
            *(uint4*)&Wsm[tid >> 1][(tid & 1) * 16]     = *(const uint4*)wp;
            *(uint4*)&Wsm[tid >> 1][(tid & 1) * 16 + 8] = *(const uint4*)(wp + 8);
        }
        __syncthreads();

#pragma unroll
        for (int kt = 0; kt < 2; kt++) {
            uint32_t a0 = *(const uint32_t*)&Xs[mrow + fr][kt * 16 + m2];
            uint32_t a1 = *(const uint32_t*)&Xs[mrow + fr + 8][kt * 16 + m2];
            uint32_t a2 = *(const uint32_t*)&Xs[mrow + fr][kt * 16 + m2 + 8];
            uint32_t a3 = *(const uint32_t*)&Xs[mrow + fr + 8][kt * 16 + m2 + 8];
#pragma unroll
            for (int nt = 0; nt < 8; nt++) {
                uint32_t b0 = *(const uint32_t*)&Wsm[colBase + nt * 8 + fr][kt * 16 + m2];
                uint32_t b1 = *(const uint32_t*)&Wsm[colBase + nt * 8 + fr][kt * 16 + m2 + 8];
                mma_bf16(c[nt], a0, a1, a2, a3, b0, b1);
            }
        }
        __syncthreads();
    }

    const int r0 = rowBase + mrow + fr;
    const int r1 = r0 + 8;
#pragma unroll
    for (int nt = 0; nt < 8; nt++) {
        int col = colBase + nt * 8 + m2;
        if (mode == 0) {
            float bb0 = bq[col], bb1 = bq[col + 1];
            if (r0 < M) *(uint32_t*)&g_qb[(size_t)r0 * CDIM + col] =
                pack_bf16x2((c[nt][0] + bb0) * ATT_SCALE, (c[nt][1] + bb1) * ATT_SCALE);
            if (r1 < M) *(uint32_t*)&g_qb[(size_t)r1 * CDIM + col] =
                pack_bf16x2((c[nt][2] + bb0) * ATT_SCALE, (c[nt][3] + bb1) * ATT_SCALE);
        } else {
            if (r0 < M) *(float2*)&outP[(size_t)r0 * CDIM + col] = make_float2(c[nt][0], c[nt][1]);
            if (r1 < M) *(float2*)&outP[(size_t)r1 * CDIM + col] = make_float2(c[nt][2], c[nt][3]);
        }
    }
}

// ---------------------------------------------------------------------------
// LN+GELU fused: sums PATCH partials (+SR bias), msg-token SR matvec, LN+GELU.
// ---------------------------------------------------------------------------
__global__ void lnfuse_kernel(const float* __restrict__ msg,
                              const float* __restrict__ sr1b, const float* __restrict__ sr2b,
                              const float* __restrict__ ln1g, const float* __restrict__ ln1b,
                              const float* __restrict__ ln2g, const float* __restrict__ ln2b) {
    __shared__ float sm1[4], sm2[4];
    __shared__ float mrow[CDIM];
    int bid = blockIdx.x;
    int t = threadIdx.x, w = t >> 5, lane = t & 31;

    int br, b, l;
    if (bid < M_KV1) { br = 0; b = bid / LT1; l = bid - b * LT1; }
    else { int r2 = bid - M_KV1; br = 1; b = r2 / LT2; l = r2 - b * LT2; }

    const int Lloc = br ? L2 : L1;
    float v;
    if (l < Lloc) {
        if (br == 0) {
            size_t o = ((size_t)b * L1 + l) * CDIM + t;
            v = g_p1[o] + g_p1[(size_t)M_P1 * CDIM + o] + g_p1[(size_t)2 * M_P1 * CDIM + o]
              + g_p1[(size_t)3 * M_P1 * CDIM + o] + sr1b[t];
        } else {
            v = g_p2[((size_t)b * L2 + l) * CDIM + t] + sr2b[t];
        }
    } else {
        int n = l - Lloc;
        mrow[t] = msg[((size_t)b * NMSG + n) * CDIM + t];
        __syncthreads();
        const float* wsT = br ? g_ws2 : g_ws1;
        float a0 = 0.f, a1 = 0.f, a2 = 0.f, a3 = 0.f;
#pragma unroll 8
        for (int cc = 0; cc < CDIM; cc += 4) {
            a0 += mrow[cc + 0] * wsT[(cc + 0) * CDIM + t];
            a1 += mrow[cc + 1] * wsT[(cc + 1) * CDIM + t];
            a2 += mrow[cc + 2] * wsT[(cc + 2) * CDIM + t];
            a3 += mrow[cc + 3] * wsT[(cc + 3) * CDIM + t];
        }
        v = (a0 + a1) + (a2 + a3) + (br ? sr2b[t] : sr1b[t]);
    }
    __syncthreads();

    float s1 = v, s2 = v * v;
#pragma unroll
    for (int off = 16; off > 0; off >>= 1) {
        s1 += __shfl_xor_sync(0xffffffffu, s1, off);
        s2 += __shfl_xor_sync(0xffffffffu, s2, off);
    }
    if (lane == 0) { sm1[w] = s1; sm2[w] = s2; }
    __syncthreads();
    s1 = (sm1[0] + sm1[1]) + (sm1[2] + sm1[3]);
    s2 = (sm2[0] + sm2[1]) + (sm2[2] + sm2[3]);
    float mu  = s1 * (1.f / 128.f);
    float var = fmaxf(s2 * (1.f / 128.f) - mu * mu, 0.f);
    const float* g  = br ? ln2g : ln1g;
    const float* be = br ? ln2b : ln1b;
    float y = (v - mu) * rsqrtf(var + 1e-5f) * g[t] + be[t];
    float gel = 0.5f * y * (1.f + erff(y * 0.70710678118654752f));
    __nv_bfloat16* ob = br ? g_xk2b : g_xk1b;
    size_t row = br ? ((size_t)b * LT2 + l) : ((size_t)b * LT1 + l);
    ob[row * CDIM + t] = __float2bfloat16(gel);
}

// ---------------------------------------------------------------------------
// KV projections, both branches, COLUMN-SPLIT x2 (64x64 tiles, grid=324).
// ---------------------------------------------------------------------------
__global__ void kv_kernel(const float* __restrict__ kv1b_, const float* __restrict__ kv2b_) {
    __shared__ __nv_bfloat16 Xs[64][40];
    __shared__ __nv_bfloat16 Wsm[64][40];

    const int tid  = threadIdx.x;
    const int warp = tid >> 5;
    const int lane = tid & 31;
    const int mrow = (warp & 3) * 16;
    const int colBase = (warp >> 2) * 32;   // 0 or 32 within the half
    const int colHalf = (blockIdx.x & 1) * 64;
    const int bid = blockIdx.x >> 1;

    int rowBase, M;
    const __nv_bfloat16 *Ab, *Wb;
    const float* bias;
    __nv_bfloat16* kb;
    float* vf;
    if (bid < KV1_TILES) {
        rowBase = bid * 64; M = M_KV1;
        Ab = g_xk1b; Wb = g_kv1wb; bias = kv1b_; kb = g_k1b; vf = g_v1f;
    } else {
        rowBase = (bid - KV1_TILES) * 64; M = M_KV2;
        Ab = g_xk2b; Wb = g_kv2wb; bias = kv2b_; kb = g_k2b; vf = g_v2f;
    }

    const int lrow = tid >> 2;
    const int koff = (tid & 3) * 8;
    const int gr = rowBase + lrow;
    const bool valid = gr < M;
    const int fr = lane >> 2;
    const int m2 = (lane & 3) * 2;

    float c[4][4];
#pragma unroll
    for (int nt = 0; nt < 4; nt++) { c[nt][0] = c[nt][1] = c[nt][2] = c[nt][3] = 0.f; }

    for (int k0 = 0; k0 < CDIM; k0 += 32) {
        uint4 xv = make_uint4(0u, 0u, 0u, 0u);
        if (valid) xv = *(const uint4*)(Ab + (size_t)gr * CDIM + k0 + koff);
        *(uint4*)&Xs[lrow][koff] = xv;
        {
            const __nv_bfloat16* wp = Wb + (size_t)(colHalf + lrow) * CDIM + k0 + koff;
            *(uint4*)&Wsm[lrow][koff] = *(const uint4*)wp;
        }
        __syncthreads();
#pragma unroll
        for (int kt = 0; kt < 2; kt++) {
            uint32_t a0 = *(const uint32_t*)&Xs[mrow + fr][kt * 16 + m2];
            uint32_t a1 = *(const uint32_t*)&Xs[mrow + fr + 8][kt * 16 + m2];
            uint32_t a2 = *(const uint32_t*)&Xs[mrow + fr][kt * 16 + m2 + 8];
            uint32_t a3 = *(const uint32_t*)&Xs[mrow + fr + 8][kt * 16 + m2 + 8];
#pragma unroll
            for (int nt = 0; nt < 4; nt++) {
                uint32_t b0 = *(const uint32_t*)&Wsm[colBase + nt * 8 + fr][kt * 16 + m2];
                uint32_t b1 = *(const uint32_t*)&Wsm[colBase + nt * 8 + fr][kt * 16 + m2 + 8];
                mma_bf16(c[nt], a0, a1, a2, a3, b0, b1);
            }
        }
        __syncthreads();
    }

    const int r0 = rowBase + mrow + fr;
    const int r1 = r0 + 8;
#pragma unroll
    for (int nt = 0; nt < 4; nt++) {
        int col = colHalf + colBase + nt * 8 + m2;
        float bb0 = bias[col], bb1 = bias[col + 1];
        float v00 = c[nt][0] + bb0, v01 = c[nt][1] + bb1;
        float v10 = c[nt][2] + bb0, v11 = c[nt][3] + bb1;
        if (col < 64) {  // K -> bf16
            if (r0 < M) *(uint32_t*)&kb[(size_t)r0 * 64 + col] = pack_bf16x2(v00, v01);
            if (r1 < M) *(uint32_t*)&kb[(size_t)r1 * 64 + col] = pack_bf16x2(v10, v11);
        } else {         // V -> fp32
            int vc = col - 64;
            if (r0 < M) *(float2*)&vf[(size_t)r0 * 64 + vc] = make_float2(v00, v01);
            if (r1 < M) *(float2*)&vf[(size_t)r1 * 64 + vc] = make_float2(v10, v11);
        }
    }
}

// ---------------------------------------------------------------------------
// v_mod both branches. bf16 out.
// ---------------------------------------------------------------------------
__global__ void vmod_kernel(const float* __restrict__ lw1, const float* __restrict__ lb1,
                            const float* __restrict__ lw2, const float* __restrict__ lb2) {
    int tid = threadIdx.x;
    int ch = tid & 63;
    int row = blockIdx.x * 4 + (tid >> 6);
    if (row >= M_KV1 + M_KV2) return;

    int b, l, Hr, Wr, Lloc, Lt;
    const float *vf, *lw, *lb;
    __nv_bfloat16* vm;
    if (row < M_KV1) {
        b = row / LT1; l = row - b * LT1;
        Hr = HR1; Wr = WR1; Lloc = L1; Lt = LT1;
        vf = g_v1f; lw = lw1; lb = lb1; vm = g_v1mb;
    } else {
        int r2 = row - M_KV1;
        b = r2 / LT2; l = r2 - b * LT2;
        Hr = HR2; Wr = WR2; Lloc = L2; Lt = LT2;
        vf = g_v2f; lw = lw2; lb = lb2; vm = g_v2mb;
    }
    float self = vf[((size_t)b * Lt + l) * 64 + ch];
    float o;
    if (l < Lloc) {
        int hr = l / Wr, wr = l - hr * Wr;
        float acc = lb[ch];
#pragma unroll
        for (int dy = 0; dy < 3; dy++) {
#pragma unroll
            for (int dx = 0; dx < 3; dx++) {
                int yy = hr + dy - 1, xx = wr + dx - 1;
                if (yy >= 0 && yy < Hr && xx >= 0 && xx < Wr)
                    acc += lw[ch * 9 + dy * 3 + dx] *
                           vf[((size_t)b * Lt + yy * Wr + xx) * 64 + ch];
            }
        }
        o = self + acc;
    } else {
        o = 2.f * self;
    }
    vm[((size_t)b * Lt + l) * 64 + ch] = __float2bfloat16(o);
}

// ---------------------------------------------------------------------------
// bf16 flash attention: 128-query tiles, 8 warps, double-buffered K/V smem,
// Vt stride 66. hg = blockIdx.y ^ 2 so branch-2 (long, 17 chunks) CTAs are
// scheduled FIRST and branch-1 shorties fill the tail waves.
// ---------------------------------------------------------------------------
#define VTS 66
__global__ void attn_mma_kernel() {
    __shared__ __nv_bfloat16 Qs[128][40];
    __shared__ __nv_bfloat16 Ks[2][64][40];
    __shared__ __nv_bfloat16 Vt[2][32][VTS];   // V transposed [d][key]

    const int tid  = threadIdx.x;
    const int warp = tid >> 5;
    const int lane = tid & 31;
    const int qt = blockIdx.x, b = blockIdx.z;
    const int hg = blockIdx.y ^ 2;     // y=0,1 -> hg=2,3 (long branch first)
    const int br = hg >> 1, hh = hg & 1;
    const __nv_bfloat16* kb = br ? g_k2b : g_k1b;
    const __nv_bfloat16* vm = br ? g_v2mb : g_v1mb;
    const int Lt = br ? LT2 : LT1;
    const int n0 = qt * 128;

    const int lr   = tid >> 2;         // 0..63 (load row)
    const int lkof = (tid & 3) * 8;    // 0/8/16/24 (load d-offset)

    // Q tile: 128 rows x 32 d
#pragma unroll
    for (int pass = 0; pass < 2; pass++) {
        int r = lr + pass * 64;
        int n = n0 + r;
        uint4 v = make_uint4(0u, 0u, 0u, 0u);
        if (n < NTOT)
            v = *(const uint4*)(g_qb + ((size_t)b * NTOT + n) * CDIM + hg * DH + lkof);
        *(uint4*)&Qs[r][lkof] = v;
    }

    // preload chunk 0 into buffer 0
    {
        uint4 kv4 = make_uint4(0u, 0u, 0u, 0u);
        uint4 vv4 = make_uint4(0u, 0u, 0u, 0u);
        if (lr < Lt) {
            size_t base = ((size_t)b * Lt + lr) * 64 + hh * DH + lkof;
            kv4 = *(const uint4*)(kb + base);
            vv4 = *(const uint4*)(vm + base);
        }
        *(uint4*)&Ks[0][lr][lkof] = kv4;
        const __nv_bfloat16* vb = (const __nv_bfloat16*)&vv4;
#pragma unroll
        for (int j = 0; j < 8; j++) Vt[0][lkof + j][lr] = vb[j];
    }
    __syncthreads();

    const int fr = lane >> 2;
    const int m2 = (lane & 3) * 2;
    const int r0 = warp * 16 + fr;

    uint32_t qa[2][4];
#pragma unroll
    for (int kt = 0; kt < 2; kt++) {
        qa[kt][0] = *(const uint32_t*)&Qs[r0][kt * 16 + m2];
        qa[kt][1] = *(const uint32_t*)&Qs[r0 + 8][kt * 16 + m2];
        qa[kt][2] = *(const uint32_t*)&Qs[r0][kt * 16 + m2 + 8];
        qa[kt][3] = *(const uint32_t*)&Qs[r0 + 8][kt * 16 + m2 + 8];
    }

    float o[4][4];
#pragma unroll
    for (int i = 0; i < 4; i++)
#pragma unroll
        for (int j = 0; j < 4; j++) o[i][j] = 0.f;
    float m0 = -1e30f, m1 = -1e30f, l0 = 0.f, l1 = 0.f;

    const int nc = (Lt + 63) >> 6;
    for (int ci = 0; ci < nc; ci++) {
        const int c0 = ci << 6;
        const int buf = ci & 1;
        const bool pf = (ci + 1) < nc;

        uint4 kv4n = make_uint4(0u, 0u, 0u, 0u);
        uint4 vv4n = make_uint4(0u, 0u, 0u, 0u);
        if (pf) {
            int gl = c0 + 64 + lr;
            if (gl < Lt) {
                size_t base = ((size_t)b * Lt + gl) * 64 + hh * DH + lkof;
                kv4n = *(const uint4*)(kb + base);
                vv4n = *(const uint4*)(vm + base);
            }
        }

        float s[8][4];
#pragma unroll
        for (int nt = 0; nt < 8; nt++) { s[nt][0] = s[nt][1] = s[nt][2] = s[nt][3] = 0.f; }
#pragma unroll
        for (int nt = 0; nt < 8; nt++) {
#pragma unroll
            for (int kt = 0; kt < 2; kt++) {
                uint32_t b0 = *(const uint32_t*)&Ks[buf][nt * 8 + fr][kt * 16 + m2];
                uint32_t b1 = *(const uint32_t*)&Ks[buf][nt * 8 + fr][kt * 16 + m2 + 8];
                mma_bf16(s[nt], qa[kt][0], qa[kt][1], qa[kt][2], qa[kt][3], b0, b1);
            }
        }

        float mx0 = m0, mx1 = m1;
#pragma unroll
        for (int nt = 0; nt < 8; nt++) {
            int gc = c0 + nt * 8 + m2;
            if (gc >= Lt)     { s[nt][0] = -1e30f; s[nt][2] = -1e30f; }
            if (gc + 1 >= Lt) { s[nt][1] = -1e30f; s[nt][3] = -1e30f; }
            mx0 = fmaxf(mx0, fmaxf(s[nt][0], s[nt][1]));
            mx1 = fmaxf(mx1, fmaxf(s[nt][2], s[nt][3]));
        }
        mx0 = fmaxf(mx0, __shfl_xor_sync(0xffffffffu, mx0, 1));
        mx0 = fmaxf(mx0, __shfl_xor_sync(0xffffffffu, mx0, 2));
        mx1 = fmaxf(mx1, __shfl_xor_sync(0xffffffffu, mx1, 1));
        mx1 = fmaxf(mx1, __shfl_xor_sync(0xffffffffu, mx1, 2));
        float corr0 = __expf(m0 - mx0), corr1 = __expf(m1 - mx1);
        m0 = mx0; m1 = mx1;

        float ls0 = 0.f, ls1 = 0.f;
#pragma unroll
        for (int nt = 0; nt < 8; nt++) {
            s[nt][0] = __expf(s[nt][0] - m0);
            s[nt][1] = __expf(s[nt][1] - m0);
            s[nt][2] = __expf(s[nt][2] - m1);
            s[nt][3] = __expf(s[nt][3] - m1);
            ls0 += s[nt][0] + s[nt][1];
            ls1 += s[nt][2] + s[nt][3];
        }
        ls0 += __shfl_xor_sync(0xffffffffu, ls0, 1);
        ls0 += __shfl_xor_sync(0xffffffffu, ls0, 2);
        ls1 += __shfl_xor_sync(0xffffffffu, ls1, 1);
        ls1 += __shfl_xor_sync(0xffffffffu, ls1, 2);
        l0 = l0 * corr0 + ls0;
        l1 = l1 * corr1 + ls1;
#pragma unroll
        for (int nt = 0; nt < 4; nt++) {
            o[nt][0] *= corr0; o[nt][1] *= corr0;
            o[nt][2] *= corr1; o[nt][3] *= corr1;
        }

#pragma unroll
        for (int kt = 0; kt < 4; kt++) {
            uint32_t a0 = pack_bf16x2(s[2 * kt][0],     s[2 * kt][1]);
            uint32_t a1 = pack_bf16x2(s[2 * kt][2],     s[2 * kt][3]);
            uint32_t a2 = pack_bf16x2(s[2 * kt + 1][0], s[2 * kt + 1][1]);
            uint32_t a3 = pack_bf16x2(s[2 * kt + 1][2], s[2 * kt + 1][3]);
#pragma unroll
            for (int nt = 0; nt < 4; nt++) {
                uint32_t b0 = *(const uint32_t*)&Vt[buf][nt * 8 + fr][kt * 16 + m2];
                uint32_t b1 = *(const uint32_t*)&Vt[buf][nt * 8 + fr][kt * 16 + m2 + 8];
                mma_bf16(o[nt], a0, a1, a2, a3, b0, b1);
            }
        }

        if (pf) {
            *(uint4*)&Ks[buf ^ 1][lr][lkof] = kv4n;
            const __nv_bfloat16* vb = (const __nv_bfloat16*)&vv4n;
#pragma unroll
            for (int j = 0; j < 8; j++) Vt[buf ^ 1][lkof + j][lr] = vb[j];
        }
        __syncthreads();
    }

    float inv0 = 1.f / l0, inv1 = 1.f / l1;
    int nr0 = n0 + r0, nr1 = nr0 + 8;
#pragma unroll
    for (int nt = 0; nt < 4; nt++) {
        int col = hg * DH + nt * 8 + m2;
        if (nr0 < NTOT)
            *(uint32_t*)&g_x12b[((size_t)b * NTOT + nr0) * CDIM + col] =
                pack_bf16x2(o[nt][0] * inv0, o[nt][1] * inv0);
        if (nr1 < NTOT)
            *(uint32_t*)&g_x12b[((size_t)b * NTOT + nr1) * CDIM + col] =
                pack_bf16x2(o[nt][2] * inv1, o[nt][3] * inv1);
    }
}

// ---------------------------------------------------------------------------
// Final projection + residual, split write to harness output.
// ---------------------------------------------------------------------------
__global__ void proj_kernel(const float* __restrict__ projb,
                            const float* __restrict__ resx, const float* __restrict__ resmsg,
                            float* __restrict__ out_img, float* __restrict__ out_msg) {
    __shared__ __nv_bfloat16 Xs[64][40];
    __shared__ __nv_bfloat16 Wsm[128][40];

    const int tid  = threadIdx.x;
    const int warp = tid >> 5;
    const int lane = tid & 31;
    const int mrow = (warp & 3) * 16;
    const int colBase = (warp >> 2) * 64;
    const int rowBase = blockIdx.x * 64;

    const int lrow = tid >> 2;
    const int koff = (tid & 3) * 8;
    const int gr = rowBase + lrow;
    const bool valid = gr < M_Q;
    const int fr = lane >> 2;
    const int m2 = (lane & 3) * 2;

    float c[8][4];
#pragma unroll
    for (int nt = 0; nt < 8; nt++) { c[nt][0] = c[nt][1] = c[nt][2] = c[nt][3] = 0.f; }

    for (int k0 = 0; k0 < CDIM; k0 += 32) {
        uint4 xv = make_uint4(0u, 0u, 0u, 0u);
        if (valid) xv = *(const uint4*)(g_x12b + (size_t)gr * CDIM + k0 + koff);
        *(uint4*)&Xs[lrow][koff] = xv;
        {
            const __nv_bfloat16* wp = g_projwb + (size_t)(tid >> 1) * CDIM + k0 + (tid & 1) * 16;
            *(uint4*)&Wsm[tid >> 1][(tid & 1) * 16]     = *(const uint4*)wp;
            *(uint4*)&Wsm[tid >> 1][(tid & 1) * 16 + 8] = *(const uint4*)(wp + 8);
        }
        __syncthreads();
#pragma unroll
        for (int kt = 0; kt < 2; kt++) {
            uint32_t a0 = *(const uint32_t*)&Xs[mrow + fr][kt * 16 + m2];
            uint32_t a1 = *(const uint32_t*)&Xs[mrow + fr + 8][kt * 16 + m2];
            uint32_t a2 = *(const uint32_t*)&Xs[mrow + fr][kt * 16 + m2 + 8];
            uint32_t a3 = *(const uint32_t*)&Xs[mrow + fr + 8][kt * 16 + m2 + 8];
#pragma unroll
            for (int nt = 0; nt < 8; nt++) {
                uint32_t b0 = *(const uint32_t*)&Wsm[colBase + nt * 8 + fr][kt * 16 + m2];
                uint32_t b1 = *(const uint32_t*)&Wsm[colBase + nt * 8 + fr][kt * 16 + m2 + 8];
                mma_bf16(c[nt], a0, a1, a2, a3, b0, b1);
            }
        }
        __syncthreads();
    }

    const int r0 = rowBase + mrow + fr;
    const int r1 = r0 + 8;
#pragma unroll
    for (int nt = 0; nt < 8; nt++) {
        int col = colBase + nt * 8 + m2;
        float bb0 = projb[col], bb1 = projb[col + 1];
        if (r0 < M_Q) {
            int b = r0 / NTOT, n = r0 - b * NTOT;
            if (n < N0) {
                size_t oo = ((size_t)b * N0 + n) * CDIM + col;
                *(float2*)&out_img[oo] = make_float2(c[nt][0] + bb0 + resx[oo],
                                                     c[nt][1] + bb1 + resx[oo + 1]);
            } else {
                size_t oo = ((size_t)b * NMSG + (n - N0)) * CDIM + col;
                *(float2*)&out_msg[oo] = make_float2(c[nt][0] + bb0 + resmsg[oo],
                                                     c[nt][1] + bb1 + resmsg[oo + 1]);
            }
        }
        if (r1 < M_Q) {
            int b = r1 / NTOT, n = r1 - b * NTOT;
            if (n < N0) {
                size_t oo = ((size_t)b * N0 + n) * CDIM + col;
                *(float2*)&out_img[oo] = make_float2(c[nt][2] + bb0 + resx[oo],
                                                     c[nt][3] + bb1 + resx[oo + 1]);
            } else {
                size_t oo = ((size_t)b * NMSG + (n - N0)) * CDIM + col;
                *(float2*)&out_msg[oo] = make_float2(c[nt][2] + bb0 + resmsg[oo],
                                                     c[nt][3] + bb1 + resmsg[oo + 1]);
            }
        }
    }
}

// ---------------------------------------------------------------------------
extern "C" void kernel_launch(void* const* d_in, const int* in_sizes, int n_in,
                              void* d_out, int out_size) {
    const float* x     = (const float*)d_in[0];
    const float* msg   = (const float*)d_in[1];
    const float* Wq    = (const float*)d_in[2];
    const float* bq    = (const float*)d_in[3];
    const float* sr1w  = (const float*)d_in[4];
    const float* sr1b  = (const float*)d_in[5];
    const float* ln1g  = (const float*)d_in[6];
    const float* ln1b  = (const float*)d_in[7];
    const float* sr2w  = (const float*)d_in[8];
    const float* sr2b  = (const float*)d_in[9];
    const float* ln2g  = (const float*)d_in[10];
    const float* ln2b  = (const float*)d_in[11];
    const float* kv1w  = (const float*)d_in[12];
    const float* kv1b  = (const float*)d_in[13];
    const float* kv2w  = (const float*)d_in[14];
    const float* kv2b  = (const float*)d_in[15];
    const float* lc1w  = (const float*)d_in[16];
    const float* lc1b  = (const float*)d_in[17];
    const float* lc2w  = (const float*)d_in[18];
    const float* lc2b  = (const float*)d_in[19];
    const float* projw = (const float*)d_in[20];
    const float* projb = (const float*)d_in[21];
    (void)in_sizes; (void)n_in; (void)out_size;

    float* out_img = (float*)d_out;
    float* out_msg = out_img + (size_t)BSZ * N0 * CDIM;

    // 1. all conversions / weight prep in one launch
    prep_kernel<<<PS9, 256>>>(x, msg, Wq, kv1w, kv2w, projw, sr1w, sr2w);

    // 2. PATCH1 + PATCH2 + Q GEMMs in one launch (long jobs scheduled first)
    stage1_kernel<<<STAGE1_GRID, 256>>>(bq);

    // 3. partial-sum + SR bias + msg matvec + LN + GELU -> bf16
    lnfuse_kernel<<<M_KV1 + M_KV2, 128>>>(msg, sr1b, sr2b, ln1g, ln1b, ln2g, ln2b);

    // 4. KV projections (both branches, column-split); K->bf16, V->fp32
    kv_kernel<<<KV_GRID, 256>>>(kv1b, kv2b);

    // 5. V augmentation -> bf16
    vmod_kernel<<<(M_KV1 + M_KV2 + 3) / 4, 256>>>(lc1w, lc1b, lc2w, lc2b);

    // 6. attention (branch-2 heads scheduled first), writes g_x12b
    {
        dim3 grid((NTOT + 127) / 128, 4, BSZ);
        attn_mma_kernel<<<grid, 256>>>();
    }

    // 7. output projection + residual, split write
    proj_kernel<<<NQ_TILES, 256>>>(projb, x, msg, out_img, out_msg);
}

// round 15
// speedup vs baseline: 1.3777x; 1.0263x over previous
#include <cuda_runtime.h>
#include <cuda_bf16.h>
#include <stdint.h>
#include <math.h>

#define BSZ   8
#define N0    4096
#define NMSG  4
#define NTOT  4100
#define CDIM  128
#define DH    32
// 1/sqrt(32) * log2(e): softmax computed in base-2 domain
#define ATT_SCALE_LOG2 0.255034863f

#define L1   256
#define LT1  260
#define HR1  16
#define WR1  16
#define L2   1024
#define LT2  1028
#define HR2  32
#define WR2  32

#define M_Q   (BSZ * NTOT)   // 32800
#define M_P1  (BSZ * L1)     // 2048
#define M_P2  (BSZ * L2)     // 8192
#define M_KV1 (BSZ * LT1)    // 2080
#define M_KV2 (BSZ * LT2)    // 8224

// stage1 grid layout: LONG jobs (PATCH, K=512) first, short Q tiles last.
#define NQ_TILES  ((M_Q + 63) / 64)            // 513
#define P1_TILES  (M_P1 / 64)                  // 32
#define KSPLIT1   4
#define P1_BLKS   (P1_TILES * KSPLIT1)         // 128
#define P2_TILES  (M_P2 / 64)                  // 128
#define STAGE1_GRID (NQ_TILES + P1_BLKS + P2_TILES)

// kv grid (column-split x2 for occupancy)
#define KV1_TILES ((M_KV1 + 63) / 64)          // 33
#define KV2_TILES ((M_KV2 + 63) / 64)          // 129
#define KV_GRID   ((KV1_TILES + KV2_TILES) * 2)

// ---------------- scratch (static device globals; no allocs) ----------------
__device__ float g_p1[KSPLIT1 * M_P1 * CDIM];  // PATCH1 K-split partials (no bias)
__device__ float g_p2[M_P2 * CDIM];            // PATCH2 output (no bias)
__device__ float g_v1f[M_KV1 * 64];            // V fp32 (pre-dwconv)
__device__ float g_v2f[M_KV2 * 64];
__device__ float g_ws1[CDIM * CDIM];           // transposed summed SR weights [c][o]
__device__ float g_ws2[CDIM * CDIM];

__device__ __nv_bfloat16 g_xb[BSZ * N0 * CDIM];
__device__ __nv_bfloat16 g_msgb[BSZ * NMSG * CDIM];
__device__ __nv_bfloat16 g_qb[M_Q * CDIM];     // Q (pre-scaled, log2-domain)
__device__ __nv_bfloat16 g_xk1b[M_KV1 * CDIM]; // post LN+GELU
__device__ __nv_bfloat16 g_xk2b[M_KV2 * CDIM];
__device__ __nv_bfloat16 g_k1b[M_KV1 * 64];    // K bf16
__device__ __nv_bfloat16 g_k2b[M_KV2 * 64];
__device__ __nv_bfloat16 g_v1mb[M_KV1 * 64];   // V + dwconv, bf16
__device__ __nv_bfloat16 g_v2mb[M_KV2 * 64];
__device__ __nv_bfloat16 g_x12b[M_Q * CDIM];   // attention outputs

__device__ __nv_bfloat16 g_wqb[CDIM * CDIM];
__device__ __nv_bfloat16 g_sr1wb[CDIM * CDIM * 16]; // [o][pos*128+c]
__device__ __nv_bfloat16 g_sr2wb[CDIM * CDIM * 4];
__device__ __nv_bfloat16 g_kv1wb[CDIM * CDIM];
__device__ __nv_bfloat16 g_kv2wb[CDIM * CDIM];
__device__ __nv_bfloat16 g_projwb[CDIM * CDIM];

// ---------------------------------------------------------------------------
__device__ __forceinline__ void mma_bf16(float c[4],
                                         uint32_t a0, uint32_t a1, uint32_t a2, uint32_t a3,
                                         uint32_t b0, uint32_t b1) {
    asm volatile(
        "mma.sync.aligned.m16n8k16.row.col.f32.bf16.bf16.f32 "
        "{%0,%1,%2,%3}, {%4,%5,%6,%7}, {%8,%9}, {%0,%1,%2,%3};"
        : "+f"(c[0]), "+f"(c[1]), "+f"(c[2]), "+f"(c[3])
        : "r"(a0), "r"(a1), "r"(a2), "r"(a3), "r"(b0), "r"(b1));
}

__device__ __forceinline__ uint32_t pack_bf16x2(float lo, float hi) {
    __nv_bfloat162 h = __floats2bfloat162_rn(lo, hi);
    return *reinterpret_cast<uint32_t*>(&h);
}

// ---------------------------------------------------------------------------
// prep: all fp32->bf16 conversions, SR weight reorder, summed-SR weights.
// ---------------------------------------------------------------------------
#define PS0 4096                  // xb (float4 per thread)
#define PS1 (PS0 + 16)            // msgb
#define PS2 (PS1 + 64)            // wqb
#define PS3 (PS2 + 64)            // kv1wb
#define PS4 (PS3 + 64)            // kv2wb
#define PS5 (PS4 + 64)            // projwb
#define PS6 (PS5 + 1024)          // wreorder sr1
#define PS7 (PS6 + 256)           // wreorder sr2
#define PS8 (PS7 + 64)            // wsum1
#define PS9 (PS8 + 64)            // wsum2   -> grid = PS9

__global__ void prep_kernel(const float* __restrict__ x,   const float* __restrict__ msg,
                            const float* __restrict__ Wq,  const float* __restrict__ kv1w,
                            const float* __restrict__ kv2w, const float* __restrict__ projw,
                            const float* __restrict__ sr1w, const float* __restrict__ sr2w) {
    int bid = blockIdx.x, t = threadIdx.x;
    if (bid < PS0) {
        int i = (bid * 256 + t) * 4;
        float4 v = *(const float4*)(x + i);
        __nv_bfloat16* o = g_xb + i;
        o[0] = __float2bfloat16(v.x); o[1] = __float2bfloat16(v.y);
        o[2] = __float2bfloat16(v.z); o[3] = __float2bfloat16(v.w);
    } else if (bid < PS1) {
        int i = (bid - PS0) * 256 + t;
        g_msgb[i] = __float2bfloat16(msg[i]);
    } else if (bid < PS2) {
        int i = (bid - PS1) * 256 + t;  g_wqb[i]   = __float2bfloat16(Wq[i]);
    } else if (bid < PS3) {
        int i = (bid - PS2) * 256 + t;  g_kv1wb[i] = __float2bfloat16(kv1w[i]);
    } else if (bid < PS4) {
        int i = (bid - PS3) * 256 + t;  g_kv2wb[i] = __float2bfloat16(kv2w[i]);
    } else if (bid < PS5) {
        int i = (bid - PS4) * 256 + t;  g_projwb[i] = __float2bfloat16(projw[i]);
    } else if (bid < PS6) {
        int idx = (bid - PS5) * 256 + t;          // [o][c][pos] src
        int o = idx >> 11;                         // / (128*16)
        int rem = idx & 2047;
        int cch = rem >> 4, pos = rem & 15;
        g_sr1wb[(size_t)o * 2048 + pos * CDIM + cch] = __float2bfloat16(sr1w[idx]);
    } else if (bid < PS7) {
        int idx = (bid - PS6) * 256 + t;
        int o = idx >> 9;                          // / (128*4)
        int rem = idx & 511;
        int cch = rem >> 2, pos = rem & 3;
        g_sr2wb[(size_t)o * 512 + pos * CDIM + cch] = __float2bfloat16(sr2w[idx]);
    } else if (bid < PS8) {
        int idx = (bid - PS7) * 256 + t;
        int c = idx >> 7, o = idx & 127;
        const float* p = sr1w + (o * CDIM + c) * 16;
        float s = 0.f;
#pragma unroll
        for (int i = 0; i < 16; i++) s += p[i];
        g_ws1[c * CDIM + o] = s;
    } else {
        int idx = (bid - PS8) * 256 + t;
        int c = idx >> 7, o = idx & 127;
        const float* p = sr2w + (o * CDIM + c) * 4;
        float s = 0.f;
#pragma unroll
        for (int i = 0; i < 4; i++) s += p[i];
        g_ws2[c * CDIM + o] = s;
    }
}

// ---------------------------------------------------------------------------
// stage1: Q projection + both SR patch-embed GEMMs in ONE launch.
// PATCH first (long), Q last (short). DOUBLE-BUFFERED k-loop: one sync/chunk,
// next chunk's X+W prefetched into registers during the MMA block.
// ---------------------------------------------------------------------------
__global__ void stage1_kernel(const float* __restrict__ bq) {
    __shared__ __nv_bfloat16 Xs[2][64][40];
    __shared__ __nv_bfloat16 Wsm[2][128][40];

    const int tid  = threadIdx.x;
    const int warp = tid >> 5;
    const int lane = tid & 31;
    const int mrow = (warp & 3) * 16;
    const int colBase = (warp >> 2) * 64;
    const int bid = blockIdx.x;

    int mode, S = 4, rowBase, K, kbase = 0, KTOT, M, Lloc = L1;
    const __nv_bfloat16* Wb;
    float* outP = nullptr;
    if (bid < P1_BLKS) {                       // PATCH1 first (longest)
        int q = bid;
        mode = 1; S = 4; Lloc = L1;
        rowBase = (q >> 2) * 64;
        int kseg = q & 3;
        K = 512; kbase = kseg * 512; KTOT = 2048; M = M_P1;
        Wb = g_sr1wb; outP = g_p1 + (size_t)kseg * M_P1 * CDIM;
    } else if (bid < P1_BLKS + P2_TILES) {     // PATCH2 next
        int q = bid - P1_BLKS;
        mode = 1; S = 2; Lloc = L2;
        rowBase = q * 64;
        K = 512; kbase = 0; KTOT = 512; M = M_P2;
        Wb = g_sr2wb; outP = g_p2;
    } else {                                   // Q tiles last (short, K=128)
        int q = bid - P1_BLKS - P2_TILES;
        mode = 0; rowBase = q * 64; K = 128; KTOT = 128; M = M_Q; Wb = g_wqb;
    }

    const int lrow = tid >> 2;
    const int koff = (tid & 3) * 8;
    const int gr = rowBase + lrow;
    const bool valid = gr < M;

    const __nv_bfloat16* srcRow = nullptr;
    int pb = 0, phr = 0, pwr = 0;
    if (mode == 0) {
        if (valid) {
            int b = gr / NTOT, n = gr - b * NTOT;
            srcRow = (n < N0) ? g_xb + ((size_t)b * N0 + n) * CDIM
                              : g_msgb + ((size_t)b * NMSG + (n - N0)) * CDIM;
        }
    } else {
        if (valid) {
            pb = gr / Lloc; int l = gr - pb * Lloc;
            int Wr = (S == 4) ? WR1 : WR2;
            phr = l / Wr; pwr = l - phr * Wr;
        }
    }

    const int fr = lane >> 2;
    const int m2 = (lane & 3) * 2;

    float c[8][4];
#pragma unroll
    for (int nt = 0; nt < 8; nt++) { c[nt][0] = c[nt][1] = c[nt][2] = c[nt][3] = 0.f; }

    const int nch = K >> 5;

    // chunk loader (registers)
    auto loadX = [&](int k0, uint4& xv) {
        xv = make_uint4(0u, 0u, 0u, 0u);
        if (valid) {
            if (mode == 1) {
                int gk = kbase + k0;
                int pos = gk >> 7;
                int ky = (S == 4) ? (pos >> 2) : (pos >> 1);
                int kx = (S == 4) ? (pos & 3)  : (pos & 1);
                int p = (phr * S + ky) * 64 + pwr * S + kx;
                xv = *(const uint4*)(g_xb + ((size_t)pb * N0 + p) * CDIM + (gk & 127) + koff);
            } else {
                xv = *(const uint4*)(srcRow + k0 + koff);
            }
        }
    };
    auto loadW = [&](int k0, uint4& w0, uint4& w1) {
        const __nv_bfloat16* wp = Wb + (size_t)(tid >> 1) * KTOT + kbase + k0 + (tid & 1) * 16;
        w0 = *(const uint4*)wp;
        w1 = *(const uint4*)(wp + 8);
    };

    // preload chunk 0 into buffer 0
    {
        uint4 xv, w0, w1;
        loadX(0, xv); loadW(0, w0, w1);
        *(uint4*)&Xs[0][lrow][koff] = xv;
        *(uint4*)&Wsm[0][tid >> 1][(tid & 1) * 16]     = w0;
        *(uint4*)&Wsm[0][tid >> 1][(tid & 1) * 16 + 8] = w1;
    }
    __syncthreads();

    for (int ci = 0; ci < nch; ci++) {
        const int buf = ci & 1;
        const bool pf = (ci + 1) < nch;
        uint4 xn, wn0, wn1;
        if (pf) { loadX((ci + 1) * 32, xn); loadW((ci + 1) * 32, wn0, wn1); }

#pragma unroll
        for (int kt = 0; kt < 2; kt++) {
            uint32_t a0 = *(const uint32_t*)&Xs[buf][mrow + fr][kt * 16 + m2];
            uint32_t a1 = *(const uint32_t*)&Xs[buf][mrow + fr + 8][kt * 16 + m2];
            uint32_t a2 = *(const uint32_t*)&Xs[buf][mrow + fr][kt * 16 + m2 + 8];
            uint32_t a3 = *(const uint32_t*)&Xs[buf][mrow + fr + 8][kt * 16 + m2 + 8];
#pragma unroll
            for (int nt = 0; nt < 8; nt++) {
                uint32_t b0 = *(const uint32_t*)&Wsm[buf][colBase + nt * 8 + fr][kt * 16 + m2];
                uint32_t b1 = *(const uint32_t*)&Wsm[buf][colBase + nt * 8 + fr][kt * 16 + m2 + 8];
                mma_bf16(c[nt], a0, a1, a2, a3, b0, b1);
            }
        }

        if (pf) {
            *(uint4*)&Xs[buf ^ 1][lrow][koff] = xn;
            *(uint4*)&Wsm[buf ^ 1][tid >> 1][(tid & 1) * 16]     = wn0;
            *(uint4*)&Wsm[buf ^ 1][tid >> 1][(tid & 1) * 16 + 8] = wn1;
        }
        __syncthreads();
    }

    const int r0 = rowBase + mrow + fr;
    const int r1 = r0 + 8;
#pragma unroll
    for (int nt = 0; nt < 8; nt++) {
        int col = colBase + nt * 8 + m2;
        if (mode == 0) {
            float bb0 = bq[col], bb1 = bq[col + 1];
            if (r0 < M) *(uint32_t*)&g_qb[(size_t)r0 * CDIM + col] =
                pack_bf16x2((c[nt][0] + bb0) * ATT_SCALE_LOG2, (c[nt][1] + bb1) * ATT_SCALE_LOG2);
            if (r1 < M) *(uint32_t*)&g_qb[(size_t)r1 * CDIM + col] =
                pack_bf16x2((c[nt][2] + bb0) * ATT_SCALE_LOG2, (c[nt][3] + bb1) * ATT_SCALE_LOG2);
        } else {
            if (r0 < M) *(float2*)&outP[(size_t)r0 * CDIM + col] = make_float2(c[nt][0], c[nt][1]);
            if (r1 < M) *(float2*)&outP[(size_t)r1 * CDIM + col] = make_float2(c[nt][2], c[nt][3]);
        }
    }
}

// ---------------------------------------------------------------------------
// LN+GELU fused: sums PATCH partials (+SR bias), msg-token SR matvec, LN+GELU.
// ---------------------------------------------------------------------------
__global__ void lnfuse_kernel(const float* __restrict__ msg,
                              const float* __restrict__ sr1b, const float* __restrict__ sr2b,
                              const float* __restrict__ ln1g, const float* __restrict__ ln1b,
                              const float* __restrict__ ln2g, const float* __restrict__ ln2b) {
    __shared__ float sm1[4], sm2[4];
    __shared__ float mrow[CDIM];
    int bid = blockIdx.x;
    int t = threadIdx.x, w = t >> 5, lane = t & 31;

    int br, b, l;
    if (bid < M_KV1) { br = 0; b = bid / LT1; l = bid - b * LT1; }
    else { int r2 = bid - M_KV1; br = 1; b = r2 / LT2; l = r2 - b * LT2; }

    const int Lloc = br ? L2 : L1;
    float v;
    if (l < Lloc) {
        if (br == 0) {
            size_t o = ((size_t)b * L1 + l) * CDIM + t;
            v = g_p1[o] + g_p1[(size_t)M_P1 * CDIM + o] + g_p1[(size_t)2 * M_P1 * CDIM + o]
              + g_p1[(size_t)3 * M_P1 * CDIM + o] + sr1b[t];
        } else {
            v = g_p2[((size_t)b * L2 + l) * CDIM + t] + sr2b[t];
        }
    } else {
        int n = l - Lloc;
        mrow[t] = msg[((size_t)b * NMSG + n) * CDIM + t];
        __syncthreads();
        const float* wsT = br ? g_ws2 : g_ws1;
        float a0 = 0.f, a1 = 0.f, a2 = 0.f, a3 = 0.f;
#pragma unroll 8
        for (int cc = 0; cc < CDIM; cc += 4) {
            a0 += mrow[cc + 0] * wsT[(cc + 0) * CDIM + t];
            a1 += mrow[cc + 1] * wsT[(cc + 1) * CDIM + t];
            a2 += mrow[cc + 2] * wsT[(cc + 2) * CDIM + t];
            a3 += mrow[cc + 3] * wsT[(cc + 3) * CDIM + t];
        }
        v = (a0 + a1) + (a2 + a3) + (br ? sr2b[t] : sr1b[t]);
    }
    __syncthreads();

    float s1 = v, s2 = v * v;
#pragma unroll
    for (int off = 16; off > 0; off >>= 1) {
        s1 += __shfl_xor_sync(0xffffffffu, s1, off);
        s2 += __shfl_xor_sync(0xffffffffu, s2, off);
    }
    if (lane == 0) { sm1[w] = s1; sm2[w] = s2; }
    __syncthreads();
    s1 = (sm1[0] + sm1[1]) + (sm1[2] + sm1[3]);
    s2 = (sm2[0] + sm2[1]) + (sm2[2] + sm2[3]);
    float mu  = s1 * (1.f / 128.f);
    float var = fmaxf(s2 * (1.f / 128.f) - mu * mu, 0.f);
    const float* g  = br ? ln2g : ln1g;
    const float* be = br ? ln2b : ln1b;
    float y = (v - mu) * rsqrtf(var + 1e-5f) * g[t] + be[t];
    float gel = 0.5f * y * (1.f + erff(y * 0.70710678118654752f));
    __nv_bfloat16* ob = br ? g_xk2b : g_xk1b;
    size_t row = br ? ((size_t)b * LT2 + l) : ((size_t)b * LT1 + l);
    ob[row * CDIM + t] = __float2bfloat16(gel);
}

// ---------------------------------------------------------------------------
// KV projections, both branches, COLUMN-SPLIT x2, DOUBLE-BUFFERED k-loop.
// ---------------------------------------------------------------------------
__global__ void kv_kernel(const float* __restrict__ kv1b_, const float* __restrict__ kv2b_) {
    __shared__ __nv_bfloat16 Xs[2][64][40];
    __shared__ __nv_bfloat16 Wsm[2][64][40];

    const int tid  = threadIdx.x;
    const int warp = tid >> 5;
    const int lane = tid & 31;
    const int mrow = (warp & 3) * 16;
    const int colBase = (warp >> 2) * 32;   // 0 or 32 within the half
    const int colHalf = (blockIdx.x & 1) * 64;
    const int bid = blockIdx.x >> 1;

    int rowBase, M;
    const __nv_bfloat16 *Ab, *Wb;
    const float* bias;
    __nv_bfloat16* kb;
    float* vf;
    if (bid < KV1_TILES) {
        rowBase = bid * 64; M = M_KV1;
        Ab = g_xk1b; Wb = g_kv1wb; bias = kv1b_; kb = g_k1b; vf = g_v1f;
    } else {
        rowBase = (bid - KV1_TILES) * 64; M = M_KV2;
        Ab = g_xk2b; Wb = g_kv2wb; bias = kv2b_; kb = g_k2b; vf = g_v2f;
    }

    const int lrow = tid >> 2;
    const int koff = (tid & 3) * 8;
    const int gr = rowBase + lrow;
    const bool valid = gr < M;
    const int fr = lane >> 2;
    const int m2 = (lane & 3) * 2;

    float c[4][4];
#pragma unroll
    for (int nt = 0; nt < 4; nt++) { c[nt][0] = c[nt][1] = c[nt][2] = c[nt][3] = 0.f; }

    // preload chunk 0
    {
        uint4 xv = make_uint4(0u, 0u, 0u, 0u);
        if (valid) xv = *(const uint4*)(Ab + (size_t)gr * CDIM + koff);
        *(uint4*)&Xs[0][lrow][koff] = xv;
        *(uint4*)&Wsm[0][lrow][koff] =
            *(const uint4*)(Wb + (size_t)(colHalf + lrow) * CDIM + koff);
    }
    __syncthreads();

#pragma unroll
    for (int ci = 0; ci < 4; ci++) {
        const int buf = ci & 1;
        const bool pf = (ci + 1) < 4;
        uint4 xn = make_uint4(0u, 0u, 0u, 0u), wn = make_uint4(0u, 0u, 0u, 0u);
        if (pf) {
            int k0 = (ci + 1) * 32;
            if (valid) xn = *(const uint4*)(Ab + (size_t)gr * CDIM + k0 + koff);
            wn = *(const uint4*)(Wb + (size_t)(colHalf + lrow) * CDIM + k0 + koff);
        }

#pragma unroll
        for (int kt = 0; kt < 2; kt++) {
            uint32_t a0 = *(const uint32_t*)&Xs[buf][mrow + fr][kt * 16 + m2];
            uint32_t a1 = *(const uint32_t*)&Xs[buf][mrow + fr + 8][kt * 16 + m2];
            uint32_t a2 = *(const uint32_t*)&Xs[buf][mrow + fr][kt * 16 + m2 + 8];
            uint32_t a3 = *(const uint32_t*)&Xs[buf][mrow + fr + 8][kt * 16 + m2 + 8];
#pragma unroll
            for (int nt = 0; nt < 4; nt++) {
                uint32_t b0 = *(const uint32_t*)&Wsm[buf][colBase + nt * 8 + fr][kt * 16 + m2];
                uint32_t b1 = *(const uint32_t*)&Wsm[buf][colBase + nt * 8 + fr][kt * 16 + m2 + 8];
                mma_bf16(c[nt], a0, a1, a2, a3, b0, b1);
            }
        }

        if (pf) {
            *(uint4*)&Xs[buf ^ 1][lrow][koff] = xn;
            *(uint4*)&Wsm[buf ^ 1][lrow][koff] = wn;
        }
        __syncthreads();
    }

    const int r0 = rowBase + mrow + fr;
    const int r1 = r0 + 8;
#pragma unroll
    for (int nt = 0; nt < 4; nt++) {
        int col = colHalf + colBase + nt * 8 + m2;
        float bb0 = bias[col], bb1 = bias[col + 1];
        float v00 = c[nt][0] + bb0, v01 = c[nt][1] + bb1;
        float v10 = c[nt][2] + bb0, v11 = c[nt][3] + bb1;
        if (col < 64) {  // K -> bf16
            if (r0 < M) *(uint32_t*)&kb[(size_t)r0 * 64 + col] = pack_bf16x2(v00, v01);
            if (r1 < M) *(uint32_t*)&kb[(size_t)r1 * 64 + col] = pack_bf16x2(v10, v11);
        } else {         // V -> fp32
            int vc = col - 64;
            if (r0 < M) *(float2*)&vf[(size_t)r0 * 64 + vc] = make_float2(v00, v01);
            if (r1 < M) *(float2*)&vf[(size_t)r1 * 64 + vc] = make_float2(v10, v11);
        }
    }
}

// ---------------------------------------------------------------------------
// v_mod both branches. bf16 out.
// ---------------------------------------------------------------------------
__global__ void vmod_kernel(const float* __restrict__ lw1, const float* __restrict__ lb1,
                            const float* __restrict__ lw2, const float* __restrict__ lb2) {
    int tid = threadIdx.x;
    int ch = tid & 63;
    int row = blockIdx.x * 4 + (tid >> 6);
    if (row >= M_KV1 + M_KV2) return;

    int b, l, Hr, Wr, Lloc, Lt;
    const float *vf, *lw, *lb;
    __nv_bfloat16* vm;
    if (row < M_KV1) {
        b = row / LT1; l = row - b * LT1;
        Hr = HR1; Wr = WR1; Lloc = L1; Lt = LT1;
        vf = g_v1f; lw = lw1; lb = lb1; vm = g_v1mb;
    } else {
        int r2 = row - M_KV1;
        b = r2 / LT2; l = r2 - b * LT2;
        Hr = HR2; Wr = WR2; Lloc = L2; Lt = LT2;
        vf = g_v2f; lw = lw2; lb = lb2; vm = g_v2mb;
    }
    float self = vf[((size_t)b * Lt + l) * 64 + ch];
    float o;
    if (l < Lloc) {
        int hr = l / Wr, wr = l - hr * Wr;
        float acc = lb[ch];
#pragma unroll
        for (int dy = 0; dy < 3; dy++) {
#pragma unroll
            for (int dx = 0; dx < 3; dx++) {
                int yy = hr + dy - 1, xx = wr + dx - 1;
                if (yy >= 0 && yy < Hr && xx >= 0 && xx < Wr)
                    acc += lw[ch * 9 + dy * 3 + dx] *
                           vf[((size_t)b * Lt + yy * Wr + xx) * 64 + ch];
            }
        }
        o = self + acc;
    } else {
        o = 2.f * self;
    }
    vm[((size_t)b * Lt + l) * 64 + ch] = __float2bfloat16(o);
}

// ---------------------------------------------------------------------------
// bf16 flash attention: 128-q tiles, 8 warps, double-buffered K/V, base-2
// softmax (Q pre-scaled by log2e; exp2f = bare MUFU.EX2).
// hg = blockIdx.y ^ 2: long branch scheduled first.
// ---------------------------------------------------------------------------
#define VTS 66
__global__ void attn_mma_kernel() {
    __shared__ __nv_bfloat16 Qs[128][40];
    __shared__ __nv_bfloat16 Ks[2][64][40];
    __shared__ __nv_bfloat16 Vt[2][32][VTS];   // V transposed [d][key]

    const int tid  = threadIdx.x;
    const int warp = tid >> 5;
    const int lane = tid & 31;
    const int qt = blockIdx.x, b = blockIdx.z;
    const int hg = blockIdx.y ^ 2;
    const int br = hg >> 1, hh = hg & 1;
    const __nv_bfloat16* kb = br ? g_k2b : g_k1b;
    const __nv_bfloat16* vm = br ? g_v2mb : g_v1mb;
    const int Lt = br ? LT2 : LT1;
    const int n0 = qt * 128;

    const int lr   = tid >> 2;
    const int lkof = (tid & 3) * 8;

    // Q tile: 128 rows x 32 d
#pragma unroll
    for (int pass = 0; pass < 2; pass++) {
        int r = lr + pass * 64;
        int n = n0 + r;
        uint4 v = make_uint4(0u, 0u, 0u, 0u);
        if (n < NTOT)
            v = *(const uint4*)(g_qb + ((size_t)b * NTOT + n) * CDIM + hg * DH + lkof);
        *(uint4*)&Qs[r][lkof] = v;
    }

    // preload chunk 0 into buffer 0
    {
        uint4 kv4 = make_uint4(0u, 0u, 0u, 0u);
        uint4 vv4 = make_uint4(0u, 0u, 0u, 0u);
        if (lr < Lt) {
            size_t base = ((size_t)b * Lt + lr) * 64 + hh * DH + lkof;
            kv4 = *(const uint4*)(kb + base);
            vv4 = *(const uint4*)(vm + base);
        }
        *(uint4*)&Ks[0][lr][lkof] = kv4;
        const __nv_bfloat16* vb = (const __nv_bfloat16*)&vv4;
#pragma unroll
        for (int j = 0; j < 8; j++) Vt[0][lkof + j][lr] = vb[j];
    }
    __syncthreads();

    const int fr = lane >> 2;
    const int m2 = (lane & 3) * 2;
    const int r0 = warp * 16 + fr;

    uint32_t qa[2][4];
#pragma unroll
    for (int kt = 0; kt < 2; kt++) {
        qa[kt][0] = *(const uint32_t*)&Qs[r0][kt * 16 + m2];
        qa[kt][1] = *(const uint32_t*)&Qs[r0 + 8][kt * 16 + m2];
        qa[kt][2] = *(const uint32_t*)&Qs[r0][kt * 16 + m2 + 8];
        qa[kt][3] = *(const uint32_t*)&Qs[r0 + 8][kt * 16 + m2 + 8];
    }

    float o[4][4];
#pragma unroll
    for (int i = 0; i < 4; i++)
#pragma unroll
        for (int j = 0; j < 4; j++) o[i][j] = 0.f;
    float m0 = -1e30f, m1 = -1e30f, l0 = 0.f, l1 = 0.f;

    const int nc = (Lt + 63) >> 6;
    for (int ci = 0; ci < nc; ci++) {
        const int c0 = ci << 6;
        const int buf = ci & 1;
        const bool pf = (ci + 1) < nc;

        uint4 kv4n = make_uint4(0u, 0u, 0u, 0u);
        uint4 vv4n = make_uint4(0u, 0u, 0u, 0u);
        if (pf) {
            int gl = c0 + 64 + lr;
            if (gl < Lt) {
                size_t base = ((size_t)b * Lt + gl) * 64 + hh * DH + lkof;
                kv4n = *(const uint4*)(kb + base);
                vv4n = *(const uint4*)(vm + base);
            }
        }

        float s[8][4];
#pragma unroll
        for (int nt = 0; nt < 8; nt++) { s[nt][0] = s[nt][1] = s[nt][2] = s[nt][3] = 0.f; }
#pragma unroll
        for (int nt = 0; nt < 8; nt++) {
#pragma unroll
            for (int kt = 0; kt < 2; kt++) {
                uint32_t b0 = *(const uint32_t*)&Ks[buf][nt * 8 + fr][kt * 16 + m2];
                uint32_t b1 = *(const uint32_t*)&Ks[buf][nt * 8 + fr][kt * 16 + m2 + 8];
                mma_bf16(s[nt], qa[kt][0], qa[kt][1], qa[kt][2], qa[kt][3], b0, b1);
            }
        }

        float mx0 = m0, mx1 = m1;
#pragma unroll
        for (int nt = 0; nt < 8; nt++) {
            int gc = c0 + nt * 8 + m2;
            if (gc >= Lt)     { s[nt][0] = -1e30f; s[nt][2] = -1e30f; }
            if (gc + 1 >= Lt) { s[nt][1] = -1e30f; s[nt][3] = -1e30f; }
            mx0 = fmaxf(mx0, fmaxf(s[nt][0], s[nt][1]));
            mx1 = fmaxf(mx1, fmaxf(s[nt][2], s[nt][3]));
        }
        mx0 = fmaxf(mx0, __shfl_xor_sync(0xffffffffu, mx0, 1));
        mx0 = fmaxf(mx0, __shfl_xor_sync(0xffffffffu, mx0, 2));
        mx1 = fmaxf(mx1, __shfl_xor_sync(0xffffffffu, mx1, 1));
        mx1 = fmaxf(mx1, __shfl_xor_sync(0xffffffffu, mx1, 2));
        float corr0 = exp2f(m0 - mx0), corr1 = exp2f(m1 - mx1);
        m0 = mx0; m1 = mx1;

        float ls0 = 0.f, ls1 = 0.f;
#pragma unroll
        for (int nt = 0; nt < 8; nt++) {
            s[nt][0] = exp2f(s[nt][0] - m0);
            s[nt][1] = exp2f(s[nt][1] - m0);
            s[nt][2] = exp2f(s[nt][2] - m1);
            s[nt][3] = exp2f(s[nt][3] - m1);
            ls0 += s[nt][0] + s[nt][1];
            ls1 += s[nt][2] + s[nt][3];
        }
        ls0 += __shfl_xor_sync(0xffffffffu, ls0, 1);
        ls0 += __shfl_xor_sync(0xffffffffu, ls0, 2);
        ls1 += __shfl_xor_sync(0xffffffffu, ls1, 1);
        ls1 += __shfl_xor_sync(0xffffffffu, ls1, 2);
        l0 = l0 * corr0 + ls0;
        l1 = l1 * corr1 + ls1;
#pragma unroll
        for (int nt = 0; nt < 4; nt++) {
            o[nt][0] *= corr0; o[nt][1] *= corr0;
            o[nt][2] *= corr1; o[nt][3] *= corr1;
        }

#pragma unroll
        for (int kt = 0; kt < 4; kt++) {
            uint32_t a0 = pack_bf16x2(s[2 * kt][0],     s[2 * kt][1]);
            uint32_t a1 = pack_bf16x2(s[2 * kt][2],     s[2 * kt][3]);
            uint32_t a2 = pack_bf16x2(s[2 * kt + 1][0], s[2 * kt + 1][1]);
            uint32_t a3 = pack_bf16x2(s[2 * kt + 1][2], s[2 * kt + 1][3]);
#pragma unroll
            for (int nt = 0; nt < 4; nt++) {
                uint32_t b0 = *(const uint32_t*)&Vt[buf][nt * 8 + fr][kt * 16 + m2];
                uint32_t b1 = *(const uint32_t*)&Vt[buf][nt * 8 + fr][kt * 16 + m2 + 8];
                mma_bf16(o[nt], a0, a1, a2, a3, b0, b1);
            }
        }

        if (pf) {
            *(uint4*)&Ks[buf ^ 1][lr][lkof] = kv4n;
            const __nv_bfloat16* vb = (const __nv_bfloat16*)&vv4n;
#pragma unroll
            for (int j = 0; j < 8; j++) Vt[buf ^ 1][lkof + j][lr] = vb[j];
        }
        __syncthreads();
    }

    float inv0 = 1.f / l0, inv1 = 1.f / l1;
    int nr0 = n0 + r0, nr1 = nr0 + 8;
#pragma unroll
    for (int nt = 0; nt < 4; nt++) {
        int col = hg * DH + nt * 8 + m2;
        if (nr0 < NTOT)
            *(uint32_t*)&g_x12b[((size_t)b * NTOT + nr0) * CDIM + col] =
                pack_bf16x2(o[nt][0] * inv0, o[nt][1] * inv0);
        if (nr1 < NTOT)
            *(uint32_t*)&g_x12b[((size_t)b * NTOT + nr1) * CDIM + col] =
                pack_bf16x2(o[nt][2] * inv1, o[nt][3] * inv1);
    }
}

// ---------------------------------------------------------------------------
// Final projection + residual, DOUBLE-BUFFERED k-loop, split write.
// ---------------------------------------------------------------------------
__global__ void proj_kernel(const float* __restrict__ projb,
                            const float* __restrict__ resx, const float* __restrict__ resmsg,
                            float* __restrict__ out_img, float* __restrict__ out_msg) {
    __shared__ __nv_bfloat16 Xs[2][64][40];
    __shared__ __nv_bfloat16 Wsm[2][128][40];

    const int tid  = threadIdx.x;
    const int warp = tid >> 5;
    const int lane = tid & 31;
    const int mrow = (warp & 3) * 16;
    const int colBase = (warp >> 2) * 64;
    const int rowBase = blockIdx.x * 64;

    const int lrow = tid >> 2;
    const int koff = (tid & 3) * 8;
    const int gr = rowBase + lrow;
    const bool valid = gr < M_Q;
    const int fr = lane >> 2;
    const int m2 = (lane & 3) * 2;

    float c[8][4];
#pragma unroll
    for (int nt = 0; nt < 8; nt++) { c[nt][0] = c[nt][1] = c[nt][2] = c[nt][3] = 0.f; }

    // preload chunk 0
    {
        uint4 xv = make_uint4(0u, 0u, 0u, 0u);
        if (valid) xv = *(const uint4*)(g_x12b + (size_t)gr * CDIM + koff);
        *(uint4*)&Xs[0][lrow][koff] = xv;
        const __nv_bfloat16* wp = g_projwb + (size_t)(tid >> 1) * CDIM + (tid & 1) * 16;
        *(uint4*)&Wsm[0][tid >> 1][(tid & 1) * 16]     = *(const uint4*)wp;
        *(uint4*)&Wsm[0][tid >> 1][(tid & 1) * 16 + 8] = *(const uint4*)(wp + 8);
    }
    __syncthreads();

#pragma unroll
    for (int ci = 0; ci < 4; ci++) {
        const int buf = ci & 1;
        const bool pf = (ci + 1) < 4;
        uint4 xn = make_uint4(0u, 0u, 0u, 0u), wn0 = xn, wn1 = xn;
        if (pf) {
            int k0 = (ci + 1) * 32;
            if (valid) xn = *(const uint4*)(g_x12b + (size_t)gr * CDIM + k0 + koff);
            const __nv_bfloat16* wp = g_projwb + (size_t)(tid >> 1) * CDIM + k0 + (tid & 1) * 16;
            wn0 = *(const uint4*)wp;
            wn1 = *(const uint4*)(wp + 8);
        }

#pragma unroll
        for (int kt = 0; kt < 2; kt++) {
            uint32_t a0 = *(const uint32_t*)&Xs[buf][mrow + fr][kt * 16 + m2];
            uint32_t a1 = *(const uint32_t*)&Xs[buf][mrow + fr + 8][kt * 16 + m2];
            uint32_t a2 = *(const uint32_t*)&Xs[buf][mrow + fr][kt * 16 + m2 + 8];
            uint32_t a3 = *(const uint32_t*)&Xs[buf][mrow + fr + 8][kt * 16 + m2 + 8];
#pragma unroll
            for (int nt = 0; nt < 8; nt++) {
                uint32_t b0 = *(const uint32_t*)&Wsm[buf][colBase + nt * 8 + fr][kt * 16 + m2];
                uint32_t b1 = *(const uint32_t*)&Wsm[buf][colBase + nt * 8 + fr][kt * 16 + m2 + 8];
                mma_bf16(c[nt], a0, a1, a2, a3, b0, b1);
            }
        }

        if (pf) {
            *(uint4*)&Xs[buf ^ 1][lrow][koff] = xn;
            *(uint4*)&Wsm[buf ^ 1][tid >> 1][(tid & 1) * 16]     = wn0;
            *(uint4*)&Wsm[buf ^ 1][tid >> 1][(tid & 1) * 16 + 8] = wn1;
        }
        __syncthreads();
    }

    const int r0 = rowBase + mrow + fr;
    const int r1 = r0 + 8;
#pragma unroll
    for (int nt = 0; nt < 8; nt++) {
        int col = colBase + nt * 8 + m2;
        float bb0 = projb[col], bb1 = projb[col + 1];
        if (r0 < M_Q) {
            int b = r0 / NTOT, n = r0 - b * NTOT;
            if (n < N0) {
                size_t oo = ((size_t)b * N0 + n) * CDIM + col;
                *(float2*)&out_img[oo] = make_float2(c[nt][0] + bb0 + resx[oo],
                                                     c[nt][1] + bb1 + resx[oo + 1]);
            } else {
                size_t oo = ((size_t)b * NMSG + (n - N0)) * CDIM + col;
                *(float2*)&out_msg[oo] = make_float2(c[nt][0] + bb0 + resmsg[oo],
                                                     c[nt][1] + bb1 + resmsg[oo + 1]);
            }
        }
        if (r1 < M_Q) {
            int b = r1 / NTOT, n = r1 - b * NTOT;
            if (n < N0) {
                size_t oo = ((size_t)b * N0 + n) * CDIM + col;
                *(float2*)&out_img[oo] = make_float2(c[nt][2] + bb0 + resx[oo],
                                                     c[nt][3] + bb1 + resx[oo + 1]);
            } else {
                size_t oo = ((size_t)b * NMSG + (n - N0)) * CDIM + col;
                *(float2*)&out_msg[oo] = make_float2(c[nt][2] + bb0 + resmsg[oo],
                                                     c[nt][3] + bb1 + resmsg[oo + 1]);
            }
        }
    }
}

// ---------------------------------------------------------------------------
extern "C" void kernel_launch(void* const* d_in, const int* in_sizes, int n_in,
                              void* d_out, int out_size) {
    const float* x     = (const float*)d_in[0];
    const float* msg   = (const float*)d_in[1];
    const float* Wq    = (const float*)d_in[2];
    const float* bq    = (const float*)d_in[3];
    const float* sr1w  = (const float*)d_in[4];
    const float* sr1b  = (const float*)d_in[5];
    const float* ln1g  = (const float*)d_in[6];
    const float* ln1b  = (const float*)d_in[7];
    const float* sr2w  = (const float*)d_in[8];
    const float* sr2b  = (const float*)d_in[9];
    const float* ln2g  = (const float*)d_in[10];
    const float* ln2b  = (const float*)d_in[11];
    const float* kv1w  = (const float*)d_in[12];
    const float* kv1b  = (const float*)d_in[13];
    const float* kv2w  = (const float*)d_in[14];
    const float* kv2b  = (const float*)d_in[15];
    const float* lc1w  = (const float*)d_in[16];
    const float* lc1b  = (const float*)d_in[17];
    const float* lc2w  = (const float*)d_in[18];
    const float* lc2b  = (const float*)d_in[19];
    const float* projw = (const float*)d_in[20];
    const float* projb = (const float*)d_in[21];
    (void)in_sizes; (void)n_in; (void)out_size;

    float* out_img = (float*)d_out;
    float* out_msg = out_img + (size_t)BSZ * N0 * CDIM;

    // 1. all conversions / weight prep in one launch
    prep_kernel<<<PS9, 256>>>(x, msg, Wq, kv1w, kv2w, projw, sr1w, sr2w);

    // 2. PATCH1 + PATCH2 + Q GEMMs in one launch (long jobs scheduled first)
    stage1_kernel<<<STAGE1_GRID, 256>>>(bq);

    // 3. partial-sum + SR bias + msg matvec + LN + GELU -> bf16
    lnfuse_kernel<<<M_KV1 + M_KV2, 128>>>(msg, sr1b, sr2b, ln1g, ln1b, ln2g, ln2b);

    // 4. KV projections (both branches, column-split, double-buffered)
    kv_kernel<<<KV_GRID, 256>>>(kv1b, kv2b);

    // 5. V augmentation -> bf16
    vmod_kernel<<<(M_KV1 + M_KV2 + 3) / 4, 256>>>(lc1w, lc1b, lc2w, lc2b);

    // 6. attention (branch-2 heads first, base-2 softmax), writes g_x12b
    {
        dim3 grid((NTOT + 127) / 128, 4, BSZ);
        attn_mma_kernel<<<grid, 256>>>();
    }

    // 7. output projection + residual (double-buffered), split write
    proj_kernel<<<NQ_TILES, 256>>>(projb, x, msg, out_img, out_msg);
}

// round 16
// speedup vs baseline: 1.4141x; 1.0265x over previous
#include <cuda_runtime.h>
#include <cuda_bf16.h>
#include <stdint.h>
#include <math.h>

#define BSZ   8
#define N0    4096
#define NMSG  4
#define NTOT  4100
#define CDIM  128
#define DH    32
// 1/sqrt(32) * log2(e): softmax computed in base-2 domain
#define ATT_SCALE_LOG2 0.255034863f

#define L1   256
#define LT1  260
#define HR1  16
#define WR1  16
#define L2   1024
#define LT2  1028
#define HR2  32
#define WR2  32

#define M_Q   (BSZ * NTOT)   // 32800
#define M_P1  (BSZ * L1)     // 2048
#define M_P2  (BSZ * L2)     // 8192
#define M_KV1 (BSZ * LT1)    // 2080
#define M_KV2 (BSZ * LT2)    // 8224

// stage1 grid layout: LONG jobs (PATCH, K=512) first, short Q tiles last.
#define NQ_TILES  ((M_Q + 63) / 64)            // 513
#define P1_TILES  (M_P1 / 64)                  // 32
#define KSPLIT1   4
#define P1_BLKS   (P1_TILES * KSPLIT1)         // 128
#define P2_TILES  (M_P2 / 64)                  // 128
#define STAGE1_GRID (NQ_TILES + P1_BLKS + P2_TILES)

// kv grid (column-split x2 for occupancy)
#define KV1_TILES ((M_KV1 + 63) / 64)          // 33
#define KV2_TILES ((M_KV2 + 63) / 64)          // 129
#define KV_GRID   ((KV1_TILES + KV2_TILES) * 2)

// ---------------- scratch (static device globals; no allocs) ----------------
__device__ float g_p1[KSPLIT1 * M_P1 * CDIM];  // PATCH1 K-split partials (no bias)
__device__ float g_p2[M_P2 * CDIM];            // PATCH2 output (no bias)
__device__ float g_v1f[M_KV1 * 64];            // V fp32 (pre-dwconv)
__device__ float g_v2f[M_KV2 * 64];
__device__ float g_ws1[CDIM * CDIM];           // transposed summed SR weights [c][o]
__device__ float g_ws2[CDIM * CDIM];

__device__ __nv_bfloat16 g_xb[BSZ * N0 * CDIM];
__device__ __nv_bfloat16 g_msgb[BSZ * NMSG * CDIM];
__device__ __nv_bfloat16 g_qb[M_Q * CDIM];     // Q (pre-scaled, log2-domain)
__device__ __nv_bfloat16 g_xk1b[M_KV1 * CDIM]; // post LN+GELU
__device__ __nv_bfloat16 g_xk2b[M_KV2 * CDIM];
__device__ __nv_bfloat16 g_k1b[M_KV1 * 64];    // K bf16
__device__ __nv_bfloat16 g_k2b[M_KV2 * 64];
__device__ __nv_bfloat16 g_v1mb[M_KV1 * 64];   // V + dwconv, bf16
__device__ __nv_bfloat16 g_v2mb[M_KV2 * 64];
__device__ __nv_bfloat16 g_x12b[M_Q * CDIM];   // attention outputs

__device__ __nv_bfloat16 g_wqb[CDIM * CDIM];
__device__ __nv_bfloat16 g_sr1wb[CDIM * CDIM * 16]; // [o][pos*128+c]
__device__ __nv_bfloat16 g_sr2wb[CDIM * CDIM * 4];
__device__ __nv_bfloat16 g_kv1wb[CDIM * CDIM];
__device__ __nv_bfloat16 g_kv2wb[CDIM * CDIM];
__device__ __nv_bfloat16 g_projwb[CDIM * CDIM];

// ---------------------------------------------------------------------------
__device__ __forceinline__ void mma_bf16(float c[4],
                                         uint32_t a0, uint32_t a1, uint32_t a2, uint32_t a3,
                                         uint32_t b0, uint32_t b1) {
    asm volatile(
        "mma.sync.aligned.m16n8k16.row.col.f32.bf16.bf16.f32 "
        "{%0,%1,%2,%3}, {%4,%5,%6,%7}, {%8,%9}, {%0,%1,%2,%3};"
        : "+f"(c[0]), "+f"(c[1]), "+f"(c[2]), "+f"(c[3])
        : "r"(a0), "r"(a1), "r"(a2), "r"(a3), "r"(b0), "r"(b1));
}

__device__ __forceinline__ uint32_t pack_bf16x2(float lo, float hi) {
    __nv_bfloat162 h = __floats2bfloat162_rn(lo, hi);
    return *reinterpret_cast<uint32_t*>(&h);
}

// single MUFU.EX2 (guaranteed fast path regardless of -use_fast_math)
__device__ __forceinline__ float ex2(float x) {
    float y;
    asm("ex2.approx.ftz.f32 %0, %1;" : "=f"(y) : "f"(x));
    return y;
}

// ---------------------------------------------------------------------------
// prep: all fp32->bf16 conversions, SR weight reorder, summed-SR weights.
// ---------------------------------------------------------------------------
#define PS0 4096                  // xb (float4 per thread, packed uint2 store)
#define PS1 (PS0 + 16)            // msgb
#define PS2 (PS1 + 64)            // wqb
#define PS3 (PS2 + 64)            // kv1wb
#define PS4 (PS3 + 64)            // kv2wb
#define PS5 (PS4 + 64)            // projwb
#define PS6 (PS5 + 1024)          // wreorder sr1
#define PS7 (PS6 + 256)           // wreorder sr2
#define PS8 (PS7 + 64)            // wsum1
#define PS9 (PS8 + 64)            // wsum2   -> grid = PS9

__global__ void prep_kernel(const float* __restrict__ x,   const float* __restrict__ msg,
                            const float* __restrict__ Wq,  const float* __restrict__ kv1w,
                            const float* __restrict__ kv2w, const float* __restrict__ projw,
                            const float* __restrict__ sr1w, const float* __restrict__ sr2w) {
    int bid = blockIdx.x, t = threadIdx.x;
    if (bid < PS0) {
        int i = (bid * 256 + t) * 4;
        float4 v = *(const float4*)(x + i);
        uint2 pk;
        pk.x = pack_bf16x2(v.x, v.y);
        pk.y = pack_bf16x2(v.z, v.w);
        *(uint2*)(g_xb + i) = pk;
    } else if (bid < PS1) {
        int i = (bid - PS0) * 256 + t;
        g_msgb[i] = __float2bfloat16(msg[i]);
    } else if (bid < PS2) {
        int i = (bid - PS1) * 256 + t;  g_wqb[i]   = __float2bfloat16(Wq[i]);
    } else if (bid < PS3) {
        int i = (bid - PS2) * 256 + t;  g_kv1wb[i] = __float2bfloat16(kv1w[i]);
    } else if (bid < PS4) {
        int i = (bid - PS3) * 256 + t;  g_kv2wb[i] = __float2bfloat16(kv2w[i]);
    } else if (bid < PS5) {
        int i = (bid - PS4) * 256 + t;  g_projwb[i] = __float2bfloat16(projw[i]);
    } else if (bid < PS6) {
        int idx = (bid - PS5) * 256 + t;          // [o][c][pos] src
        int o = idx >> 11;                         // / (128*16)
        int rem = idx & 2047;
        int cch = rem >> 4, pos = rem & 15;
        g_sr1wb[(size_t)o * 2048 + pos * CDIM + cch] = __float2bfloat16(sr1w[idx]);
    } else if (bid < PS7) {
        int idx = (bid - PS6) * 256 + t;
        int o = idx >> 9;                          // / (128*4)
        int rem = idx & 511;
        int cch = rem >> 2, pos = rem & 3;
        g_sr2wb[(size_t)o * 512 + pos * CDIM + cch] = __float2bfloat16(sr2w[idx]);
    } else if (bid < PS8) {
        int idx = (bid - PS7) * 256 + t;
        int c = idx >> 7, o = idx & 127;
        const float* p = sr1w + (o * CDIM + c) * 16;
        float s = 0.f;
#pragma unroll
        for (int i = 0; i < 16; i++) s += p[i];
        g_ws1[c * CDIM + o] = s;
    } else {
        int idx = (bid - PS8) * 256 + t;
        int c = idx >> 7, o = idx & 127;
        const float* p = sr2w + (o * CDIM + c) * 4;
        float s = 0.f;
#pragma unroll
        for (int i = 0; i < 4; i++) s += p[i];
        g_ws2[c * CDIM + o] = s;
    }
}

// ---------------------------------------------------------------------------
// stage1: Q projection + both SR patch-embed GEMMs in ONE launch.
// PATCH first (long), Q last (short). Double-buffered k-loop.
// ---------------------------------------------------------------------------
__global__ void stage1_kernel(const float* __restrict__ bq) {
    __shared__ __nv_bfloat16 Xs[2][64][40];
    __shared__ __nv_bfloat16 Wsm[2][128][40];

    const int tid  = threadIdx.x;
    const int warp = tid >> 5;
    const int lane = tid & 31;
    const int mrow = (warp & 3) * 16;
    const int colBase = (warp >> 2) * 64;
    const int bid = blockIdx.x;

    int mode, S = 4, rowBase, K, kbase = 0, KTOT, M, Lloc = L1;
    const __nv_bfloat16* Wb;
    float* outP = nullptr;
    if (bid < P1_BLKS) {                       // PATCH1 first (longest)
        int q = bid;
        mode = 1; S = 4; Lloc = L1;
        rowBase = (q >> 2) * 64;
        int kseg = q & 3;
        K = 512; kbase = kseg * 512; KTOT = 2048; M = M_P1;
        Wb = g_sr1wb; outP = g_p1 + (size_t)kseg * M_P1 * CDIM;
    } else if (bid < P1_BLKS + P2_TILES) {     // PATCH2 next
        int q = bid - P1_BLKS;
        mode = 1; S = 2; Lloc = L2;
        rowBase = q * 64;
        K = 512; kbase = 0; KTOT = 512; M = M_P2;
        Wb = g_sr2wb; outP = g_p2;
    } else {                                   // Q tiles last (short, K=128)
        int q = bid - P1_BLKS - P2_TILES;
        mode = 0; rowBase = q * 64; K = 128; KTOT = 128; M = M_Q; Wb = g_wqb;
    }

    const int lrow = tid >> 2;
    const int koff = (tid & 3) * 8;
    const int gr = rowBase + lrow;
    const bool valid = gr < M;

    const __nv_bfloat16* srcRow = nullptr;
    int pb = 0, phr = 0, pwr = 0;
    if (mode == 0) {
        if (valid) {
            int b = gr / NTOT, n = gr - b * NTOT;
            srcRow = (n < N0) ? g_xb + ((size_t)b * N0 + n) * CDIM
                              : g_msgb + ((size_t)b * NMSG + (n - N0)) * CDIM;
        }
    } else {
        if (valid) {
            pb = gr / Lloc; int l = gr - pb * Lloc;
            int Wr = (S == 4) ? WR1 : WR2;
            phr = l / Wr; pwr = l - phr * Wr;
        }
    }

    const int fr = lane >> 2;
    const int m2 = (lane & 3) * 2;

    float c[8][4];
#pragma unroll
    for (int nt = 0; nt < 8; nt++) { c[nt][0] = c[nt][1] = c[nt][2] = c[nt][3] = 0.f; }

    const int nch = K >> 5;

    auto loadX = [&](int k0, uint4& xv) {
        xv = make_uint4(0u, 0u, 0u, 0u);
        if (valid) {
            if (mode == 1) {
                int gk = kbase + k0;
                int pos = gk >> 7;
                int ky = (S == 4) ? (pos >> 2) : (pos >> 1);
                int kx = (S == 4) ? (pos & 3)  : (pos & 1);
                int p = (phr * S + ky) * 64 + pwr * S + kx;
                xv = *(const uint4*)(g_xb + ((size_t)pb * N0 + p) * CDIM + (gk & 127) + koff);
            } else {
                xv = *(const uint4*)(srcRow + k0 + koff);
            }
        }
    };
    auto loadW = [&](int k0, uint4& w0, uint4& w1) {
        const __nv_bfloat16* wp = Wb + (size_t)(tid >> 1) * KTOT + kbase + k0 + (tid & 1) * 16;
        w0 = *(const uint4*)wp;
        w1 = *(const uint4*)(wp + 8);
    };

    {
        uint4 xv, w0, w1;
        loadX(0, xv); loadW(0, w0, w1);
        *(uint4*)&Xs[0][lrow][koff] = xv;
        *(uint4*)&Wsm[0][tid >> 1][(tid & 1) * 16]     = w0;
        *(uint4*)&Wsm[0][tid >> 1][(tid & 1) * 16 + 8] = w1;
    }
    __syncthreads();

    for (int ci = 0; ci < nch; ci++) {
        const int buf = ci & 1;
        const bool pf = (ci + 1) < nch;
        uint4 xn, wn0, wn1;
        if (pf) { loadX((ci + 1) * 32, xn); loadW((ci + 1) * 32, wn0, wn1); }

#pragma unroll
        for (int kt = 0; kt < 2; kt++) {
            uint32_t a0 = *(const uint32_t*)&Xs[buf][mrow + fr][kt * 16 + m2];
            uint32_t a1 = *(const uint32_t*)&Xs[buf][mrow + fr + 8][kt * 16 + m2];
            uint32_t a2 = *(const uint32_t*)&Xs[buf][mrow + fr][kt * 16 + m2 + 8];
            uint32_t a3 = *(const uint32_t*)&Xs[buf][mrow + fr + 8][kt * 16 + m2 + 8];
#pragma unroll
            for (int nt = 0; nt < 8; nt++) {
                uint32_t b0 = *(const uint32_t*)&Wsm[buf][colBase + nt * 8 + fr][kt * 16 + m2];
                uint32_t b1 = *(const uint32_t*)&Wsm[buf][colBase + nt * 8 + fr][kt * 16 + m2 + 8];
                mma_bf16(c[nt], a0, a1, a2, a3, b0, b1);
            }
        }

        if (pf) {
            *(uint4*)&Xs[buf ^ 1][lrow][koff] = xn;
            *(uint4*)&Wsm[buf ^ 1][tid >> 1][(tid & 1) * 16]     = wn0;
            *(uint4*)&Wsm[buf ^ 1][tid >> 1][(tid & 1) * 16 + 8] = wn1;
        }
        __syncthreads();
    }

    const int r0 = rowBase + mrow + fr;
    const int r1 = r0 + 8;
#pragma unroll
    for (int nt = 0; nt < 8; nt++) {
        int col = colBase + nt * 8 + m2;
        if (mode == 0) {
            float bb0 = bq[col], bb1 = bq[col + 1];
            if (r0 < M) *(uint32_t*)&g_qb[(size_t)r0 * CDIM + col] =
                pack_bf16x2((c[nt][0] + bb0) * ATT_SCALE_LOG2, (c[nt][1] + bb1) * ATT_SCALE_LOG2);
            if (r1 < M) *(uint32_t*)&g_qb[(size_t)r1 * CDIM + col] =
                pack_bf16x2((c[nt][2] + bb0) * ATT_SCALE_LOG2, (c[nt][3] + bb1) * ATT_SCALE_LOG2);
        } else {
            if (r0 < M) *(float2*)&outP[(size_t)r0 * CDIM + col] = make_float2(c[nt][0], c[nt][1]);
            if (r1 < M) *(float2*)&outP[(size_t)r1 * CDIM + col] = make_float2(c[nt][2], c[nt][3]);
        }
    }
}

// ---------------------------------------------------------------------------
// LN+GELU fused: sums PATCH partials (+SR bias), msg-token SR matvec, LN+GELU.
// ---------------------------------------------------------------------------
__global__ void lnfuse_kernel(const float* __restrict__ msg,
                              const float* __restrict__ sr1b, const float* __restrict__ sr2b,
                              const float* __restrict__ ln1g, const float* __restrict__ ln1b,
                              const float* __restrict__ ln2g, const float* __restrict__ ln2b) {
    __shared__ float sm1[4], sm2[4];
    __shared__ float mrow[CDIM];
    int bid = blockIdx.x;
    int t = threadIdx.x, w = t >> 5, lane = t & 31;

    int br, b, l;
    if (bid < M_KV1) { br = 0; b = bid / LT1; l = bid - b * LT1; }
    else { int r2 = bid - M_KV1; br = 1; b = r2 / LT2; l = r2 - b * LT2; }

    const int Lloc = br ? L2 : L1;
    float v;
    if (l < Lloc) {
        if (br == 0) {
            size_t o = ((size_t)b * L1 + l) * CDIM + t;
            v = g_p1[o] + g_p1[(size_t)M_P1 * CDIM + o] + g_p1[(size_t)2 * M_P1 * CDIM + o]
              + g_p1[(size_t)3 * M_P1 * CDIM + o] + sr1b[t];
        } else {
            v = g_p2[((size_t)b * L2 + l) * CDIM + t] + sr2b[t];
        }
    } else {
        int n = l - Lloc;
        mrow[t] = msg[((size_t)b * NMSG + n) * CDIM + t];
        __syncthreads();
        const float* wsT = br ? g_ws2 : g_ws1;
        float a0 = 0.f, a1 = 0.f, a2 = 0.f, a3 = 0.f;
#pragma unroll 8
        for (int cc = 0; cc < CDIM; cc += 4) {
            a0 += mrow[cc + 0] * wsT[(cc + 0) * CDIM + t];
            a1 += mrow[cc + 1] * wsT[(cc + 1) * CDIM + t];
            a2 += mrow[cc + 2] * wsT[(cc + 2) * CDIM + t];
            a3 += mrow[cc + 3] * wsT[(cc + 3) * CDIM + t];
        }
        v = (a0 + a1) + (a2 + a3) + (br ? sr2b[t] : sr1b[t]);
    }
    __syncthreads();

    float s1 = v, s2 = v * v;
#pragma unroll
    for (int off = 16; off > 0; off >>= 1) {
        s1 += __shfl_xor_sync(0xffffffffu, s1, off);
        s2 += __shfl_xor_sync(0xffffffffu, s2, off);
    }
    if (lane == 0) { sm1[w] = s1; sm2[w] = s2; }
    __syncthreads();
    s1 = (sm1[0] + sm1[1]) + (sm1[2] + sm1[3]);
    s2 = (sm2[0] + sm2[1]) + (sm2[2] + sm2[3]);
    float mu  = s1 * (1.f / 128.f);
    float var = fmaxf(s2 * (1.f / 128.f) - mu * mu, 0.f);
    const float* g  = br ? ln2g : ln1g;
    const float* be = br ? ln2b : ln1b;
    float y = (v - mu) * rsqrtf(var + 1e-5f) * g[t] + be[t];
    float gel = 0.5f * y * (1.f + erff(y * 0.70710678118654752f));
    __nv_bfloat16* ob = br ? g_xk2b : g_xk1b;
    size_t row = br ? ((size_t)b * LT2 + l) : ((size_t)b * LT1 + l);
    ob[row * CDIM + t] = __float2bfloat16(gel);
}

// ---------------------------------------------------------------------------
// KV projections, both branches, COLUMN-SPLIT x2, DOUBLE-BUFFERED k-loop.
// ---------------------------------------------------------------------------
__global__ void kv_kernel(const float* __restrict__ kv1b_, const float* __restrict__ kv2b_) {
    __shared__ __nv_bfloat16 Xs[2][64][40];
    __shared__ __nv_bfloat16 Wsm[2][64][40];

    const int tid  = threadIdx.x;
    const int warp = tid >> 5;
    const int lane = tid & 31;
    const int mrow = (warp & 3) * 16;
    const int colBase = (warp >> 2) * 32;   // 0 or 32 within the half
    const int colHalf = (blockIdx.x & 1) * 64;
    const int bid = blockIdx.x >> 1;

    int rowBase, M;
    const __nv_bfloat16 *Ab, *Wb;
    const float* bias;
    __nv_bfloat16* kb;
    float* vf;
    if (bid < KV1_TILES) {
        rowBase = bid * 64; M = M_KV1;
        Ab = g_xk1b; Wb = g_kv1wb; bias = kv1b_; kb = g_k1b; vf = g_v1f;
    } else {
        rowBase = (bid - KV1_TILES) * 64; M = M_KV2;
        Ab = g_xk2b; Wb = g_kv2wb; bias = kv2b_; kb = g_k2b; vf = g_v2f;
    }

    const int lrow = tid >> 2;
    const int koff = (tid & 3) * 8;
    const int gr = rowBase + lrow;
    const bool valid = gr < M;
    const int fr = lane >> 2;
    const int m2 = (lane & 3) * 2;

    float c[4][4];
#pragma unroll
    for (int nt = 0; nt < 4; nt++) { c[nt][0] = c[nt][1] = c[nt][2] = c[nt][3] = 0.f; }

    {
        uint4 xv = make_uint4(0u, 0u, 0u, 0u);
        if (valid) xv = *(const uint4*)(Ab + (size_t)gr * CDIM + koff);
        *(uint4*)&Xs[0][lrow][koff] = xv;
        *(uint4*)&Wsm[0][lrow][koff] =
            *(const uint4*)(Wb + (size_t)(colHalf + lrow) * CDIM + koff);
    }
    __syncthreads();

#pragma unroll
    for (int ci = 0; ci < 4; ci++) {
        const int buf = ci & 1;
        const bool pf = (ci + 1) < 4;
        uint4 xn = make_uint4(0u, 0u, 0u, 0u), wn = make_uint4(0u, 0u, 0u, 0u);
        if (pf) {
            int k0 = (ci + 1) * 32;
            if (valid) xn = *(const uint4*)(Ab + (size_t)gr * CDIM + k0 + koff);
            wn = *(const uint4*)(Wb + (size_t)(colHalf + lrow) * CDIM + k0 + koff);
        }

#pragma unroll
        for (int kt = 0; kt < 2; kt++) {
            uint32_t a0 = *(const uint32_t*)&Xs[buf][mrow + fr][kt * 16 + m2];
            uint32_t a1 = *(const uint32_t*)&Xs[buf][mrow + fr + 8][kt * 16 + m2];
            uint32_t a2 = *(const uint32_t*)&Xs[buf][mrow + fr][kt * 16 + m2 + 8];
            uint32_t a3 = *(const uint32_t*)&Xs[buf][mrow + fr + 8][kt * 16 + m2 + 8];
#pragma unroll
            for (int nt = 0; nt < 4; nt++) {
                uint32_t b0 = *(const uint32_t*)&Wsm[buf][colBase + nt * 8 + fr][kt * 16 + m2];
                uint32_t b1 = *(const uint32_t*)&Wsm[buf][colBase + nt * 8 + fr][kt * 16 + m2 + 8];
                mma_bf16(c[nt], a0, a1, a2, a3, b0, b1);
            }
        }

        if (pf) {
            *(uint4*)&Xs[buf ^ 1][lrow][koff] = xn;
            *(uint4*)&Wsm[buf ^ 1][lrow][koff] = wn;
        }
        __syncthreads();
    }

    const int r0 = rowBase + mrow + fr;
    const int r1 = r0 + 8;
#pragma unroll
    for (int nt = 0; nt < 4; nt++) {
        int col = colHalf + colBase + nt * 8 + m2;
        float bb0 = bias[col], bb1 = bias[col + 1];
        float v00 = c[nt][0] + bb0, v01 = c[nt][1] + bb1;
        float v10 = c[nt][2] + bb0, v11 = c[nt][3] + bb1;
        if (col < 64) {  // K -> bf16
            if (r0 < M) *(uint32_t*)&kb[(size_t)r0 * 64 + col] = pack_bf16x2(v00, v01);
            if (r1 < M) *(uint32_t*)&kb[(size_t)r1 * 64 + col] = pack_bf16x2(v10, v11);
        } else {         // V -> fp32
            int vc = col - 64;
            if (r0 < M) *(float2*)&vf[(size_t)r0 * 64 + vc] = make_float2(v00, v01);
            if (r1 < M) *(float2*)&vf[(size_t)r1 * 64 + vc] = make_float2(v10, v11);
        }
    }
}

// ---------------------------------------------------------------------------
// v_mod both branches. bf16 out.
// ---------------------------------------------------------------------------
__global__ void vmod_kernel(const float* __restrict__ lw1, const float* __restrict__ lb1,
                            const float* __restrict__ lw2, const float* __restrict__ lb2) {
    int tid = threadIdx.x;
    int ch = tid & 63;
    int row = blockIdx.x * 4 + (tid >> 6);
    if (row >= M_KV1 + M_KV2) return;

    int b, l, Hr, Wr, Lloc, Lt;
    const float *vf, *lw, *lb;
    __nv_bfloat16* vm;
    if (row < M_KV1) {
        b = row / LT1; l = row - b * LT1;
        Hr = HR1; Wr = WR1; Lloc = L1; Lt = LT1;
        vf = g_v1f; lw = lw1; lb = lb1; vm = g_v1mb;
    } else {
        int r2 = row - M_KV1;
        b = r2 / LT2; l = r2 - b * LT2;
        Hr = HR2; Wr = WR2; Lloc = L2; Lt = LT2;
        vf = g_v2f; lw = lw2; lb = lb2; vm = g_v2mb;
    }
    float self = vf[((size_t)b * Lt + l) * 64 + ch];
    float o;
    if (l < Lloc) {
        int hr = l / Wr, wr = l - hr * Wr;
        float acc = lb[ch];
#pragma unroll
        for (int dy = 0; dy < 3; dy++) {
#pragma unroll
            for (int dx = 0; dx < 3; dx++) {
                int yy = hr + dy - 1, xx = wr + dx - 1;
                if (yy >= 0 && yy < Hr && xx >= 0 && xx < Wr)
                    acc += lw[ch * 9 + dy * 3 + dx] *
                           vf[((size_t)b * Lt + yy * Wr + xx) * 64 + ch];
            }
        }
        o = self + acc;
    } else {
        o = 2.f * self;
    }
    vm[((size_t)b * Lt + l) * 64 + ch] = __float2bfloat16(o);
}

// ---------------------------------------------------------------------------
// bf16 flash attention: 128-q tiles, 8 warps, double-buffered K/V, base-2
// softmax via inline ex2.approx (single MUFU.EX2 per exponential).
// hg = blockIdx.y ^ 2: long branch scheduled first.
// ---------------------------------------------------------------------------
#define VTS 66
__global__ void attn_mma_kernel() {
    __shared__ __nv_bfloat16 Qs[128][40];
    __shared__ __nv_bfloat16 Ks[2][64][40];
    __shared__ __nv_bfloat16 Vt[2][32][VTS];   // V transposed [d][key]

    const int tid  = threadIdx.x;
    const int warp = tid >> 5;
    const int lane = tid & 31;
    const int qt = blockIdx.x, b = blockIdx.z;
    const int hg = blockIdx.y ^ 2;
    const int br = hg >> 1, hh = hg & 1;
    const __nv_bfloat16* kb = br ? g_k2b : g_k1b;
    const __nv_bfloat16* vm = br ? g_v2mb : g_v1mb;
    const int Lt = br ? LT2 : LT1;
    const int n0 = qt * 128;

    const int lr   = tid >> 2;
    const int lkof = (tid & 3) * 8;

    // Q tile: 128 rows x 32 d
#pragma unroll
    for (int pass = 0; pass < 2; pass++) {
        int r = lr + pass * 64;
        int n = n0 + r;
        uint4 v = make_uint4(0u, 0u, 0u, 0u);
        if (n < NTOT)
            v = *(const uint4*)(g_qb + ((size_t)b * NTOT + n) * CDIM + hg * DH + lkof);
        *(uint4*)&Qs[r][lkof] = v;
    }

    // preload chunk 0 into buffer 0
    {
        uint4 kv4 = make_uint4(0u, 0u, 0u, 0u);
        uint4 vv4 = make_uint4(0u, 0u, 0u, 0u);
        if (lr < Lt) {
            size_t base = ((size_t)b * Lt + lr) * 64 + hh * DH + lkof;
            kv4 = *(const uint4*)(kb + base);
            vv4 = *(const uint4*)(vm + base);
        }
        *(uint4*)&Ks[0][lr][lkof] = kv4;
        const __nv_bfloat16* vb = (const __nv_bfloat16*)&vv4;
#pragma unroll
        for (int j = 0; j < 8; j++) Vt[0][lkof + j][lr] = vb[j];
    }
    __syncthreads();

    const int fr = lane >> 2;
    const int m2 = (lane & 3) * 2;
    const int r0 = warp * 16 + fr;

    uint32_t qa[2][4];
#pragma unroll
    for (int kt = 0; kt < 2; kt++) {
        qa[kt][0] = *(const uint32_t*)&Qs[r0][kt * 16 + m2];
        qa[kt][1] = *(const uint32_t*)&Qs[r0 + 8][kt * 16 + m2];
        qa[kt][2] = *(const uint32_t*)&Qs[r0][kt * 16 + m2 + 8];
        qa[kt][3] = *(const uint32_t*)&Qs[r0 + 8][kt * 16 + m2 + 8];
    }

    float o[4][4];
#pragma unroll
    for (int i = 0; i < 4; i++)
#pragma unroll
        for (int j = 0; j < 4; j++) o[i][j] = 0.f;
    float m0 = -1e30f, m1 = -1e30f, l0 = 0.f, l1 = 0.f;

    const int nc = (Lt + 63) >> 6;
    for (int ci = 0; ci < nc; ci++) {
        const int c0 = ci << 6;
        const int buf = ci & 1;
        const bool pf = (ci + 1) < nc;

        uint4 kv4n = make_uint4(0u, 0u, 0u, 0u);
        uint4 vv4n = make_uint4(0u, 0u, 0u, 0u);
        if (pf) {
            int gl = c0 + 64 + lr;
            if (gl < Lt) {
                size_t base = ((size_t)b * Lt + gl) * 64 + hh * DH + lkof;
                kv4n = *(const uint4*)(kb + base);
                vv4n = *(const uint4*)(vm + base);
            }
        }

        float s[8][4];
#pragma unroll
        for (int nt = 0; nt < 8; nt++) { s[nt][0] = s[nt][1] = s[nt][2] = s[nt][3] = 0.f; }
#pragma unroll
        for (int nt = 0; nt < 8; nt++) {
#pragma unroll
            for (int kt = 0; kt < 2; kt++) {
                uint32_t b0 = *(const uint32_t*)&Ks[buf][nt * 8 + fr][kt * 16 + m2];
                uint32_t b1 = *(const uint32_t*)&Ks[buf][nt * 8 + fr][kt * 16 + m2 + 8];
                mma_bf16(s[nt], qa[kt][0], qa[kt][1], qa[kt][2], qa[kt][3], b0, b1);
            }
        }

        float mx0 = m0, mx1 = m1;
#pragma unroll
        for (int nt = 0; nt < 8; nt++) {
            int gc = c0 + nt * 8 + m2;
            if (gc >= Lt)     { s[nt][0] = -1e30f; s[nt][2] = -1e30f; }
            if (gc + 1 >= Lt) { s[nt][1] = -1e30f; s[nt][3] = -1e30f; }
            mx0 = fmaxf(mx0, fmaxf(s[nt][0], s[nt][1]));
            mx1 = fmaxf(mx1, fmaxf(s[nt][2], s[nt][3]));
        }
        mx0 = fmaxf(mx0, __shfl_xor_sync(0xffffffffu, mx0, 1));
        mx0 = fmaxf(mx0, __shfl_xor_sync(0xffffffffu, mx0, 2));
        mx1 = fmaxf(mx1, __shfl_xor_sync(0xffffffffu, mx1, 1));
        mx1 = fmaxf(mx1, __shfl_xor_sync(0xffffffffu, mx1, 2));
        float corr0 = ex2(m0 - mx0), corr1 = ex2(m1 - mx1);
        m0 = mx0; m1 = mx1;

        float ls0 = 0.f, ls1 = 0.f;
#pragma unroll
        for (int nt = 0; nt < 8; nt++) {
            s[nt][0] = ex2(s[nt][0] - m0);
            s[nt][1] = ex2(s[nt][1] - m0);
            s[nt][2] = ex2(s[nt][2] - m1);
            s[nt][3] = ex2(s[nt][3] - m1);
            ls0 += s[nt][0] + s[nt][1];
            ls1 += s[nt][2] + s[nt][3];
        }
        ls0 += __shfl_xor_sync(0xffffffffu, ls0, 1);
        ls0 += __shfl_xor_sync(0xffffffffu, ls0, 2);
        ls1 += __shfl_xor_sync(0xffffffffu, ls1, 1);
        ls1 += __shfl_xor_sync(0xffffffffu, ls1, 2);
        l0 = l0 * corr0 + ls0;
        l1 = l1 * corr1 + ls1;
#pragma unroll
        for (int nt = 0; nt < 4; nt++) {
            o[nt][0] *= corr0; o[nt][1] *= corr0;
            o[nt][2] *= corr1; o[nt][3] *= corr1;
        }

#pragma unroll
        for (int kt = 0; kt < 4; kt++) {
            uint32_t a0 = pack_bf16x2(s[2 * kt][0],     s[2 * kt][1]);
            uint32_t a1 = pack_bf16x2(s[2 * kt][2],     s[2 * kt][3]);
            uint32_t a2 = pack_bf16x2(s[2 * kt + 1][0], s[2 * kt + 1][1]);
            uint32_t a3 = pack_bf16x2(s[2 * kt + 1][2], s[2 * kt + 1][3]);
#pragma unroll
            for (int nt = 0; nt < 4; nt++) {
                uint32_t b0 = *(const uint32_t*)&Vt[buf][nt * 8 + fr][kt * 16 + m2];
                uint32_t b1 = *(const uint32_t*)&Vt[buf][nt * 8 + fr][kt * 16 + m2 + 8];
                mma_bf16(o[nt], a0, a1, a2, a3, b0, b1);
            }
        }

        if (pf) {
            *(uint4*)&Ks[buf ^ 1][lr][lkof] = kv4n;
            const __nv_bfloat16* vb = (const __nv_bfloat16*)&vv4n;
#pragma unroll
            for (int j = 0; j < 8; j++) Vt[buf ^ 1][lkof + j][lr] = vb[j];
        }
        __syncthreads();
    }

    float inv0 = 1.f / l0, inv1 = 1.f / l1;
    int nr0 = n0 + r0, nr1 = nr0 + 8;
#pragma unroll
    for (int nt = 0; nt < 4; nt++) {
        int col = hg * DH + nt * 8 + m2;
        if (nr0 < NTOT)
            *(uint32_t*)&g_x12b[((size_t)b * NTOT + nr0) * CDIM + col] =
                pack_bf16x2(o[nt][0] * inv0, o[nt][1] * inv0);
        if (nr1 < NTOT)
            *(uint32_t*)&g_x12b[((size_t)b * NTOT + nr1) * CDIM + col] =
                pack_bf16x2(o[nt][2] * inv1, o[nt][3] * inv1);
    }
}

// ---------------------------------------------------------------------------
// Final projection + residual, DOUBLE-BUFFERED k-loop, split write.
// ---------------------------------------------------------------------------
__global__ void proj_kernel(const float* __restrict__ projb,
                            const float* __restrict__ resx, const float* __restrict__ resmsg,
                            float* __restrict__ out_img, float* __restrict__ out_msg) {
    __shared__ __nv_bfloat16 Xs[2][64][40];
    __shared__ __nv_bfloat16 Wsm[2][128][40];

    const int tid  = threadIdx.x;
    const int warp = tid >> 5;
    const int lane = tid & 31;
    const int mrow = (warp & 3) * 16;
    const int colBase = (warp >> 2) * 64;
    const int rowBase = blockIdx.x * 64;

    const int lrow = tid >> 2;
    const int koff = (tid & 3) * 8;
    const int gr = rowBase + lrow;
    const bool valid = gr < M_Q;
    const int fr = lane >> 2;
    const int m2 = (lane & 3) * 2;

    float c[8][4];
#pragma unroll
    for (int nt = 0; nt < 8; nt++) { c[nt][0] = c[nt][1] = c[nt][2] = c[nt][3] = 0.f; }

    {
        uint4 xv = make_uint4(0u, 0u, 0u, 0u);
        if (valid) xv = *(const uint4*)(g_x12b + (size_t)gr * CDIM + koff);
        *(uint4*)&Xs[0][lrow][koff] = xv;
        const __nv_bfloat16* wp = g_projwb + (size_t)(tid >> 1) * CDIM + (tid & 1) * 16;
        *(uint4*)&Wsm[0][tid >> 1][(tid & 1) * 16]     = *(const uint4*)wp;
        *(uint4*)&Wsm[0][tid >> 1][(tid & 1) * 16 + 8] = *(const uint4*)(wp + 8);
    }
    __syncthreads();

#pragma unroll
    for (int ci = 0; ci < 4; ci++) {
        const int buf = ci & 1;
        const bool pf = (ci + 1) < 4;
        uint4 xn = make_uint4(0u, 0u, 0u, 0u), wn0 = xn, wn1 = xn;
        if (pf) {
            int k0 = (ci + 1) * 32;
            if (valid) xn = *(const uint4*)(g_x12b + (size_t)gr * CDIM + k0 + koff);
            const __nv_bfloat16* wp = g_projwb + (size_t)(tid >> 1) * CDIM + k0 + (tid & 1) * 16;
            wn0 = *(const uint4*)wp;
            wn1 = *(const uint4*)(wp + 8);
        }

#pragma unroll
        for (int kt = 0; kt < 2; kt++) {
            uint32_t a0 = *(const uint32_t*)&Xs[buf][mrow + fr][kt * 16 + m2];
            uint32_t a1 = *(const uint32_t*)&Xs[buf][mrow + fr + 8][kt * 16 + m2];
            uint32_t a2 = *(const uint32_t*)&Xs[buf][mrow + fr][kt * 16 + m2 + 8];
            uint32_t a3 = *(const uint32_t*)&Xs[buf][mrow + fr + 8][kt * 16 + m2 + 8];
#pragma unroll
            for (int nt = 0; nt < 8; nt++) {
                uint32_t b0 = *(const uint32_t*)&Wsm[buf][colBase + nt * 8 + fr][kt * 16 + m2];
                uint32_t b1 = *(const uint32_t*)&Wsm[buf][colBase + nt * 8 + fr][kt * 16 + m2 + 8];
                mma_bf16(c[nt], a0, a1, a2, a3, b0, b1);
            }
        }

        if (pf) {
            *(uint4*)&Xs[buf ^ 1][lrow][koff] = xn;
            *(uint4*)&Wsm[buf ^ 1][tid >> 1][(tid & 1) * 16]     = wn0;
            *(uint4*)&Wsm[buf ^ 1][tid >> 1][(tid & 1) * 16 + 8] = wn1;
        }
        __syncthreads();
    }

    const int r0 = rowBase + mrow + fr;
    const int r1 = r0 + 8;
#pragma unroll
    for (int nt = 0; nt < 8; nt++) {
        int col = colBase + nt * 8 + m2;
        float bb0 = projb[col], bb1 = projb[col + 1];
        if (r0 < M_Q) {
            int b = r0 / NTOT, n = r0 - b * NTOT;
            if (n < N0) {
                size_t oo = ((size_t)b * N0 + n) * CDIM + col;
                *(float2*)&out_img[oo] = make_float2(c[nt][0] + bb0 + resx[oo],
                                                     c[nt][1] + bb1 + resx[oo + 1]);
            } else {
                size_t oo = ((size_t)b * NMSG + (n - N0)) * CDIM + col;
                *(float2*)&out_msg[oo] = make_float2(c[nt][0] + bb0 + resmsg[oo],
                                                     c[nt][1] + bb1 + resmsg[oo + 1]);
            }
        }
        if (r1 < M_Q) {
            int b = r1 / NTOT, n = r1 - b * NTOT;
            if (n < N0) {
                size_t oo = ((size_t)b * N0 + n) * CDIM + col;
                *(float2*)&out_img[oo] = make_float2(c[nt][2] + bb0 + resx[oo],
                                                     c[nt][3] + bb1 + resx[oo + 1]);
            } else {
                size_t oo = ((size_t)b * NMSG + (n - N0)) * CDIM + col;
                *(float2*)&out_msg[oo] = make_float2(c[nt][2] + bb0 + resmsg[oo],
                                                     c[nt][3] + bb1 + resmsg[oo + 1]);
            }
        }
    }
}

// ---------------------------------------------------------------------------
extern "C" void kernel_launch(void* const* d_in, const int* in_sizes, int n_in,
                              void* d_out, int out_size) {
    const float* x     = (const float*)d_in[0];
    const float* msg   = (const float*)d_in[1];
    const float* Wq    = (const float*)d_in[2];
    const float* bq    = (const float*)d_in[3];
    const float* sr1w  = (const float*)d_in[4];
    const float* sr1b  = (const float*)d_in[5];
    const float* ln1g  = (const float*)d_in[6];
    const float* ln1b  = (const float*)d_in[7];
    const float* sr2w  = (const float*)d_in[8];
    const float* sr2b  = (const float*)d_in[9];
    const float* ln2g  = (const float*)d_in[10];
    const float* ln2b  = (const float*)d_in[11];
    const float* kv1w  = (const float*)d_in[12];
    const float* kv1b  = (const float*)d_in[13];
    const float* kv2w  = (const float*)d_in[14];
    const float* kv2b  = (const float*)d_in[15];
    const float* lc1w  = (const float*)d_in[16];
    const float* lc1b  = (const float*)d_in[17];
    const float* lc2w  = (const float*)d_in[18];
    const float* lc2b  = (const float*)d_in[19];
    const float* projw = (const float*)d_in[20];
    const float* projb = (const float*)d_in[21];
    (void)in_sizes; (void)n_in; (void)out_size;

    float* out_img = (float*)d_out;
    float* out_msg = out_img + (size_t)BSZ * N0 * CDIM;

    // 1. all conversions / weight prep in one launch
    prep_kernel<<<PS9, 256>>>(x, msg, Wq, kv1w, kv2w, projw, sr1w, sr2w);

    // 2. PATCH1 + PATCH2 + Q GEMMs in one launch (long jobs scheduled first)
    stage1_kernel<<<STAGE1_GRID, 256>>>(bq);

    // 3. partial-sum + SR bias + msg matvec + LN + GELU -> bf16
    lnfuse_kernel<<<M_KV1 + M_KV2, 128>>>(msg, sr1b, sr2b, ln1g, ln1b, ln2g, ln2b);

    // 4. KV projections (both branches, column-split, double-buffered)
    kv_kernel<<<KV_GRID, 256>>>(kv1b, kv2b);

    // 5. V augmentation -> bf16
    vmod_kernel<<<(M_KV1 + M_KV2 + 3) / 4, 256>>>(lc1w, lc1b, lc2w, lc2b);

    // 6. attention (branch-2 heads first, ex2.approx softmax), writes g_x12b
    {
        dim3 grid((NTOT + 127) / 128, 4, BSZ);
        attn_mma_kernel<<<grid, 256>>>();
    }

    // 7. output projection + residual (double-buffered), split write
    proj_kernel<<<NQ_TILES, 256>>>(projb, x, msg, out_img, out_msg);
}